// round 2
// baseline (speedup 1.0000x reference)
#include <cuda_runtime.h>

// Problem constants
#define R_DIM 128
#define W_DIM 256
#define DNODE 256
#define DEDGE 128
#define H_N   8
#define DHEAD 32
#define NTOK  (R_DIM * W_DIM)       // 32768
#define NEGMAX (-3.4028234663852886e38f)

// ---------------- scratch (device globals: allocation-free) ----------------
__device__ float g_xn  [NTOK * DNODE];          // LayerNorm(x), token-major
__device__ float g_q   [NTOK * DNODE];          // [r][h][i][d]
__device__ float g_k   [NTOK * DNODE];          // [r][h][j][d]
__device__ float g_v   [NTOK * DNODE];          // [r][h][j][d]
__device__ float g_gate[NTOK * DNODE];          // sigmoid gates, token-major
__device__ float g_att [NTOK * DNODE];          // gated attention out, token-major
__device__ float g_bias[H_N * W_DIM * W_DIM];   // [h][j][i]  (edge-mask applied)

// ---------------- f32x2 helpers ----------------
__device__ __forceinline__ unsigned long long f2dup(float x) {
    unsigned long long r;
    asm("mov.b64 %0, {%1, %1};" : "=l"(r) : "f"(x));
    return r;
}
__device__ __forceinline__ unsigned long long f2pack(float lo, float hi) {
    unsigned long long r;
    asm("mov.b64 %0, {%1, %2};" : "=l"(r) : "f"(lo), "f"(hi));
    return r;
}
__device__ __forceinline__ void f2unpack(unsigned long long v, float& lo, float& hi) {
    asm("mov.b64 {%0, %1}, %2;" : "=f"(lo), "=f"(hi) : "l"(v));
}
__device__ __forceinline__ unsigned long long f2fma(unsigned long long a,
                                                    unsigned long long b,
                                                    unsigned long long c) {
    unsigned long long d;
    asm("fma.rn.f32x2 %0, %1, %2, %3;" : "=l"(d) : "l"(a), "l"(b), "l"(c));
    return d;
}

// ---------------- kernel 1: LayerNorm(x) -> g_xn ----------------
// one warp per token (256 floats), 8 tokens per block
__global__ void ln_x_kernel(const float* __restrict__ x,
                            const float* __restrict__ g,
                            const float* __restrict__ b) {
    int warp = threadIdx.x >> 5, lane = threadIdx.x & 31;
    int tok  = blockIdx.x * 8 + warp;
    const float* xp = x + (size_t)tok * 256 + lane * 8;
    float4 a0 = *(const float4*)xp;
    float4 a1 = *(const float4*)(xp + 4);
    float s  = a0.x + a0.y + a0.z + a0.w + a1.x + a1.y + a1.z + a1.w;
    float ss = a0.x*a0.x + a0.y*a0.y + a0.z*a0.z + a0.w*a0.w
             + a1.x*a1.x + a1.y*a1.y + a1.z*a1.z + a1.w*a1.w;
    #pragma unroll
    for (int off = 16; off; off >>= 1) {
        s  += __shfl_xor_sync(0xffffffffu, s,  off);
        ss += __shfl_xor_sync(0xffffffffu, ss, off);
    }
    float mu  = s * (1.0f / 256.0f);
    float var = ss * (1.0f / 256.0f) - mu * mu;
    float rs  = rsqrtf(var + 1e-5f);
    float4 g0 = *(const float4*)(g + lane * 8);
    float4 g1 = *(const float4*)(g + lane * 8 + 4);
    float4 b0 = *(const float4*)(b + lane * 8);
    float4 b1 = *(const float4*)(b + lane * 8 + 4);
    float* op = g_xn + (size_t)tok * 256 + lane * 8;
    float4 o0, o1;
    o0.x = (a0.x - mu) * rs * g0.x + b0.x;
    o0.y = (a0.y - mu) * rs * g0.y + b0.y;
    o0.z = (a0.z - mu) * rs * g0.z + b0.z;
    o0.w = (a0.w - mu) * rs * g0.w + b0.w;
    o1.x = (a1.x - mu) * rs * g1.x + b1.x;
    o1.y = (a1.y - mu) * rs * g1.y + b1.y;
    o1.z = (a1.z - mu) * rs * g1.z + b1.z;
    o1.w = (a1.w - mu) * rs * g1.w + b1.w;
    *(float4*)op = o0;
    *(float4*)(op + 4) = o1;
}

// ---------------- kernel 2: edge LN + W_edge + edge_mask -> g_bias[h][j][i] ----------------
// one warp per (i,j) pair; 8 pairs per block
// masks arrive as 32-bit words (bool cast by harness to int32 or float32):
// nonzero bit-pattern == true for both encodings.
__global__ void bias_kernel(const float* __restrict__ edges,
                            const float* __restrict__ lg,
                            const float* __restrict__ lb,
                            const float* __restrict__ We,
                            const unsigned int* __restrict__ emask) {
    __shared__ float sW[DEDGE * H_N];  // 1024
    __shared__ float sg[DEDGE], sb[DEDGE];
    int t = threadIdx.x;
    for (int l = t; l < DEDGE * H_N; l += 256) sW[l] = We[l];
    if (t < DEDGE) { sg[t] = lg[t]; sb[t] = lb[t]; }
    __syncthreads();

    int warp = t >> 5, lane = t & 31;
    int p = blockIdx.x * 8 + warp;          // pair index, i = p>>8, j = p&255
    int i = p >> 8, j = p & 255;

    if (emask[p] == 0u) {
        if (lane < 8) g_bias[(lane * W_DIM + j) * W_DIM + i] = NEGMAX;
        return;
    }
    const float* ep = edges + (size_t)p * DEDGE + lane * 4;
    float4 e = *(const float4*)ep;
    float s  = e.x + e.y + e.z + e.w;
    float ss = e.x*e.x + e.y*e.y + e.z*e.z + e.w*e.w;
    #pragma unroll
    for (int off = 16; off; off >>= 1) {
        s  += __shfl_xor_sync(0xffffffffu, s,  off);
        ss += __shfl_xor_sync(0xffffffffu, ss, off);
    }
    float mu  = s * (1.0f / 128.0f);
    float var = ss * (1.0f / 128.0f) - mu * mu;
    float rs  = rsqrtf(var + 1e-5f);
    int e0 = lane * 4;
    float en[4];
    en[0] = (e.x - mu) * rs * sg[e0 + 0] + sb[e0 + 0];
    en[1] = (e.y - mu) * rs * sg[e0 + 1] + sb[e0 + 1];
    en[2] = (e.z - mu) * rs * sg[e0 + 2] + sb[e0 + 2];
    en[3] = (e.w - mu) * rs * sg[e0 + 3] + sb[e0 + 3];
    float acc[8];
    #pragma unroll
    for (int h = 0; h < 8; h++) acc[h] = 0.0f;
    #pragma unroll
    for (int c = 0; c < 4; c++) {
        const float* wr = &sW[(e0 + c) * 8];
        #pragma unroll
        for (int h = 0; h < 8; h++) acc[h] += en[c] * wr[h];
    }
    #pragma unroll
    for (int h = 0; h < 8; h++) {
        #pragma unroll
        for (int off = 16; off; off >>= 1)
            acc[h] += __shfl_xor_sync(0xffffffffu, acc[h], off);
    }
    if (lane == 0) {
        #pragma unroll
        for (int h = 0; h < 8; h++)
            g_bias[(h * W_DIM + j) * W_DIM + i] = acc[h];
    }
}

// ---------------- kernel 3: projection GEMM (q,k,v,gate) ----------------
// C[32768 x 1024] = g_xn @ [Wq | Wkv | Wg]; BM=128, BN=128, BK=16, f32x2 inner
__global__ void __launch_bounds__(256, 2)
proj_kernel(const float* __restrict__ Wq, const float* __restrict__ Wkv,
            const float* __restrict__ Wg, const float* __restrict__ bg) {
    __shared__ float sA[16][128];
    __shared__ float sB[16][128];
    int bn = blockIdx.x, bm = blockIdx.y;
    int t = threadIdx.x;
    int warp = t >> 5, lane = t & 31;
    int wm = warp & 3, wn = warp >> 2;
    int lm = lane >> 3, ln = lane & 7;
    int tm0 = wm * 32 + lm * 8;
    int tn0 = wn * 64 + ln * 8;

    const float* Bsrc; int ldb, col0;
    int nbase = bn * 128;
    if (nbase < 256)      { Bsrc = Wq;  ldb = 256; col0 = nbase; }
    else if (nbase < 768) { Bsrc = Wkv; ldb = 512; col0 = nbase - 256; }
    else                  { Bsrc = Wg;  ldb = 256; col0 = nbase - 768; }

    int arow = t >> 1, ak0 = (t & 1) * 8;
    int bk = t >> 4, bn8 = (t & 15) * 8;
    const float* Ap = g_xn + (size_t)(bm * 128 + arow) * 256;
    const float* Bp = Bsrc + (size_t)bk * ldb + col0 + bn8;

    unsigned long long acc[8][4];
    #pragma unroll
    for (int i2 = 0; i2 < 8; i2++)
        #pragma unroll
        for (int j2 = 0; j2 < 4; j2++) acc[i2][j2] = 0ull;

    float4 a0 = *(const float4*)(Ap + ak0);
    float4 a1 = *(const float4*)(Ap + ak0 + 4);
    float4 b0 = *(const float4*)Bp;
    float4 b1 = *(const float4*)(Bp + 4);

    for (int kt = 0; kt < 16; kt++) {
        __syncthreads();
        sA[ak0 + 0][arow] = a0.x; sA[ak0 + 1][arow] = a0.y;
        sA[ak0 + 2][arow] = a0.z; sA[ak0 + 3][arow] = a0.w;
        sA[ak0 + 4][arow] = a1.x; sA[ak0 + 5][arow] = a1.y;
        sA[ak0 + 6][arow] = a1.z; sA[ak0 + 7][arow] = a1.w;
        *(float4*)&sB[bk][bn8] = b0;
        *(float4*)&sB[bk][bn8 + 4] = b1;
        __syncthreads();
        if (kt < 15) {
            a0 = *(const float4*)(Ap + (kt + 1) * 16 + ak0);
            a1 = *(const float4*)(Ap + (kt + 1) * 16 + ak0 + 4);
            b0 = *(const float4*)(Bp + (size_t)(kt + 1) * 16 * ldb);
            b1 = *(const float4*)(Bp + (size_t)(kt + 1) * 16 * ldb + 4);
        }
        #pragma unroll
        for (int kk = 0; kk < 16; kk++) {
            float4 av0 = *(const float4*)&sA[kk][tm0];
            float4 av1 = *(const float4*)&sA[kk][tm0 + 4];
            unsigned long long a2[8];
            a2[0] = f2dup(av0.x); a2[1] = f2dup(av0.y);
            a2[2] = f2dup(av0.z); a2[3] = f2dup(av0.w);
            a2[4] = f2dup(av1.x); a2[5] = f2dup(av1.y);
            a2[6] = f2dup(av1.z); a2[7] = f2dup(av1.w);
            ulonglong2 bb0 = *(const ulonglong2*)&sB[kk][tn0];
            ulonglong2 bb1 = *(const ulonglong2*)&sB[kk][tn0 + 4];
            #pragma unroll
            for (int i2 = 0; i2 < 8; i2++) {
                acc[i2][0] = f2fma(a2[i2], bb0.x, acc[i2][0]);
                acc[i2][1] = f2fma(a2[i2], bb0.y, acc[i2][1]);
                acc[i2][2] = f2fma(a2[i2], bb1.x, acc[i2][2]);
                acc[i2][3] = f2fma(a2[i2], bb1.y, acc[i2][3]);
            }
        }
    }

    int gc = nbase + tn0;                       // global output column
    if (gc < 768) {                             // q/k/v regions
        float* dst; int cq;
        if (gc < 256)      { dst = g_q; cq = gc; }
        else if (gc < 512) { dst = g_k; cq = gc - 256; }
        else               { dst = g_v; cq = gc - 512; }
        int hh = cq >> 5, d8 = cq & 31;
        #pragma unroll
        for (int i2 = 0; i2 < 8; i2++) {
            int tok = bm * 128 + tm0 + i2;
            int rr = tok >> 8, iw = tok & 255;
            float c0, c1, c2, c3, c4, c5, c6, c7;
            f2unpack(acc[i2][0], c0, c1); f2unpack(acc[i2][1], c2, c3);
            f2unpack(acc[i2][2], c4, c5); f2unpack(acc[i2][3], c6, c7);
            float* pp = dst + ((size_t)((rr * 8 + hh) * 256 + iw) * 32 + d8);
            *(float4*)pp       = make_float4(c0, c1, c2, c3);
            *(float4*)(pp + 4) = make_float4(c4, c5, c6, c7);
        }
    } else {                                    // gate region (sigmoid)
        int gcol = gc - 768;
        float4 bg0 = *(const float4*)(bg + gcol);
        float4 bg1 = *(const float4*)(bg + gcol + 4);
        #pragma unroll
        for (int i2 = 0; i2 < 8; i2++) {
            int tok = bm * 128 + tm0 + i2;
            float c0, c1, c2, c3, c4, c5, c6, c7;
            f2unpack(acc[i2][0], c0, c1); f2unpack(acc[i2][1], c2, c3);
            f2unpack(acc[i2][2], c4, c5); f2unpack(acc[i2][3], c6, c7);
            float4 o0, o1;
            o0.x = 1.0f / (1.0f + __expf(-(c0 + bg0.x)));
            o0.y = 1.0f / (1.0f + __expf(-(c1 + bg0.y)));
            o0.z = 1.0f / (1.0f + __expf(-(c2 + bg0.z)));
            o0.w = 1.0f / (1.0f + __expf(-(c3 + bg0.w)));
            o1.x = 1.0f / (1.0f + __expf(-(c4 + bg1.x)));
            o1.y = 1.0f / (1.0f + __expf(-(c5 + bg1.y)));
            o1.z = 1.0f / (1.0f + __expf(-(c6 + bg1.z)));
            o1.w = 1.0f / (1.0f + __expf(-(c7 + bg1.w)));
            float* pp = g_gate + (size_t)tok * 256 + gcol;
            *(float4*)pp       = o0;
            *(float4*)(pp + 4) = o1;
        }
    }
}

// ---------------- kernel 4: fused attention + gating ----------------
// one CTA per (r, h); 256 threads, thread i = query i; j streamed in chunks of 32
__global__ void __launch_bounds__(256, 2)
attn_kernel(const unsigned int* __restrict__ mask) {
    __shared__ float k_s[32 * 32];
    __shared__ float v_s[32 * 32];
    __shared__ float bias_s[32 * 256];
    __shared__ unsigned char msk[256];

    int rh = blockIdx.x;
    int r = rh >> 3, h = rh & 7;
    int i = threadIdx.x;

    unsigned int mw = mask[r * 256 + i];
    msk[i] = (mw != 0u) ? 1 : 0;
    int mi = (mw != 0u) ? 1 : 0;

    const float sc = 0.17677669529663689f;   // 32^-0.5
    const float* qp = g_q + ((size_t)((r * 8 + h) * 256 + i)) * 32;
    unsigned long long q2[16];
    #pragma unroll
    for (int dd = 0; dd < 8; dd++) {
        float4 q4 = ((const float4*)qp)[dd];
        q2[2 * dd]     = f2pack(q4.x * sc, q4.y * sc);
        q2[2 * dd + 1] = f2pack(q4.z * sc, q4.w * sc);
    }

    unsigned long long acc2[16];
    #pragma unroll
    for (int dd = 0; dd < 16; dd++) acc2[dd] = 0ull;
    float l_sum = 0.0f;

    const float* kbase = g_k + (size_t)((r * 8 + h) * 256) * 32;
    const float* vbase = g_v + (size_t)((r * 8 + h) * 256) * 32;
    const float* bbase = g_bias + (size_t)(h * 256) * 256;

    for (int jb = 0; jb < 8; jb++) {
        __syncthreads();
        ((float4*)k_s)[i] = ((const float4*)(kbase + jb * 32 * 32))[i];
        ((float4*)v_s)[i] = ((const float4*)(vbase + jb * 32 * 32))[i];
        const float4* bp4 = (const float4*)(bbase + jb * 32 * 256);
        #pragma unroll
        for (int l = 0; l < 8; l++)
            ((float4*)bias_s)[i + l * 256] = bp4[i + l * 256];
        __syncthreads();

        #pragma unroll 4
        for (int jj = 0; jj < 32; jj++) {
            const ulonglong2* kr = (const ulonglong2*)(k_s + jj * 32);
            unsigned long long d2a = 0ull, d2b = 0ull;
            #pragma unroll
            for (int dd = 0; dd < 8; dd++) {
                ulonglong2 kk2 = kr[dd];
                d2a = f2fma(q2[2 * dd],     kk2.x, d2a);
                d2b = f2fma(q2[2 * dd + 1], kk2.y, d2b);
            }
            float s0, s1, t0, t1;
            f2unpack(d2a, s0, s1);
            f2unpack(d2b, t0, t1);
            float s = (s0 + s1) + (t0 + t1) + bias_s[jj * 256 + i];
            if (!msk[jb * 32 + jj]) s = NEGMAX;
            float p = mi ? __expf(s) : 1.0f;   // masked-i rows: uniform attention
            l_sum += p;
            unsigned long long p2 = f2dup(p);
            const ulonglong2* vr = (const ulonglong2*)(v_s + jj * 32);
            #pragma unroll
            for (int dd = 0; dd < 8; dd++) {
                ulonglong2 vv = vr[dd];
                acc2[2 * dd]     = f2fma(p2, vv.x, acc2[2 * dd]);
                acc2[2 * dd + 1] = f2fma(p2, vv.y, acc2[2 * dd + 1]);
            }
        }
    }

    float inv = 1.0f / l_sum;
    const float* gp = g_gate + (size_t)(r * 256 + i) * 256 + h * 32;
    float* op       = g_att  + (size_t)(r * 256 + i) * 256 + h * 32;
    #pragma unroll
    for (int dd = 0; dd < 8; dd++) {
        float a, b2, c, d;
        f2unpack(acc2[2 * dd], a, b2);
        f2unpack(acc2[2 * dd + 1], c, d);
        float4 g4 = ((const float4*)gp)[dd];
        float4 o;
        o.x = a  * inv * g4.x;
        o.y = b2 * inv * g4.y;
        o.z = c  * inv * g4.z;
        o.w = d  * inv * g4.w;
        ((float4*)op)[dd] = o;
    }
}

// ---------------- kernel 5: output projection GEMM ----------------
// d_out[32768 x 256] = g_att @ Wo + bo
__global__ void __launch_bounds__(256, 2)
out_kernel(const float* __restrict__ Wo, const float* __restrict__ bo,
           float* __restrict__ out) {
    __shared__ float sA[16][128];
    __shared__ float sB[16][128];
    int bn = blockIdx.x, bm = blockIdx.y;
    int t = threadIdx.x;
    int warp = t >> 5, lane = t & 31;
    int wm = warp & 3, wn = warp >> 2;
    int lm = lane >> 3, ln = lane & 7;
    int tm0 = wm * 32 + lm * 8;
    int tn0 = wn * 64 + ln * 8;

    int col0 = bn * 128;
    int arow = t >> 1, ak0 = (t & 1) * 8;
    int bk = t >> 4, bn8 = (t & 15) * 8;
    const float* Ap = g_att + (size_t)(bm * 128 + arow) * 256;
    const float* Bp = Wo + (size_t)bk * 256 + col0 + bn8;

    unsigned long long acc[8][4];
    #pragma unroll
    for (int i2 = 0; i2 < 8; i2++)
        #pragma unroll
        for (int j2 = 0; j2 < 4; j2++) acc[i2][j2] = 0ull;

    float4 a0 = *(const float4*)(Ap + ak0);
    float4 a1 = *(const float4*)(Ap + ak0 + 4);
    float4 b0 = *(const float4*)Bp;
    float4 b1 = *(const float4*)(Bp + 4);

    for (int kt = 0; kt < 16; kt++) {
        __syncthreads();
        sA[ak0 + 0][arow] = a0.x; sA[ak0 + 1][arow] = a0.y;
        sA[ak0 + 2][arow] = a0.z; sA[ak0 + 3][arow] = a0.w;
        sA[ak0 + 4][arow] = a1.x; sA[ak0 + 5][arow] = a1.y;
        sA[ak0 + 6][arow] = a1.z; sA[ak0 + 7][arow] = a1.w;
        *(float4*)&sB[bk][bn8] = b0;
        *(float4*)&sB[bk][bn8 + 4] = b1;
        __syncthreads();
        if (kt < 15) {
            a0 = *(const float4*)(Ap + (kt + 1) * 16 + ak0);
            a1 = *(const float4*)(Ap + (kt + 1) * 16 + ak0 + 4);
            b0 = *(const float4*)(Bp + (size_t)(kt + 1) * 16 * 256);
            b1 = *(const float4*)(Bp + (size_t)(kt + 1) * 16 * 256 + 4);
        }
        #pragma unroll
        for (int kk = 0; kk < 16; kk++) {
            float4 av0 = *(const float4*)&sA[kk][tm0];
            float4 av1 = *(const float4*)&sA[kk][tm0 + 4];
            unsigned long long a2[8];
            a2[0] = f2dup(av0.x); a2[1] = f2dup(av0.y);
            a2[2] = f2dup(av0.z); a2[3] = f2dup(av0.w);
            a2[4] = f2dup(av1.x); a2[5] = f2dup(av1.y);
            a2[6] = f2dup(av1.z); a2[7] = f2dup(av1.w);
            ulonglong2 bb0 = *(const ulonglong2*)&sB[kk][tn0];
            ulonglong2 bb1 = *(const ulonglong2*)&sB[kk][tn0 + 4];
            #pragma unroll
            for (int i2 = 0; i2 < 8; i2++) {
                acc[i2][0] = f2fma(a2[i2], bb0.x, acc[i2][0]);
                acc[i2][1] = f2fma(a2[i2], bb0.y, acc[i2][1]);
                acc[i2][2] = f2fma(a2[i2], bb1.x, acc[i2][2]);
                acc[i2][3] = f2fma(a2[i2], bb1.y, acc[i2][3]);
            }
        }
    }

    int gc = col0 + tn0;
    float4 bo0 = *(const float4*)(bo + gc);
    float4 bo1 = *(const float4*)(bo + gc + 4);
    #pragma unroll
    for (int i2 = 0; i2 < 8; i2++) {
        int tok = bm * 128 + tm0 + i2;
        float c0, c1, c2, c3, c4, c5, c6, c7;
        f2unpack(acc[i2][0], c0, c1); f2unpack(acc[i2][1], c2, c3);
        f2unpack(acc[i2][2], c4, c5); f2unpack(acc[i2][3], c6, c7);
        float* pp = out + (size_t)tok * 256 + gc;
        *(float4*)pp       = make_float4(c0 + bo0.x, c1 + bo0.y, c2 + bo0.z, c3 + bo0.w);
        *(float4*)(pp + 4) = make_float4(c4 + bo1.x, c5 + bo1.y, c6 + bo1.z, c7 + bo1.w);
    }
}

// ---------------- launch ----------------
extern "C" void kernel_launch(void* const* d_in, const int* in_sizes, int n_in,
                              void* d_out, int out_size) {
    const float* x      = (const float*)d_in[0];
    const float* edges  = (const float*)d_in[1];
    const unsigned int* mask      = (const unsigned int*)d_in[2];
    const unsigned int* edge_mask = (const unsigned int*)d_in[3];
    const float* ln_g   = (const float*)d_in[4];
    const float* ln_b   = (const float*)d_in[5];
    const float* lne_g  = (const float*)d_in[6];
    const float* lne_b  = (const float*)d_in[7];
    const float* W_edge = (const float*)d_in[8];
    const float* Wq     = (const float*)d_in[9];
    const float* Wkv    = (const float*)d_in[10];
    const float* Wg     = (const float*)d_in[11];
    const float* bg     = (const float*)d_in[12];
    const float* Wo     = (const float*)d_in[13];
    const float* bo     = (const float*)d_in[14];
    float* out = (float*)d_out;

    ln_x_kernel<<<NTOK / 8, 256>>>(x, ln_g, ln_b);
    bias_kernel<<<(W_DIM * W_DIM) / 8, 256>>>(edges, lne_g, lne_b, W_edge, edge_mask);
    proj_kernel<<<dim3(8, NTOK / 128), 256>>>(Wq, Wkv, Wg, bg);
    attn_kernel<<<R_DIM * H_N, 256>>>(mask);
    out_kernel<<<dim3(2, NTOK / 128), 256>>>(Wo, bo, out);
}

// round 4
// speedup vs baseline: 1.0677x; 1.0677x over previous
#include <cuda_runtime.h>

// Problem constants
#define R_DIM 128
#define W_DIM 256
#define DNODE 256
#define DEDGE 128
#define H_N   8
#define DHEAD 32
#define NTOK  (R_DIM * W_DIM)       // 32768
#define NEGMAX (-3.4028234663852886e38f)

// ---------------- scratch (device globals: allocation-free) ----------------
__device__ float g_xn  [NTOK * DNODE];
__device__ float g_q   [NTOK * DNODE];          // [r][h][i][d]
__device__ float g_k   [NTOK * DNODE];          // [r][h][j][d]
__device__ float g_v   [NTOK * DNODE];          // [r][h][j][d]
__device__ float g_gate[NTOK * DNODE];
__device__ float g_att [NTOK * DNODE];
__device__ float g_bias[H_N * W_DIM * W_DIM];   // [h][j][i]

// ---------------- f32x2 helpers (attention kernel) ----------------
__device__ __forceinline__ unsigned long long f2dup(float x) {
    unsigned long long r;
    asm("mov.b64 %0, {%1, %1};" : "=l"(r) : "f"(x));
    return r;
}
__device__ __forceinline__ unsigned long long f2pack(float lo, float hi) {
    unsigned long long r;
    asm("mov.b64 %0, {%1, %2};" : "=l"(r) : "f"(lo), "f"(hi));
    return r;
}
__device__ __forceinline__ void f2unpack(unsigned long long v, float& lo, float& hi) {
    asm("mov.b64 {%0, %1}, %2;" : "=f"(lo), "=f"(hi) : "l"(v));
}
__device__ __forceinline__ unsigned long long f2fma(unsigned long long a,
                                                    unsigned long long b,
                                                    unsigned long long c) {
    unsigned long long d;
    asm("fma.rn.f32x2 %0, %1, %2, %3;" : "=l"(d) : "l"(a), "l"(b), "l"(c));
    return d;
}

// ---------------- tf32 mma helpers ----------------
__device__ __forceinline__ void mma_tf32(float* d,
                                         unsigned a0, unsigned a1, unsigned a2, unsigned a3,
                                         unsigned b0, unsigned b1) {
    asm volatile(
        "mma.sync.aligned.m16n8k8.row.col.f32.tf32.tf32.f32 "
        "{%0,%1,%2,%3}, {%4,%5,%6,%7}, {%8,%9}, {%0,%1,%2,%3};"
        : "+f"(d[0]), "+f"(d[1]), "+f"(d[2]), "+f"(d[3])
        : "r"(a0), "r"(a1), "r"(a2), "r"(a3), "r"(b0), "r"(b1));
}
// error-compensated split: x ~= hi + lo, both tf32-representable
__device__ __forceinline__ void split_tf32(float x, unsigned& hi, unsigned& lo) {
    asm("cvt.rna.tf32.f32 %0, %1;" : "=r"(hi) : "f"(x));
    float l = x - __uint_as_float(hi);
    asm("cvt.rna.tf32.f32 %0, %1;" : "=r"(lo) : "f"(l));
}
#define CP16(dst_u32, src_ptr) \
    asm volatile("cp.async.ca.shared.global [%0], [%1], 16;" :: "r"(dst_u32), "l"(src_ptr))
__device__ __forceinline__ void cp_commit() { asm volatile("cp.async.commit_group;"); }
__device__ __forceinline__ void cp_wait1()  { asm volatile("cp.async.wait_group 1;"); }
__device__ __forceinline__ void cp_wait0()  { asm volatile("cp.async.wait_group 0;"); }

// smem geometry for the tf32 GEMMs
#define SA_STRIDE 20                 // 16 + 4 pad
#define SA_STAGE  (128 * SA_STRIDE)
#define SB_STAGE  (16 * 128)

// ---------------- kernel 1: LayerNorm(x) -> g_xn ----------------
__global__ void ln_x_kernel(const float* __restrict__ x,
                            const float* __restrict__ g,
                            const float* __restrict__ b) {
    int warp = threadIdx.x >> 5, lane = threadIdx.x & 31;
    int tok  = blockIdx.x * 8 + warp;
    const float* xp = x + (size_t)tok * 256 + lane * 8;
    float4 a0 = *(const float4*)xp;
    float4 a1 = *(const float4*)(xp + 4);
    float s  = a0.x + a0.y + a0.z + a0.w + a1.x + a1.y + a1.z + a1.w;
    float ss = a0.x*a0.x + a0.y*a0.y + a0.z*a0.z + a0.w*a0.w
             + a1.x*a1.x + a1.y*a1.y + a1.z*a1.z + a1.w*a1.w;
    #pragma unroll
    for (int off = 16; off; off >>= 1) {
        s  += __shfl_xor_sync(0xffffffffu, s,  off);
        ss += __shfl_xor_sync(0xffffffffu, ss, off);
    }
    float mu  = s * (1.0f / 256.0f);
    float var = ss * (1.0f / 256.0f) - mu * mu;
    float rs  = rsqrtf(var + 1e-5f);
    float4 g0 = *(const float4*)(g + lane * 8);
    float4 g1 = *(const float4*)(g + lane * 8 + 4);
    float4 b0 = *(const float4*)(b + lane * 8);
    float4 b1 = *(const float4*)(b + lane * 8 + 4);
    float* op = g_xn + (size_t)tok * 256 + lane * 8;
    float4 o0, o1;
    o0.x = (a0.x - mu) * rs * g0.x + b0.x;
    o0.y = (a0.y - mu) * rs * g0.y + b0.y;
    o0.z = (a0.z - mu) * rs * g0.z + b0.z;
    o0.w = (a0.w - mu) * rs * g0.w + b0.w;
    o1.x = (a1.x - mu) * rs * g1.x + b1.x;
    o1.y = (a1.y - mu) * rs * g1.y + b1.y;
    o1.z = (a1.z - mu) * rs * g1.z + b1.z;
    o1.w = (a1.w - mu) * rs * g1.w + b1.w;
    *(float4*)op = o0;
    *(float4*)(op + 4) = o1;
}

// ---------------- kernel 2: edge LN + W_edge + edge_mask -> g_bias[h][j][i] ----------------
__global__ void bias_kernel(const float* __restrict__ edges,
                            const float* __restrict__ lg,
                            const float* __restrict__ lb,
                            const float* __restrict__ We,
                            const unsigned int* __restrict__ emask) {
    __shared__ float sW[DEDGE * H_N];
    __shared__ float sg[DEDGE], sb[DEDGE];
    int t = threadIdx.x;
    for (int l = t; l < DEDGE * H_N; l += 256) sW[l] = We[l];
    if (t < DEDGE) { sg[t] = lg[t]; sb[t] = lb[t]; }
    __syncthreads();

    int warp = t >> 5, lane = t & 31;
    int p = blockIdx.x * 8 + warp;
    int i = p >> 8, j = p & 255;

    if (emask[p] == 0u) {
        if (lane < 8) g_bias[(lane * W_DIM + j) * W_DIM + i] = NEGMAX;
        return;
    }
    const float* ep = edges + (size_t)p * DEDGE + lane * 4;
    float4 e = *(const float4*)ep;
    float s  = e.x + e.y + e.z + e.w;
    float ss = e.x*e.x + e.y*e.y + e.z*e.z + e.w*e.w;
    #pragma unroll
    for (int off = 16; off; off >>= 1) {
        s  += __shfl_xor_sync(0xffffffffu, s,  off);
        ss += __shfl_xor_sync(0xffffffffu, ss, off);
    }
    float mu  = s * (1.0f / 128.0f);
    float var = ss * (1.0f / 128.0f) - mu * mu;
    float rs  = rsqrtf(var + 1e-5f);
    int e0 = lane * 4;
    float en[4];
    en[0] = (e.x - mu) * rs * sg[e0 + 0] + sb[e0 + 0];
    en[1] = (e.y - mu) * rs * sg[e0 + 1] + sb[e0 + 1];
    en[2] = (e.z - mu) * rs * sg[e0 + 2] + sb[e0 + 2];
    en[3] = (e.w - mu) * rs * sg[e0 + 3] + sb[e0 + 3];
    float acc[8];
    #pragma unroll
    for (int h = 0; h < 8; h++) acc[h] = 0.0f;
    #pragma unroll
    for (int c = 0; c < 4; c++) {
        const float* wr = &sW[(e0 + c) * 8];
        #pragma unroll
        for (int h = 0; h < 8; h++) acc[h] += en[c] * wr[h];
    }
    #pragma unroll
    for (int h = 0; h < 8; h++) {
        #pragma unroll
        for (int off = 16; off; off >>= 1)
            acc[h] += __shfl_xor_sync(0xffffffffu, acc[h], off);
    }
    if (lane == 0) {
        #pragma unroll
        for (int h = 0; h < 8; h++)
            g_bias[(h * W_DIM + j) * W_DIM + i] = acc[h];
    }
}

// ---------------- shared 3xTF32 mainloop body (macro to keep both GEMMs in sync) ----
// computes acc += A(128x16) * B(16x128) for one k-tile using error-compensated tf32
#define MMA_KTILE_3XTF32(A0, B0)                                               \
    {                                                                          \
        unsigned bh[4][4], bl[4][4];                                           \
        _Pragma("unroll")                                                      \
        for (int an = 0; an < 4; an++) {                                       \
            int n = wn * 32 + an * 8 + g;                                      \
            split_tf32(B0[(c)      * 128 + n], bh[an][0], bl[an][0]);          \
            split_tf32(B0[(c + 4)  * 128 + n], bh[an][1], bl[an][1]);          \
            split_tf32(B0[(c + 8)  * 128 + n], bh[an][2], bl[an][2]);          \
            split_tf32(B0[(c + 12) * 128 + n], bh[an][3], bl[an][3]);          \
        }                                                                      \
        _Pragma("unroll")                                                      \
        for (int am = 0; am < 4; am++) {                                       \
            int m0 = (wm * 64 + am * 16 + g) * SA_STRIDE;                      \
            int m1 = m0 + 8 * SA_STRIDE;                                       \
            unsigned ah[8], al[8];                                             \
            split_tf32(A0[m0 + c],      ah[0], al[0]);                         \
            split_tf32(A0[m1 + c],      ah[1], al[1]);                         \
            split_tf32(A0[m0 + c + 4],  ah[2], al[2]);                         \
            split_tf32(A0[m1 + c + 4],  ah[3], al[3]);                         \
            split_tf32(A0[m0 + c + 8],  ah[4], al[4]);                         \
            split_tf32(A0[m1 + c + 8],  ah[5], al[5]);                         \
            split_tf32(A0[m0 + c + 12], ah[6], al[6]);                         \
            split_tf32(A0[m1 + c + 12], ah[7], al[7]);                         \
            _Pragma("unroll")                                                  \
            for (int an = 0; an < 4; an++) {                                   \
                float* ac = acc[am][an];                                       \
                mma_tf32(ac, ah[0], ah[1], ah[2], ah[3], bh[an][0], bh[an][1]);\
                mma_tf32(ac, ah[0], ah[1], ah[2], ah[3], bl[an][0], bl[an][1]);\
                mma_tf32(ac, al[0], al[1], al[2], al[3], bh[an][0], bh[an][1]);\
                mma_tf32(ac, ah[4], ah[5], ah[6], ah[7], bh[an][2], bh[an][3]);\
                mma_tf32(ac, ah[4], ah[5], ah[6], ah[7], bl[an][2], bl[an][3]);\
                mma_tf32(ac, al[4], al[5], al[6], al[7], bh[an][2], bh[an][3]);\
            }                                                                  \
        }                                                                      \
    }

// ---------------- kernel 3: projection GEMM via 3xTF32 mma.sync ----------------
__global__ void __launch_bounds__(256, 2)
proj_mma(const float* __restrict__ Wq, const float* __restrict__ Wkv,
         const float* __restrict__ Wg, const float* __restrict__ bg) {
    __shared__ float sA[2 * SA_STAGE];
    __shared__ float sB[2 * SB_STAGE];
    int t = threadIdx.x, lane = t & 31, warp = t >> 5;
    int wm = warp >> 2, wn = warp & 3;
    int g = lane >> 2, c = lane & 3;
    int bn = blockIdx.x, bm = blockIdx.y;

    int nb = bn * 128;
    const float* Bsrc; int ldb, col0;
    if (nb < 256)      { Bsrc = Wq;  ldb = 256; col0 = nb; }
    else if (nb < 768) { Bsrc = Wkv; ldb = 512; col0 = nb - 256; }
    else               { Bsrc = Wg;  ldb = 256; col0 = nb - 768; }

    const float* Ab = g_xn + (size_t)bm * 128 * 256;
    unsigned sA_u = (unsigned)__cvta_generic_to_shared(sA);
    unsigned sB_u = (unsigned)__cvta_generic_to_shared(sB);

    int a_row0 = t >> 2,         a_q0 = t & 3;
    int a_row1 = (t + 256) >> 2, a_q1 = t & 3;
    int b_k0 = t >> 5,           b_seg0 = t & 31;
    int b_k1 = (t + 256) >> 5,   b_seg1 = t & 31;

    float acc[4][4][4];
    #pragma unroll
    for (int am = 0; am < 4; am++)
        #pragma unroll
        for (int an = 0; an < 4; an++)
            #pragma unroll
            for (int v = 0; v < 4; v++) acc[am][an][v] = 0.0f;

    {
        CP16(sA_u + (a_row0 * SA_STRIDE + a_q0 * 4) * 4, Ab + (size_t)a_row0 * 256 + a_q0 * 4);
        CP16(sA_u + (a_row1 * SA_STRIDE + a_q1 * 4) * 4, Ab + (size_t)a_row1 * 256 + a_q1 * 4);
        CP16(sB_u + (b_k0 * 128 + b_seg0 * 4) * 4, Bsrc + (size_t)b_k0 * ldb + col0 + b_seg0 * 4);
        CP16(sB_u + (b_k1 * 128 + b_seg1 * 4) * 4, Bsrc + (size_t)b_k1 * ldb + col0 + b_seg1 * 4);
        cp_commit();
    }

    for (int kt = 0; kt < 16; kt++) {
        if (kt < 15) {
            int buf = (kt + 1) & 1;
            int kk = (kt + 1) * 16;
            CP16(sA_u + (buf * SA_STAGE + a_row0 * SA_STRIDE + a_q0 * 4) * 4,
                 Ab + (size_t)a_row0 * 256 + kk + a_q0 * 4);
            CP16(sA_u + (buf * SA_STAGE + a_row1 * SA_STRIDE + a_q1 * 4) * 4,
                 Ab + (size_t)a_row1 * 256 + kk + a_q1 * 4);
            CP16(sB_u + (buf * SB_STAGE + b_k0 * 128 + b_seg0 * 4) * 4,
                 Bsrc + (size_t)(kk + b_k0) * ldb + col0 + b_seg0 * 4);
            CP16(sB_u + (buf * SB_STAGE + b_k1 * 128 + b_seg1 * 4) * 4,
                 Bsrc + (size_t)(kk + b_k1) * ldb + col0 + b_seg1 * 4);
            cp_commit();
            cp_wait1();
        } else {
            cp_wait0();
        }
        __syncthreads();

        const float* A0 = sA + (kt & 1) * SA_STAGE;
        const float* B0 = sB + (kt & 1) * SB_STAGE;
        MMA_KTILE_3XTF32(A0, B0)
        __syncthreads();
    }

    // epilogue
    if (nb < 768) {
        float* dst; int base;
        if (nb < 256)      { dst = g_q; base = 0; }
        else if (nb < 512) { dst = g_k; base = 256; }
        else               { dst = g_v; base = 512; }
        #pragma unroll
        for (int am = 0; am < 4; am++) {
            int tok = bm * 128 + wm * 64 + am * 16 + g;
            int rr = tok >> 8, iw = tok & 255;
            #pragma unroll
            for (int an = 0; an < 4; an++) {
                int gc = nb + wn * 32 + an * 8 + 2 * c;
                int cq = gc - base;
                int hh = cq >> 5, d8 = cq & 31;
                float* p0 = dst + ((size_t)((rr * 8 + hh) * 256 + iw)) * 32 + d8;
                float* p1 = p0 + 8 * 32;
                *(float2*)p0 = make_float2(acc[am][an][0], acc[am][an][1]);
                *(float2*)p1 = make_float2(acc[am][an][2], acc[am][an][3]);
            }
        }
    } else {
        #pragma unroll
        for (int am = 0; am < 4; am++) {
            int tok = bm * 128 + wm * 64 + am * 16 + g;
            #pragma unroll
            for (int an = 0; an < 4; an++) {
                int gc = nb + wn * 32 + an * 8 + 2 * c;
                int gcol = gc - 768;
                float2 bg2 = *(const float2*)(bg + gcol);
                float* p0 = g_gate + (size_t)tok * 256 + gcol;
                float* p1 = p0 + 8 * 256;
                float2 o0, o1;
                o0.x = 1.0f / (1.0f + __expf(-(acc[am][an][0] + bg2.x)));
                o0.y = 1.0f / (1.0f + __expf(-(acc[am][an][1] + bg2.y)));
                o1.x = 1.0f / (1.0f + __expf(-(acc[am][an][2] + bg2.x)));
                o1.y = 1.0f / (1.0f + __expf(-(acc[am][an][3] + bg2.y)));
                *(float2*)p0 = o0;
                *(float2*)p1 = o1;
            }
        }
    }
}

// ---------------- kernel 5: output projection via 3xTF32 mma.sync ----------------
__global__ void __launch_bounds__(256, 2)
out_mma(const float* __restrict__ Wo, const float* __restrict__ bo,
        float* __restrict__ out) {
    __shared__ float sA[2 * SA_STAGE];
    __shared__ float sB[2 * SB_STAGE];
    int t = threadIdx.x, lane = t & 31, warp = t >> 5;
    int wm = warp >> 2, wn = warp & 3;
    int g = lane >> 2, c = lane & 3;
    int bn = blockIdx.x, bm = blockIdx.y;
    int nb = bn * 128;

    const float* Ab = g_att + (size_t)bm * 128 * 256;
    unsigned sA_u = (unsigned)__cvta_generic_to_shared(sA);
    unsigned sB_u = (unsigned)__cvta_generic_to_shared(sB);

    int a_row0 = t >> 2,         a_q0 = t & 3;
    int a_row1 = (t + 256) >> 2, a_q1 = t & 3;
    int b_k0 = t >> 5,           b_seg0 = t & 31;
    int b_k1 = (t + 256) >> 5,   b_seg1 = t & 31;

    float acc[4][4][4];
    #pragma unroll
    for (int am = 0; am < 4; am++)
        #pragma unroll
        for (int an = 0; an < 4; an++)
            #pragma unroll
            for (int v = 0; v < 4; v++) acc[am][an][v] = 0.0f;

    {
        CP16(sA_u + (a_row0 * SA_STRIDE + a_q0 * 4) * 4, Ab + (size_t)a_row0 * 256 + a_q0 * 4);
        CP16(sA_u + (a_row1 * SA_STRIDE + a_q1 * 4) * 4, Ab + (size_t)a_row1 * 256 + a_q1 * 4);
        CP16(sB_u + (b_k0 * 128 + b_seg0 * 4) * 4, Wo + (size_t)b_k0 * 256 + nb + b_seg0 * 4);
        CP16(sB_u + (b_k1 * 128 + b_seg1 * 4) * 4, Wo + (size_t)b_k1 * 256 + nb + b_seg1 * 4);
        cp_commit();
    }

    for (int kt = 0; kt < 16; kt++) {
        if (kt < 15) {
            int buf = (kt + 1) & 1;
            int kk = (kt + 1) * 16;
            CP16(sA_u + (buf * SA_STAGE + a_row0 * SA_STRIDE + a_q0 * 4) * 4,
                 Ab + (size_t)a_row0 * 256 + kk + a_q0 * 4);
            CP16(sA_u + (buf * SA_STAGE + a_row1 * SA_STRIDE + a_q1 * 4) * 4,
                 Ab + (size_t)a_row1 * 256 + kk + a_q1 * 4);
            CP16(sB_u + (buf * SB_STAGE + b_k0 * 128 + b_seg0 * 4) * 4,
                 Wo + (size_t)(kk + b_k0) * 256 + nb + b_seg0 * 4);
            CP16(sB_u + (buf * SB_STAGE + b_k1 * 128 + b_seg1 * 4) * 4,
                 Wo + (size_t)(kk + b_k1) * 256 + nb + b_seg1 * 4);
            cp_commit();
            cp_wait1();
        } else {
            cp_wait0();
        }
        __syncthreads();

        const float* A0 = sA + (kt & 1) * SA_STAGE;
        const float* B0 = sB + (kt & 1) * SB_STAGE;
        MMA_KTILE_3XTF32(A0, B0)
        __syncthreads();
    }

    #pragma unroll
    for (int am = 0; am < 4; am++) {
        int tok = bm * 128 + wm * 64 + am * 16 + g;
        #pragma unroll
        for (int an = 0; an < 4; an++) {
            int gc = nb + wn * 32 + an * 8 + 2 * c;
            float2 bo2 = *(const float2*)(bo + gc);
            float* p0 = out + (size_t)tok * 256 + gc;
            float* p1 = p0 + 8 * 256;
            *(float2*)p0 = make_float2(acc[am][an][0] + bo2.x, acc[am][an][1] + bo2.y);
            *(float2*)p1 = make_float2(acc[am][an][2] + bo2.x, acc[am][an][3] + bo2.y);
        }
    }
}

// ---------------- kernel 4: fused attention + gating (unchanged) ----------------
__global__ void __launch_bounds__(256, 2)
attn_kernel(const unsigned int* __restrict__ mask) {
    __shared__ float k_s[32 * 32];
    __shared__ float v_s[32 * 32];
    __shared__ float bias_s[32 * 256];
    __shared__ unsigned char msk[256];

    int rh = blockIdx.x;
    int r = rh >> 3, h = rh & 7;
    int i = threadIdx.x;

    unsigned int mw = mask[r * 256 + i];
    msk[i] = (mw != 0u) ? 1 : 0;
    int mi = (mw != 0u) ? 1 : 0;

    const float sc = 0.17677669529663689f;
    const float* qp = g_q + ((size_t)((r * 8 + h) * 256 + i)) * 32;
    unsigned long long q2[16];
    #pragma unroll
    for (int dd = 0; dd < 8; dd++) {
        float4 q4 = ((const float4*)qp)[dd];
        q2[2 * dd]     = f2pack(q4.x * sc, q4.y * sc);
        q2[2 * dd + 1] = f2pack(q4.z * sc, q4.w * sc);
    }

    unsigned long long acc2[16];
    #pragma unroll
    for (int dd = 0; dd < 16; dd++) acc2[dd] = 0ull;
    float l_sum = 0.0f;

    const float* kbase = g_k + (size_t)((r * 8 + h) * 256) * 32;
    const float* vbase = g_v + (size_t)((r * 8 + h) * 256) * 32;
    const float* bbase = g_bias + (size_t)(h * 256) * 256;

    for (int jb = 0; jb < 8; jb++) {
        __syncthreads();
        ((float4*)k_s)[i] = ((const float4*)(kbase + jb * 32 * 32))[i];
        ((float4*)v_s)[i] = ((const float4*)(vbase + jb * 32 * 32))[i];
        const float4* bp4 = (const float4*)(bbase + jb * 32 * 256);
        #pragma unroll
        for (int l = 0; l < 8; l++)
            ((float4*)bias_s)[i + l * 256] = bp4[i + l * 256];
        __syncthreads();

        #pragma unroll 4
        for (int jj = 0; jj < 32; jj++) {
            const ulonglong2* kr = (const ulonglong2*)(k_s + jj * 32);
            unsigned long long d2a = 0ull, d2b = 0ull;
            #pragma unroll
            for (int dd = 0; dd < 8; dd++) {
                ulonglong2 kk2 = kr[dd];
                d2a = f2fma(q2[2 * dd],     kk2.x, d2a);
                d2b = f2fma(q2[2 * dd + 1], kk2.y, d2b);
            }
            float s0, s1, t0, t1;
            f2unpack(d2a, s0, s1);
            f2unpack(d2b, t0, t1);
            float s = (s0 + s1) + (t0 + t1) + bias_s[jj * 256 + i];
            if (!msk[jb * 32 + jj]) s = NEGMAX;
            float p = mi ? __expf(s) : 1.0f;
            l_sum += p;
            unsigned long long p2 = f2dup(p);
            const ulonglong2* vr = (const ulonglong2*)(v_s + jj * 32);
            #pragma unroll
            for (int dd = 0; dd < 8; dd++) {
                ulonglong2 vv = vr[dd];
                acc2[2 * dd]     = f2fma(p2, vv.x, acc2[2 * dd]);
                acc2[2 * dd + 1] = f2fma(p2, vv.y, acc2[2 * dd + 1]);
            }
        }
    }

    float inv = 1.0f / l_sum;
    const float* gp = g_gate + (size_t)(r * 256 + i) * 256 + h * 32;
    float* op       = g_att  + (size_t)(r * 256 + i) * 256 + h * 32;
    #pragma unroll
    for (int dd = 0; dd < 8; dd++) {
        float a, b2, c, d;
        f2unpack(acc2[2 * dd], a, b2);
        f2unpack(acc2[2 * dd + 1], c, d);
        float4 g4 = ((const float4*)gp)[dd];
        float4 o;
        o.x = a  * inv * g4.x;
        o.y = b2 * inv * g4.y;
        o.z = c  * inv * g4.z;
        o.w = d  * inv * g4.w;
        ((float4*)op)[dd] = o;
    }
}

// ---------------- launch ----------------
extern "C" void kernel_launch(void* const* d_in, const int* in_sizes, int n_in,
                              void* d_out, int out_size) {
    const float* x      = (const float*)d_in[0];
    const float* edges  = (const float*)d_in[1];
    const unsigned int* mask      = (const unsigned int*)d_in[2];
    const unsigned int* edge_mask = (const unsigned int*)d_in[3];
    const float* ln_g   = (const float*)d_in[4];
    const float* ln_b   = (const float*)d_in[5];
    const float* lne_g  = (const float*)d_in[6];
    const float* lne_b  = (const float*)d_in[7];
    const float* W_edge = (const float*)d_in[8];
    const float* Wq     = (const float*)d_in[9];
    const float* Wkv    = (const float*)d_in[10];
    const float* Wg     = (const float*)d_in[11];
    const float* bg     = (const float*)d_in[12];
    const float* Wo     = (const float*)d_in[13];
    const float* bo     = (const float*)d_in[14];
    float* out = (float*)d_out;

    ln_x_kernel<<<NTOK / 8, 256>>>(x, ln_g, ln_b);
    bias_kernel<<<(W_DIM * W_DIM) / 8, 256>>>(edges, lne_g, lne_b, W_edge, edge_mask);
    proj_mma<<<dim3(8, NTOK / 128), 256>>>(Wq, Wkv, Wg, bg);
    attn_kernel<<<R_DIM * H_N, 256>>>(mask);
    out_mma<<<dim3(2, NTOK / 128), 256>>>(Wo, bo, out);
}

// round 5
// speedup vs baseline: 1.0725x; 1.0045x over previous
#include <cuda_runtime.h>

// Problem constants
#define R_DIM 128
#define W_DIM 256
#define DNODE 256
#define DEDGE 128
#define H_N   8
#define DHEAD 32
#define NTOK  (R_DIM * W_DIM)       // 32768
#define NEGMAX (-3.4028234663852886e38f)

// ---------------- scratch (device globals: allocation-free) ----------------
__device__ float g_xn  [NTOK * DNODE];
__device__ float g_q   [NTOK * DNODE];          // [r][h][i][d]
__device__ float g_k   [NTOK * DNODE];          // [r][h][j][d]
__device__ float g_v   [NTOK * DNODE];          // [r][h][j][d]
__device__ float g_gate[NTOK * DNODE];
__device__ float g_att [NTOK * DNODE];
__device__ float g_bias[H_N * W_DIM * W_DIM];   // [h][j][i]

// ---------------- f32x2 helpers (attention kernel) ----------------
__device__ __forceinline__ unsigned long long f2dup(float x) {
    unsigned long long r;
    asm("mov.b64 %0, {%1, %1};" : "=l"(r) : "f"(x));
    return r;
}
__device__ __forceinline__ unsigned long long f2pack(float lo, float hi) {
    unsigned long long r;
    asm("mov.b64 %0, {%1, %2};" : "=l"(r) : "f"(lo), "f"(hi));
    return r;
}
__device__ __forceinline__ void f2unpack(unsigned long long v, float& lo, float& hi) {
    asm("mov.b64 {%0, %1}, %2;" : "=f"(lo), "=f"(hi) : "l"(v));
}
__device__ __forceinline__ unsigned long long f2fma(unsigned long long a,
                                                    unsigned long long b,
                                                    unsigned long long c) {
    unsigned long long d;
    asm("fma.rn.f32x2 %0, %1, %2, %3;" : "=l"(d) : "l"(a), "l"(b), "l"(c));
    return d;
}

// ---------------- tf32 mma helpers ----------------
__device__ __forceinline__ void mma_tf32(float* d,
                                         unsigned a0, unsigned a1, unsigned a2, unsigned a3,
                                         unsigned b0, unsigned b1) {
    asm volatile(
        "mma.sync.aligned.m16n8k8.row.col.f32.tf32.tf32.f32 "
        "{%0,%1,%2,%3}, {%4,%5,%6,%7}, {%8,%9}, {%0,%1,%2,%3};"
        : "+f"(d[0]), "+f"(d[1]), "+f"(d[2]), "+f"(d[3])
        : "r"(a0), "r"(a1), "r"(a2), "r"(a3), "r"(b0), "r"(b1));
}
__device__ __forceinline__ void split_tf32(float x, unsigned& hi, unsigned& lo) {
    asm("cvt.rna.tf32.f32 %0, %1;" : "=r"(hi) : "f"(x));
    float l = x - __uint_as_float(hi);
    asm("cvt.rna.tf32.f32 %0, %1;" : "=r"(lo) : "f"(l));
}
#define CP16(dst_u32, src_ptr) \
    asm volatile("cp.async.ca.shared.global [%0], [%1], 16;" :: "r"(dst_u32), "l"(src_ptr))
__device__ __forceinline__ void cp_commit() { asm volatile("cp.async.commit_group;"); }
__device__ __forceinline__ void cp_wait1()  { asm volatile("cp.async.wait_group 1;"); }
__device__ __forceinline__ void cp_wait0()  { asm volatile("cp.async.wait_group 0;"); }

// smem geometry for the tf32 GEMMs
#define SA_STRIDE 20
#define SA_STAGE  (128 * SA_STRIDE)
#define SB_STAGE  (16 * 128)

// ---------------- kernel 1: LayerNorm(x) -> g_xn ----------------
__global__ void ln_x_kernel(const float* __restrict__ x,
                            const float* __restrict__ g,
                            const float* __restrict__ b) {
    int warp = threadIdx.x >> 5, lane = threadIdx.x & 31;
    int tok  = blockIdx.x * 8 + warp;
    const float* xp = x + (size_t)tok * 256 + lane * 8;
    float4 a0 = *(const float4*)xp;
    float4 a1 = *(const float4*)(xp + 4);
    float s  = a0.x + a0.y + a0.z + a0.w + a1.x + a1.y + a1.z + a1.w;
    float ss = a0.x*a0.x + a0.y*a0.y + a0.z*a0.z + a0.w*a0.w
             + a1.x*a1.x + a1.y*a1.y + a1.z*a1.z + a1.w*a1.w;
    #pragma unroll
    for (int off = 16; off; off >>= 1) {
        s  += __shfl_xor_sync(0xffffffffu, s,  off);
        ss += __shfl_xor_sync(0xffffffffu, ss, off);
    }
    float mu  = s * (1.0f / 256.0f);
    float var = ss * (1.0f / 256.0f) - mu * mu;
    float rs  = rsqrtf(var + 1e-5f);
    float4 g0 = *(const float4*)(g + lane * 8);
    float4 g1 = *(const float4*)(g + lane * 8 + 4);
    float4 b0 = *(const float4*)(b + lane * 8);
    float4 b1 = *(const float4*)(b + lane * 8 + 4);
    float* op = g_xn + (size_t)tok * 256 + lane * 8;
    float4 o0, o1;
    o0.x = (a0.x - mu) * rs * g0.x + b0.x;
    o0.y = (a0.y - mu) * rs * g0.y + b0.y;
    o0.z = (a0.z - mu) * rs * g0.z + b0.z;
    o0.w = (a0.w - mu) * rs * g0.w + b0.w;
    o1.x = (a1.x - mu) * rs * g1.x + b1.x;
    o1.y = (a1.y - mu) * rs * g1.y + b1.y;
    o1.z = (a1.z - mu) * rs * g1.z + b1.z;
    o1.w = (a1.w - mu) * rs * g1.w + b1.w;
    *(float4*)op = o0;
    *(float4*)(op + 4) = o1;
}

// ---------------- kernel 2: edge LN + W_edge + edge_mask -> g_bias[h][j][i] ----------------
__global__ void bias_kernel(const float* __restrict__ edges,
                            const float* __restrict__ lg,
                            const float* __restrict__ lb,
                            const float* __restrict__ We,
                            const unsigned int* __restrict__ emask) {
    __shared__ float sW[DEDGE * H_N];
    __shared__ float sg[DEDGE], sb[DEDGE];
    int t = threadIdx.x;
    for (int l = t; l < DEDGE * H_N; l += 256) sW[l] = We[l];
    if (t < DEDGE) { sg[t] = lg[t]; sb[t] = lb[t]; }
    __syncthreads();

    int warp = t >> 5, lane = t & 31;
    int p = blockIdx.x * 8 + warp;
    int i = p >> 8, j = p & 255;

    if (emask[p] == 0u) {
        if (lane < 8) g_bias[(lane * W_DIM + j) * W_DIM + i] = NEGMAX;
        return;
    }
    const float* ep = edges + (size_t)p * DEDGE + lane * 4;
    float4 e = *(const float4*)ep;
    float s  = e.x + e.y + e.z + e.w;
    float ss = e.x*e.x + e.y*e.y + e.z*e.z + e.w*e.w;
    #pragma unroll
    for (int off = 16; off; off >>= 1) {
        s  += __shfl_xor_sync(0xffffffffu, s,  off);
        ss += __shfl_xor_sync(0xffffffffu, ss, off);
    }
    float mu  = s * (1.0f / 128.0f);
    float var = ss * (1.0f / 128.0f) - mu * mu;
    float rs  = rsqrtf(var + 1e-5f);
    int e0 = lane * 4;
    float en[4];
    en[0] = (e.x - mu) * rs * sg[e0 + 0] + sb[e0 + 0];
    en[1] = (e.y - mu) * rs * sg[e0 + 1] + sb[e0 + 1];
    en[2] = (e.z - mu) * rs * sg[e0 + 2] + sb[e0 + 2];
    en[3] = (e.w - mu) * rs * sg[e0 + 3] + sb[e0 + 3];
    float acc[8];
    #pragma unroll
    for (int h = 0; h < 8; h++) acc[h] = 0.0f;
    #pragma unroll
    for (int c = 0; c < 4; c++) {
        const float* wr = &sW[(e0 + c) * 8];
        #pragma unroll
        for (int h = 0; h < 8; h++) acc[h] += en[c] * wr[h];
    }
    #pragma unroll
    for (int h = 0; h < 8; h++) {
        #pragma unroll
        for (int off = 16; off; off >>= 1)
            acc[h] += __shfl_xor_sync(0xffffffffu, acc[h], off);
    }
    if (lane == 0) {
        #pragma unroll
        for (int h = 0; h < 8; h++)
            g_bias[(h * W_DIM + j) * W_DIM + i] = acc[h];
    }
}

// ---------------- shared 3xTF32 mainloop body ----------------
#define MMA_KTILE_3XTF32(A0, B0)                                               \
    {                                                                          \
        unsigned bh[4][4], bl[4][4];                                           \
        _Pragma("unroll")                                                      \
        for (int an = 0; an < 4; an++) {                                       \
            int n = wn * 32 + an * 8 + g;                                      \
            split_tf32(B0[(c)      * 128 + n], bh[an][0], bl[an][0]);          \
            split_tf32(B0[(c + 4)  * 128 + n], bh[an][1], bl[an][1]);          \
            split_tf32(B0[(c + 8)  * 128 + n], bh[an][2], bl[an][2]);          \
            split_tf32(B0[(c + 12) * 128 + n], bh[an][3], bl[an][3]);          \
        }                                                                      \
        _Pragma("unroll")                                                      \
        for (int am = 0; am < 4; am++) {                                       \
            int m0 = (wm * 64 + am * 16 + g) * SA_STRIDE;                      \
            int m1 = m0 + 8 * SA_STRIDE;                                       \
            unsigned ah[8], al[8];                                             \
            split_tf32(A0[m0 + c],      ah[0], al[0]);                         \
            split_tf32(A0[m1 + c],      ah[1], al[1]);                         \
            split_tf32(A0[m0 + c + 4],  ah[2], al[2]);                         \
            split_tf32(A0[m1 + c + 4],  ah[3], al[3]);                         \
            split_tf32(A0[m0 + c + 8],  ah[4], al[4]);                         \
            split_tf32(A0[m1 + c + 8],  ah[5], al[5]);                         \
            split_tf32(A0[m0 + c + 12], ah[6], al[6]);                         \
            split_tf32(A0[m1 + c + 12], ah[7], al[7]);                         \
            _Pragma("unroll")                                                  \
            for (int an = 0; an < 4; an++) {                                   \
                float* ac = acc[am][an];                                       \
                mma_tf32(ac, ah[0], ah[1], ah[2], ah[3], bh[an][0], bh[an][1]);\
                mma_tf32(ac, ah[0], ah[1], ah[2], ah[3], bl[an][0], bl[an][1]);\
                mma_tf32(ac, al[0], al[1], al[2], al[3], bh[an][0], bh[an][1]);\
                mma_tf32(ac, ah[4], ah[5], ah[6], ah[7], bh[an][2], bh[an][3]);\
                mma_tf32(ac, ah[4], ah[5], ah[6], ah[7], bl[an][2], bl[an][3]);\
                mma_tf32(ac, al[4], al[5], al[6], al[7], bh[an][2], bh[an][3]);\
            }                                                                  \
        }                                                                      \
    }

// ---------------- kernel 3: projection GEMM via 3xTF32 mma.sync ----------------
__global__ void __launch_bounds__(256, 2)
proj_mma(const float* __restrict__ Wq, const float* __restrict__ Wkv,
         const float* __restrict__ Wg, const float* __restrict__ bg) {
    __shared__ float sA[2 * SA_STAGE];
    __shared__ float sB[2 * SB_STAGE];
    int t = threadIdx.x, lane = t & 31, warp = t >> 5;
    int wm = warp >> 2, wn = warp & 3;
    int g = lane >> 2, c = lane & 3;
    int bn = blockIdx.x, bm = blockIdx.y;

    int nb = bn * 128;
    const float* Bsrc; int ldb, col0;
    if (nb < 256)      { Bsrc = Wq;  ldb = 256; col0 = nb; }
    else if (nb < 768) { Bsrc = Wkv; ldb = 512; col0 = nb - 256; }
    else               { Bsrc = Wg;  ldb = 256; col0 = nb - 768; }

    const float* Ab = g_xn + (size_t)bm * 128 * 256;
    unsigned sA_u = (unsigned)__cvta_generic_to_shared(sA);
    unsigned sB_u = (unsigned)__cvta_generic_to_shared(sB);

    int a_row0 = t >> 2,         a_q0 = t & 3;
    int a_row1 = (t + 256) >> 2, a_q1 = t & 3;
    int b_k0 = t >> 5,           b_seg0 = t & 31;
    int b_k1 = (t + 256) >> 5,   b_seg1 = t & 31;

    float acc[4][4][4];
    #pragma unroll
    for (int am = 0; am < 4; am++)
        #pragma unroll
        for (int an = 0; an < 4; an++)
            #pragma unroll
            for (int v = 0; v < 4; v++) acc[am][an][v] = 0.0f;

    {
        CP16(sA_u + (a_row0 * SA_STRIDE + a_q0 * 4) * 4, Ab + (size_t)a_row0 * 256 + a_q0 * 4);
        CP16(sA_u + (a_row1 * SA_STRIDE + a_q1 * 4) * 4, Ab + (size_t)a_row1 * 256 + a_q1 * 4);
        CP16(sB_u + (b_k0 * 128 + b_seg0 * 4) * 4, Bsrc + (size_t)b_k0 * ldb + col0 + b_seg0 * 4);
        CP16(sB_u + (b_k1 * 128 + b_seg1 * 4) * 4, Bsrc + (size_t)b_k1 * ldb + col0 + b_seg1 * 4);
        cp_commit();
    }

    for (int kt = 0; kt < 16; kt++) {
        if (kt < 15) {
            int buf = (kt + 1) & 1;
            int kk = (kt + 1) * 16;
            CP16(sA_u + (buf * SA_STAGE + a_row0 * SA_STRIDE + a_q0 * 4) * 4,
                 Ab + (size_t)a_row0 * 256 + kk + a_q0 * 4);
            CP16(sA_u + (buf * SA_STAGE + a_row1 * SA_STRIDE + a_q1 * 4) * 4,
                 Ab + (size_t)a_row1 * 256 + kk + a_q1 * 4);
            CP16(sB_u + (buf * SB_STAGE + b_k0 * 128 + b_seg0 * 4) * 4,
                 Bsrc + (size_t)(kk + b_k0) * ldb + col0 + b_seg0 * 4);
            CP16(sB_u + (buf * SB_STAGE + b_k1 * 128 + b_seg1 * 4) * 4,
                 Bsrc + (size_t)(kk + b_k1) * ldb + col0 + b_seg1 * 4);
            cp_commit();
            cp_wait1();
        } else {
            cp_wait0();
        }
        __syncthreads();

        const float* A0 = sA + (kt & 1) * SA_STAGE;
        const float* B0 = sB + (kt & 1) * SB_STAGE;
        MMA_KTILE_3XTF32(A0, B0)
        __syncthreads();
    }

    if (nb < 768) {
        float* dst; int base;
        if (nb < 256)      { dst = g_q; base = 0; }
        else if (nb < 512) { dst = g_k; base = 256; }
        else               { dst = g_v; base = 512; }
        #pragma unroll
        for (int am = 0; am < 4; am++) {
            int tok = bm * 128 + wm * 64 + am * 16 + g;
            int rr = tok >> 8, iw = tok & 255;
            #pragma unroll
            for (int an = 0; an < 4; an++) {
                int gc = nb + wn * 32 + an * 8 + 2 * c;
                int cq = gc - base;
                int hh = cq >> 5, d8 = cq & 31;
                float* p0 = dst + ((size_t)((rr * 8 + hh) * 256 + iw)) * 32 + d8;
                float* p1 = p0 + 8 * 32;
                *(float2*)p0 = make_float2(acc[am][an][0], acc[am][an][1]);
                *(float2*)p1 = make_float2(acc[am][an][2], acc[am][an][3]);
            }
        }
    } else {
        #pragma unroll
        for (int am = 0; am < 4; am++) {
            int tok = bm * 128 + wm * 64 + am * 16 + g;
            #pragma unroll
            for (int an = 0; an < 4; an++) {
                int gc = nb + wn * 32 + an * 8 + 2 * c;
                int gcol = gc - 768;
                float2 bg2 = *(const float2*)(bg + gcol);
                float* p0 = g_gate + (size_t)tok * 256 + gcol;
                float* p1 = p0 + 8 * 256;
                float2 o0, o1;
                o0.x = 1.0f / (1.0f + __expf(-(acc[am][an][0] + bg2.x)));
                o0.y = 1.0f / (1.0f + __expf(-(acc[am][an][1] + bg2.y)));
                o1.x = 1.0f / (1.0f + __expf(-(acc[am][an][2] + bg2.x)));
                o1.y = 1.0f / (1.0f + __expf(-(acc[am][an][3] + bg2.y)));
                *(float2*)p0 = o0;
                *(float2*)p1 = o1;
            }
        }
    }
}

// ---------------- kernel 5: output projection via 3xTF32 mma.sync ----------------
__global__ void __launch_bounds__(256, 2)
out_mma(const float* __restrict__ Wo, const float* __restrict__ bo,
        float* __restrict__ out) {
    __shared__ float sA[2 * SA_STAGE];
    __shared__ float sB[2 * SB_STAGE];
    int t = threadIdx.x, lane = t & 31, warp = t >> 5;
    int wm = warp >> 2, wn = warp & 3;
    int g = lane >> 2, c = lane & 3;
    int bn = blockIdx.x, bm = blockIdx.y;
    int nb = bn * 128;

    const float* Ab = g_att + (size_t)bm * 128 * 256;
    unsigned sA_u = (unsigned)__cvta_generic_to_shared(sA);
    unsigned sB_u = (unsigned)__cvta_generic_to_shared(sB);

    int a_row0 = t >> 2,         a_q0 = t & 3;
    int a_row1 = (t + 256) >> 2, a_q1 = t & 3;
    int b_k0 = t >> 5,           b_seg0 = t & 31;
    int b_k1 = (t + 256) >> 5,   b_seg1 = t & 31;

    float acc[4][4][4];
    #pragma unroll
    for (int am = 0; am < 4; am++)
        #pragma unroll
        for (int an = 0; an < 4; an++)
            #pragma unroll
            for (int v = 0; v < 4; v++) acc[am][an][v] = 0.0f;

    {
        CP16(sA_u + (a_row0 * SA_STRIDE + a_q0 * 4) * 4, Ab + (size_t)a_row0 * 256 + a_q0 * 4);
        CP16(sA_u + (a_row1 * SA_STRIDE + a_q1 * 4) * 4, Ab + (size_t)a_row1 * 256 + a_q1 * 4);
        CP16(sB_u + (b_k0 * 128 + b_seg0 * 4) * 4, Wo + (size_t)b_k0 * 256 + nb + b_seg0 * 4);
        CP16(sB_u + (b_k1 * 128 + b_seg1 * 4) * 4, Wo + (size_t)b_k1 * 256 + nb + b_seg1 * 4);
        cp_commit();
    }

    for (int kt = 0; kt < 16; kt++) {
        if (kt < 15) {
            int buf = (kt + 1) & 1;
            int kk = (kt + 1) * 16;
            CP16(sA_u + (buf * SA_STAGE + a_row0 * SA_STRIDE + a_q0 * 4) * 4,
                 Ab + (size_t)a_row0 * 256 + kk + a_q0 * 4);
            CP16(sA_u + (buf * SA_STAGE + a_row1 * SA_STRIDE + a_q1 * 4) * 4,
                 Ab + (size_t)a_row1 * 256 + kk + a_q1 * 4);
            CP16(sB_u + (buf * SB_STAGE + b_k0 * 128 + b_seg0 * 4) * 4,
                 Wo + (size_t)(kk + b_k0) * 256 + nb + b_seg0 * 4);
            CP16(sB_u + (buf * SB_STAGE + b_k1 * 128 + b_seg1 * 4) * 4,
                 Wo + (size_t)(kk + b_k1) * 256 + nb + b_seg1 * 4);
            cp_commit();
            cp_wait1();
        } else {
            cp_wait0();
        }
        __syncthreads();

        const float* A0 = sA + (kt & 1) * SA_STAGE;
        const float* B0 = sB + (kt & 1) * SB_STAGE;
        MMA_KTILE_3XTF32(A0, B0)
        __syncthreads();
    }

    #pragma unroll
    for (int am = 0; am < 4; am++) {
        int tok = bm * 128 + wm * 64 + am * 16 + g;
        #pragma unroll
        for (int an = 0; an < 4; an++) {
            int gc = nb + wn * 32 + an * 8 + 2 * c;
            float2 bo2 = *(const float2*)(bo + gc);
            float* p0 = out + (size_t)tok * 256 + gc;
            float* p1 = p0 + 8 * 256;
            *(float2*)p0 = make_float2(acc[am][an][0] + bo2.x, acc[am][an][1] + bo2.y);
            *(float2*)p1 = make_float2(acc[am][an][2] + bo2.x, acc[am][an][3] + bo2.y);
        }
    }
}

// ---------------- kernel 4: fused attention, 3-stage cp.async pipeline ----------------
// one CTA per (r, h); 256 threads, thread i = query i; 32 chunks of 8 j's
#define JCH 8
#define NCH (W_DIM / JCH)       // 32
__global__ void __launch_bounds__(256, 2)
attn_kernel(const unsigned int* __restrict__ mask) {
    __shared__ float bias_s[3][JCH][256];   // 24 KB
    __shared__ float k_s[3][JCH][32];       // 3 KB
    __shared__ float v_s[3][JCH][32];       // 3 KB
    __shared__ unsigned char msk[256];

    int rh = blockIdx.x;
    int r = rh >> 3, h = rh & 7;
    int i = threadIdx.x;

    unsigned int mw = mask[r * 256 + i];
    msk[i] = (mw != 0u) ? 1 : 0;
    int mi = (mw != 0u) ? 1 : 0;

    const float sc = 0.17677669529663689f;   // 32^-0.5
    const float* qp = g_q + ((size_t)((r * 8 + h) * 256 + i)) * 32;
    const float* kbase = g_k + (size_t)((r * 8 + h) * 256) * 32;
    const float* vbase = g_v + (size_t)((r * 8 + h) * 256) * 32;
    const float* bbase = g_bias + (size_t)(h * 256) * 256;

    unsigned sb_u = (unsigned)__cvta_generic_to_shared(bias_s);
    unsigned sk_u = (unsigned)__cvta_generic_to_shared(k_s);
    unsigned sv_u = (unsigned)__cvta_generic_to_shared(v_s);

    // per-thread cp.async assignments (per chunk):
    // bias: 8 rows x 256 floats = 512 x 16B; thread handles idx=t and t+256
    int br0 = i >> 6,        bc0 = (i & 63) * 4;
    int br1 = (i + 256) >> 6, bc1 = (i & 63) * 4;
    // k/v: 8 rows x 32 floats = 64 x 16B
    int kr = i >> 3, kd = (i & 7) * 4;   // threads 0..63 -> k, 64..127 -> v

    unsigned long long q2[16];
    #pragma unroll
    for (int dd = 0; dd < 8; dd++) {
        float4 q4 = ((const float4*)qp)[dd];
        q2[2 * dd]     = f2pack(q4.x * sc, q4.y * sc);
        q2[2 * dd + 1] = f2pack(q4.z * sc, q4.w * sc);
    }

    unsigned long long acc2[16];
    #pragma unroll
    for (int dd = 0; dd < 16; dd++) acc2[dd] = 0ull;
    float l_sum = 0.0f;

    // issue chunk into stage ch%3
    #define ISSUE(ch)                                                              \
    {                                                                              \
        int st_ = (ch) % 3;                                                        \
        int j0_ = (ch) * JCH;                                                      \
        CP16(sb_u + ((st_ * JCH + br0) * 256 + bc0) * 4,                           \
             bbase + (size_t)(j0_ + br0) * 256 + bc0);                             \
        CP16(sb_u + ((st_ * JCH + br1 - 4) * 256 + bc1 + 4 * 256) * 4,             \
             bbase + (size_t)(j0_ + br1) * 256 + bc1);                             \
        if (i < 64) {                                                              \
            CP16(sk_u + ((st_ * JCH + kr) * 32 + kd) * 4,                          \
                 kbase + (size_t)(j0_ + kr) * 32 + kd);                            \
        } else if (i < 128) {                                                      \
            int kr_ = kr - 8, kd_ = kd;                                            \
            CP16(sv_u + ((st_ * JCH + kr_) * 32 + kd_) * 4,                        \
                 vbase + (size_t)(j0_ + kr_) * 32 + kd_);                          \
        }                                                                          \
        cp_commit();                                                               \
    }

    ISSUE(0)
    ISSUE(1)

    for (int ch = 0; ch < NCH; ch++) {
        if (ch < NCH - 1) cp_wait1(); else cp_wait0();
        __syncthreads();
        if (ch + 2 < NCH) ISSUE(ch + 2)

        int st = ch % 3;
        int j0 = ch * JCH;
        #pragma unroll
        for (int jj = 0; jj < JCH; jj++) {
            const ulonglong2* kp = (const ulonglong2*)&k_s[st][jj][0];
            unsigned long long d2a = 0ull, d2b = 0ull;
            #pragma unroll
            for (int dd = 0; dd < 8; dd++) {
                ulonglong2 kk2 = kp[dd];
                d2a = f2fma(q2[2 * dd],     kk2.x, d2a);
                d2b = f2fma(q2[2 * dd + 1], kk2.y, d2b);
            }
            float s0, s1, t0, t1;
            f2unpack(d2a, s0, s1);
            f2unpack(d2b, t0, t1);
            float s = (s0 + s1) + (t0 + t1) + bias_s[st][jj][i];
            if (!msk[j0 + jj]) s = NEGMAX;
            float p = mi ? __expf(s) : 1.0f;   // masked-i rows: uniform attention
            l_sum += p;
            unsigned long long p2 = f2dup(p);
            const ulonglong2* vp = (const ulonglong2*)&v_s[st][jj][0];
            #pragma unroll
            for (int dd = 0; dd < 8; dd++) {
                ulonglong2 vv = vp[dd];
                acc2[2 * dd]     = f2fma(p2, vv.x, acc2[2 * dd]);
                acc2[2 * dd + 1] = f2fma(p2, vv.y, acc2[2 * dd + 1]);
            }
        }
    }
    #undef ISSUE

    float inv = 1.0f / l_sum;
    const float* gp = g_gate + (size_t)(r * 256 + i) * 256 + h * 32;
    float* op       = g_att  + (size_t)(r * 256 + i) * 256 + h * 32;
    #pragma unroll
    for (int dd = 0; dd < 8; dd++) {
        float a, b2, c, d;
        f2unpack(acc2[2 * dd], a, b2);
        f2unpack(acc2[2 * dd + 1], c, d);
        float4 g4 = ((const float4*)gp)[dd];
        float4 o;
        o.x = a  * inv * g4.x;
        o.y = b2 * inv * g4.y;
        o.z = c  * inv * g4.z;
        o.w = d  * inv * g4.w;
        ((float4*)op)[dd] = o;
    }
}

// ---------------- launch ----------------
extern "C" void kernel_launch(void* const* d_in, const int* in_sizes, int n_in,
                              void* d_out, int out_size) {
    const float* x      = (const float*)d_in[0];
    const float* edges  = (const float*)d_in[1];
    const unsigned int* mask      = (const unsigned int*)d_in[2];
    const unsigned int* edge_mask = (const unsigned int*)d_in[3];
    const float* ln_g   = (const float*)d_in[4];
    const float* ln_b   = (const float*)d_in[5];
    const float* lne_g  = (const float*)d_in[6];
    const float* lne_b  = (const float*)d_in[7];
    const float* W_edge = (const float*)d_in[8];
    const float* Wq     = (const float*)d_in[9];
    const float* Wkv    = (const float*)d_in[10];
    const float* Wg     = (const float*)d_in[11];
    const float* bg     = (const float*)d_in[12];
    const float* Wo     = (const float*)d_in[13];
    const float* bo     = (const float*)d_in[14];
    float* out = (float*)d_out;

    ln_x_kernel<<<NTOK / 8, 256>>>(x, ln_g, ln_b);
    bias_kernel<<<(W_DIM * W_DIM) / 8, 256>>>(edges, lne_g, lne_b, W_edge, edge_mask);
    proj_mma<<<dim3(8, NTOK / 128), 256>>>(Wq, Wkv, Wg, bg);
    attn_kernel<<<R_DIM * H_N, 256>>>(mask);
    out_mma<<<dim3(2, NTOK / 128), 256>>>(Wo, bo, out);
}

// round 6
// speedup vs baseline: 1.1916x; 1.1111x over previous
#include <cuda_runtime.h>

// Problem constants
#define R_DIM 128
#define W_DIM 256
#define DNODE 256
#define DEDGE 128
#define H_N   8
#define DHEAD 32
#define NTOK  (R_DIM * W_DIM)       // 32768
#define NEGMAX (-3.4028234663852886e38f)

// ---------------- scratch (device globals: allocation-free) ----------------
__device__ float g_xn  [NTOK * DNODE];
__device__ float g_q   [NTOK * DNODE];          // [r][h][i][d]
__device__ float g_k   [NTOK * DNODE];          // [r][h][j][d]
__device__ float g_v   [NTOK * DNODE];          // [r][h][j][d]
__device__ float g_gate[NTOK * DNODE];
__device__ float g_att [NTOK * DNODE];
__device__ float g_bias[H_N * W_DIM * W_DIM];   // [h][j][i]

// ---------------- f32x2 helpers (attention kernel) ----------------
__device__ __forceinline__ unsigned long long f2dup(float x) {
    unsigned long long r;
    asm("mov.b64 %0, {%1, %1};" : "=l"(r) : "f"(x));
    return r;
}
__device__ __forceinline__ unsigned long long f2pack(float lo, float hi) {
    unsigned long long r;
    asm("mov.b64 %0, {%1, %2};" : "=l"(r) : "f"(lo), "f"(hi));
    return r;
}
__device__ __forceinline__ void f2unpack(unsigned long long v, float& lo, float& hi) {
    asm("mov.b64 {%0, %1}, %2;" : "=f"(lo), "=f"(hi) : "l"(v));
}
__device__ __forceinline__ unsigned long long f2fma(unsigned long long a,
                                                    unsigned long long b,
                                                    unsigned long long c) {
    unsigned long long d;
    asm("fma.rn.f32x2 %0, %1, %2, %3;" : "=l"(d) : "l"(a), "l"(b), "l"(c));
    return d;
}

// ---------------- tf32 mma helpers ----------------
__device__ __forceinline__ void mma_tf32(float* d,
                                         unsigned a0, unsigned a1, unsigned a2, unsigned a3,
                                         unsigned b0, unsigned b1) {
    asm volatile(
        "mma.sync.aligned.m16n8k8.row.col.f32.tf32.tf32.f32 "
        "{%0,%1,%2,%3}, {%4,%5,%6,%7}, {%8,%9}, {%0,%1,%2,%3};"
        : "+f"(d[0]), "+f"(d[1]), "+f"(d[2]), "+f"(d[3])
        : "r"(a0), "r"(a1), "r"(a2), "r"(a3), "r"(b0), "r"(b1));
}
__device__ __forceinline__ void split_tf32(float x, unsigned& hi, unsigned& lo) {
    asm("cvt.rna.tf32.f32 %0, %1;" : "=r"(hi) : "f"(x));
    float l = x - __uint_as_float(hi);
    asm("cvt.rna.tf32.f32 %0, %1;" : "=r"(lo) : "f"(l));
}
#define CP16(dst_u32, src_ptr) \
    asm volatile("cp.async.ca.shared.global [%0], [%1], 16;" :: "r"(dst_u32), "l"(src_ptr))
__device__ __forceinline__ void cp_commit() { asm volatile("cp.async.commit_group;"); }
__device__ __forceinline__ void cp_wait1()  { asm volatile("cp.async.wait_group 1;"); }
__device__ __forceinline__ void cp_wait0()  { asm volatile("cp.async.wait_group 0;"); }

// smem geometry for the tf32 GEMMs
#define SA_STRIDE 20
#define SA_STAGE  (128 * SA_STRIDE)
#define SB_STAGE  (16 * 128)

// ---------------- kernel 1: LayerNorm(x) -> g_xn ----------------
__global__ void ln_x_kernel(const float* __restrict__ x,
                            const float* __restrict__ g,
                            const float* __restrict__ b) {
    int warp = threadIdx.x >> 5, lane = threadIdx.x & 31;
    int tok  = blockIdx.x * 8 + warp;
    const float* xp = x + (size_t)tok * 256 + lane * 8;
    float4 a0 = *(const float4*)xp;
    float4 a1 = *(const float4*)(xp + 4);
    float s  = a0.x + a0.y + a0.z + a0.w + a1.x + a1.y + a1.z + a1.w;
    float ss = a0.x*a0.x + a0.y*a0.y + a0.z*a0.z + a0.w*a0.w
             + a1.x*a1.x + a1.y*a1.y + a1.z*a1.z + a1.w*a1.w;
    #pragma unroll
    for (int off = 16; off; off >>= 1) {
        s  += __shfl_xor_sync(0xffffffffu, s,  off);
        ss += __shfl_xor_sync(0xffffffffu, ss, off);
    }
    float mu  = s * (1.0f / 256.0f);
    float var = ss * (1.0f / 256.0f) - mu * mu;
    float rs  = rsqrtf(var + 1e-5f);
    float4 g0 = *(const float4*)(g + lane * 8);
    float4 g1 = *(const float4*)(g + lane * 8 + 4);
    float4 b0 = *(const float4*)(b + lane * 8);
    float4 b1 = *(const float4*)(b + lane * 8 + 4);
    float* op = g_xn + (size_t)tok * 256 + lane * 8;
    float4 o0, o1;
    o0.x = (a0.x - mu) * rs * g0.x + b0.x;
    o0.y = (a0.y - mu) * rs * g0.y + b0.y;
    o0.z = (a0.z - mu) * rs * g0.z + b0.z;
    o0.w = (a0.w - mu) * rs * g0.w + b0.w;
    o1.x = (a1.x - mu) * rs * g1.x + b1.x;
    o1.y = (a1.y - mu) * rs * g1.y + b1.y;
    o1.z = (a1.z - mu) * rs * g1.z + b1.z;
    o1.w = (a1.w - mu) * rs * g1.w + b1.w;
    *(float4*)op = o0;
    *(float4*)(op + 4) = o1;
}

// ---------------- kernel 2: edge LN + W_edge + edge_mask -> g_bias[h][j][i] ----------------
__global__ void bias_kernel(const float* __restrict__ edges,
                            const float* __restrict__ lg,
                            const float* __restrict__ lb,
                            const float* __restrict__ We,
                            const unsigned int* __restrict__ emask) {
    __shared__ float sW[DEDGE * H_N];
    __shared__ float sg[DEDGE], sb[DEDGE];
    int t = threadIdx.x;
    for (int l = t; l < DEDGE * H_N; l += 256) sW[l] = We[l];
    if (t < DEDGE) { sg[t] = lg[t]; sb[t] = lb[t]; }
    __syncthreads();

    int warp = t >> 5, lane = t & 31;
    int p = blockIdx.x * 8 + warp;
    int i = p >> 8, j = p & 255;

    if (emask[p] == 0u) {
        if (lane < 8) g_bias[(lane * W_DIM + j) * W_DIM + i] = NEGMAX;
        return;
    }
    const float* ep = edges + (size_t)p * DEDGE + lane * 4;
    float4 e = *(const float4*)ep;
    float s  = e.x + e.y + e.z + e.w;
    float ss = e.x*e.x + e.y*e.y + e.z*e.z + e.w*e.w;
    #pragma unroll
    for (int off = 16; off; off >>= 1) {
        s  += __shfl_xor_sync(0xffffffffu, s,  off);
        ss += __shfl_xor_sync(0xffffffffu, ss, off);
    }
    float mu  = s * (1.0f / 128.0f);
    float var = ss * (1.0f / 128.0f) - mu * mu;
    float rs  = rsqrtf(var + 1e-5f);
    int e0 = lane * 4;
    float en[4];
    en[0] = (e.x - mu) * rs * sg[e0 + 0] + sb[e0 + 0];
    en[1] = (e.y - mu) * rs * sg[e0 + 1] + sb[e0 + 1];
    en[2] = (e.z - mu) * rs * sg[e0 + 2] + sb[e0 + 2];
    en[3] = (e.w - mu) * rs * sg[e0 + 3] + sb[e0 + 3];
    float acc[8];
    #pragma unroll
    for (int h = 0; h < 8; h++) acc[h] = 0.0f;
    #pragma unroll
    for (int c = 0; c < 4; c++) {
        const float* wr = &sW[(e0 + c) * 8];
        #pragma unroll
        for (int h = 0; h < 8; h++) acc[h] += en[c] * wr[h];
    }
    #pragma unroll
    for (int h = 0; h < 8; h++) {
        #pragma unroll
        for (int off = 16; off; off >>= 1)
            acc[h] += __shfl_xor_sync(0xffffffffu, acc[h], off);
    }
    if (lane == 0) {
        #pragma unroll
        for (int h = 0; h < 8; h++)
            g_bias[(h * W_DIM + j) * W_DIM + i] = acc[h];
    }
}

// ---------------- shared 3xTF32 mainloop body ----------------
#define MMA_KTILE_3XTF32(A0, B0)                                               \
    {                                                                          \
        unsigned bh[4][4], bl[4][4];                                           \
        _Pragma("unroll")                                                      \
        for (int an = 0; an < 4; an++) {                                       \
            int n = wn * 32 + an * 8 + g;                                      \
            split_tf32(B0[(c)      * 128 + n], bh[an][0], bl[an][0]);          \
            split_tf32(B0[(c + 4)  * 128 + n], bh[an][1], bl[an][1]);          \
            split_tf32(B0[(c + 8)  * 128 + n], bh[an][2], bl[an][2]);          \
            split_tf32(B0[(c + 12) * 128 + n], bh[an][3], bl[an][3]);          \
        }                                                                      \
        _Pragma("unroll")                                                      \
        for (int am = 0; am < 4; am++) {                                       \
            int m0 = (wm * 64 + am * 16 + g) * SA_STRIDE;                      \
            int m1 = m0 + 8 * SA_STRIDE;                                       \
            unsigned ah[8], al[8];                                             \
            split_tf32(A0[m0 + c],      ah[0], al[0]);                         \
            split_tf32(A0[m1 + c],      ah[1], al[1]);                         \
            split_tf32(A0[m0 + c + 4],  ah[2], al[2]);                         \
            split_tf32(A0[m1 + c + 4],  ah[3], al[3]);                         \
            split_tf32(A0[m0 + c + 8],  ah[4], al[4]);                         \
            split_tf32(A0[m1 + c + 8],  ah[5], al[5]);                         \
            split_tf32(A0[m0 + c + 12], ah[6], al[6]);                         \
            split_tf32(A0[m1 + c + 12], ah[7], al[7]);                         \
            _Pragma("unroll")                                                  \
            for (int an = 0; an < 4; an++) {                                   \
                float* ac = acc[am][an];                                       \
                mma_tf32(ac, ah[0], ah[1], ah[2], ah[3], bh[an][0], bh[an][1]);\
                mma_tf32(ac, ah[0], ah[1], ah[2], ah[3], bl[an][0], bl[an][1]);\
                mma_tf32(ac, al[0], al[1], al[2], al[3], bh[an][0], bh[an][1]);\
                mma_tf32(ac, ah[4], ah[5], ah[6], ah[7], bh[an][2], bh[an][3]);\
                mma_tf32(ac, ah[4], ah[5], ah[6], ah[7], bl[an][2], bl[an][3]);\
                mma_tf32(ac, al[4], al[5], al[6], al[7], bh[an][2], bh[an][3]);\
            }                                                                  \
        }                                                                      \
    }

// ---------------- kernel 3: projection GEMM via 3xTF32 mma.sync ----------------
__global__ void __launch_bounds__(256, 2)
proj_mma(const float* __restrict__ Wq, const float* __restrict__ Wkv,
         const float* __restrict__ Wg, const float* __restrict__ bg) {
    __shared__ float sA[2 * SA_STAGE];
    __shared__ float sB[2 * SB_STAGE];
    int t = threadIdx.x, lane = t & 31, warp = t >> 5;
    int wm = warp >> 2, wn = warp & 3;
    int g = lane >> 2, c = lane & 3;
    int bn = blockIdx.x, bm = blockIdx.y;

    int nb = bn * 128;
    const float* Bsrc; int ldb, col0;
    if (nb < 256)      { Bsrc = Wq;  ldb = 256; col0 = nb; }
    else if (nb < 768) { Bsrc = Wkv; ldb = 512; col0 = nb - 256; }
    else               { Bsrc = Wg;  ldb = 256; col0 = nb - 768; }

    const float* Ab = g_xn + (size_t)bm * 128 * 256;
    unsigned sA_u = (unsigned)__cvta_generic_to_shared(sA);
    unsigned sB_u = (unsigned)__cvta_generic_to_shared(sB);

    int a_row0 = t >> 2,         a_q0 = t & 3;
    int a_row1 = (t + 256) >> 2, a_q1 = t & 3;
    int b_k0 = t >> 5,           b_seg0 = t & 31;
    int b_k1 = (t + 256) >> 5,   b_seg1 = t & 31;

    float acc[4][4][4];
    #pragma unroll
    for (int am = 0; am < 4; am++)
        #pragma unroll
        for (int an = 0; an < 4; an++)
            #pragma unroll
            for (int v = 0; v < 4; v++) acc[am][an][v] = 0.0f;

    {
        CP16(sA_u + (a_row0 * SA_STRIDE + a_q0 * 4) * 4, Ab + (size_t)a_row0 * 256 + a_q0 * 4);
        CP16(sA_u + (a_row1 * SA_STRIDE + a_q1 * 4) * 4, Ab + (size_t)a_row1 * 256 + a_q1 * 4);
        CP16(sB_u + (b_k0 * 128 + b_seg0 * 4) * 4, Bsrc + (size_t)b_k0 * ldb + col0 + b_seg0 * 4);
        CP16(sB_u + (b_k1 * 128 + b_seg1 * 4) * 4, Bsrc + (size_t)b_k1 * ldb + col0 + b_seg1 * 4);
        cp_commit();
    }

    for (int kt = 0; kt < 16; kt++) {
        if (kt < 15) {
            int buf = (kt + 1) & 1;
            int kk = (kt + 1) * 16;
            CP16(sA_u + (buf * SA_STAGE + a_row0 * SA_STRIDE + a_q0 * 4) * 4,
                 Ab + (size_t)a_row0 * 256 + kk + a_q0 * 4);
            CP16(sA_u + (buf * SA_STAGE + a_row1 * SA_STRIDE + a_q1 * 4) * 4,
                 Ab + (size_t)a_row1 * 256 + kk + a_q1 * 4);
            CP16(sB_u + (buf * SB_STAGE + b_k0 * 128 + b_seg0 * 4) * 4,
                 Bsrc + (size_t)(kk + b_k0) * ldb + col0 + b_seg0 * 4);
            CP16(sB_u + (buf * SB_STAGE + b_k1 * 128 + b_seg1 * 4) * 4,
                 Bsrc + (size_t)(kk + b_k1) * ldb + col0 + b_seg1 * 4);
            cp_commit();
            cp_wait1();
        } else {
            cp_wait0();
        }
        __syncthreads();

        const float* A0 = sA + (kt & 1) * SA_STAGE;
        const float* B0 = sB + (kt & 1) * SB_STAGE;
        MMA_KTILE_3XTF32(A0, B0)
        __syncthreads();
    }

    if (nb < 768) {
        float* dst; int base;
        if (nb < 256)      { dst = g_q; base = 0; }
        else if (nb < 512) { dst = g_k; base = 256; }
        else               { dst = g_v; base = 512; }
        #pragma unroll
        for (int am = 0; am < 4; am++) {
            int tok = bm * 128 + wm * 64 + am * 16 + g;
            int rr = tok >> 8, iw = tok & 255;
            #pragma unroll
            for (int an = 0; an < 4; an++) {
                int gc = nb + wn * 32 + an * 8 + 2 * c;
                int cq = gc - base;
                int hh = cq >> 5, d8 = cq & 31;
                float* p0 = dst + ((size_t)((rr * 8 + hh) * 256 + iw)) * 32 + d8;
                float* p1 = p0 + 8 * 32;
                *(float2*)p0 = make_float2(acc[am][an][0], acc[am][an][1]);
                *(float2*)p1 = make_float2(acc[am][an][2], acc[am][an][3]);
            }
        }
    } else {
        #pragma unroll
        for (int am = 0; am < 4; am++) {
            int tok = bm * 128 + wm * 64 + am * 16 + g;
            #pragma unroll
            for (int an = 0; an < 4; an++) {
                int gc = nb + wn * 32 + an * 8 + 2 * c;
                int gcol = gc - 768;
                float2 bg2 = *(const float2*)(bg + gcol);
                float* p0 = g_gate + (size_t)tok * 256 + gcol;
                float* p1 = p0 + 8 * 256;
                float2 o0, o1;
                o0.x = 1.0f / (1.0f + __expf(-(acc[am][an][0] + bg2.x)));
                o0.y = 1.0f / (1.0f + __expf(-(acc[am][an][1] + bg2.y)));
                o1.x = 1.0f / (1.0f + __expf(-(acc[am][an][2] + bg2.x)));
                o1.y = 1.0f / (1.0f + __expf(-(acc[am][an][3] + bg2.y)));
                *(float2*)p0 = o0;
                *(float2*)p1 = o1;
            }
        }
    }
}

// ---------------- kernel 5: output projection via 3xTF32 mma.sync ----------------
__global__ void __launch_bounds__(256, 2)
out_mma(const float* __restrict__ Wo, const float* __restrict__ bo,
        float* __restrict__ out) {
    __shared__ float sA[2 * SA_STAGE];
    __shared__ float sB[2 * SB_STAGE];
    int t = threadIdx.x, lane = t & 31, warp = t >> 5;
    int wm = warp >> 2, wn = warp & 3;
    int g = lane >> 2, c = lane & 3;
    int bn = blockIdx.x, bm = blockIdx.y;
    int nb = bn * 128;

    const float* Ab = g_att + (size_t)bm * 128 * 256;
    unsigned sA_u = (unsigned)__cvta_generic_to_shared(sA);
    unsigned sB_u = (unsigned)__cvta_generic_to_shared(sB);

    int a_row0 = t >> 2,         a_q0 = t & 3;
    int a_row1 = (t + 256) >> 2, a_q1 = t & 3;
    int b_k0 = t >> 5,           b_seg0 = t & 31;
    int b_k1 = (t + 256) >> 5,   b_seg1 = t & 31;

    float acc[4][4][4];
    #pragma unroll
    for (int am = 0; am < 4; am++)
        #pragma unroll
        for (int an = 0; an < 4; an++)
            #pragma unroll
            for (int v = 0; v < 4; v++) acc[am][an][v] = 0.0f;

    {
        CP16(sA_u + (a_row0 * SA_STRIDE + a_q0 * 4) * 4, Ab + (size_t)a_row0 * 256 + a_q0 * 4);
        CP16(sA_u + (a_row1 * SA_STRIDE + a_q1 * 4) * 4, Ab + (size_t)a_row1 * 256 + a_q1 * 4);
        CP16(sB_u + (b_k0 * 128 + b_seg0 * 4) * 4, Wo + (size_t)b_k0 * 256 + nb + b_seg0 * 4);
        CP16(sB_u + (b_k1 * 128 + b_seg1 * 4) * 4, Wo + (size_t)b_k1 * 256 + nb + b_seg1 * 4);
        cp_commit();
    }

    for (int kt = 0; kt < 16; kt++) {
        if (kt < 15) {
            int buf = (kt + 1) & 1;
            int kk = (kt + 1) * 16;
            CP16(sA_u + (buf * SA_STAGE + a_row0 * SA_STRIDE + a_q0 * 4) * 4,
                 Ab + (size_t)a_row0 * 256 + kk + a_q0 * 4);
            CP16(sA_u + (buf * SA_STAGE + a_row1 * SA_STRIDE + a_q1 * 4) * 4,
                 Ab + (size_t)a_row1 * 256 + kk + a_q1 * 4);
            CP16(sB_u + (buf * SB_STAGE + b_k0 * 128 + b_seg0 * 4) * 4,
                 Wo + (size_t)(kk + b_k0) * 256 + nb + b_seg0 * 4);
            CP16(sB_u + (buf * SB_STAGE + b_k1 * 128 + b_seg1 * 4) * 4,
                 Wo + (size_t)(kk + b_k1) * 256 + nb + b_seg1 * 4);
            cp_commit();
            cp_wait1();
        } else {
            cp_wait0();
        }
        __syncthreads();

        const float* A0 = sA + (kt & 1) * SA_STAGE;
        const float* B0 = sB + (kt & 1) * SB_STAGE;
        MMA_KTILE_3XTF32(A0, B0)
        __syncthreads();
    }

    #pragma unroll
    for (int am = 0; am < 4; am++) {
        int tok = bm * 128 + wm * 64 + am * 16 + g;
        #pragma unroll
        for (int an = 0; an < 4; an++) {
            int gc = nb + wn * 32 + an * 8 + 2 * c;
            float2 bo2 = *(const float2*)(bo + gc);
            float* p0 = out + (size_t)tok * 256 + gc;
            float* p1 = p0 + 8 * 256;
            *(float2*)p0 = make_float2(acc[am][an][0] + bo2.x, acc[am][an][1] + bo2.y);
            *(float2*)p1 = make_float2(acc[am][an][2] + bo2.x, acc[am][an][3] + bo2.y);
        }
    }
}

// ---------------- kernel 4: fused attention, 2 queries/thread + cp.async pipeline ----
// one CTA per (r, h); 128 threads; thread i handles queries i and i+128
#define JCH 8
#define NCH (W_DIM / JCH)       // 32
__global__ void __launch_bounds__(128, 2)
attn_kernel(const unsigned int* __restrict__ mask) {
    __shared__ float bias_s[3][JCH][256];   // 24 KB
    __shared__ float k_s[3][JCH][32];       // 3 KB
    __shared__ float v_s[3][JCH][32];       // 3 KB
    __shared__ unsigned char msk[256];

    int rh = blockIdx.x;
    int r = rh >> 3, h = rh & 7;
    int i = threadIdx.x;                    // 0..127

    unsigned int mw0 = mask[r * 256 + i];
    unsigned int mw1 = mask[r * 256 + i + 128];
    msk[i]       = (mw0 != 0u) ? 1 : 0;
    msk[i + 128] = (mw1 != 0u) ? 1 : 0;
    int mi0 = (mw0 != 0u) ? 1 : 0;
    int mi1 = (mw1 != 0u) ? 1 : 0;

    const float sc = 0.17677669529663689f;  // 32^-0.5
    const float* qbase = g_q + (size_t)((r * 8 + h) * 256) * 32;
    const float* kbase = g_k + (size_t)((r * 8 + h) * 256) * 32;
    const float* vbase = g_v + (size_t)((r * 8 + h) * 256) * 32;
    const float* bbase = g_bias + (size_t)(h * 256) * 256;

    unsigned sb_u = (unsigned)__cvta_generic_to_shared(bias_s);
    unsigned sk_u = (unsigned)__cvta_generic_to_shared(k_s);
    unsigned sv_u = (unsigned)__cvta_generic_to_shared(v_s);

    // per-chunk cp.async assignments (128 threads):
    // bias: 8 rows x 256 floats = 512 float4; thread does idx = i, i+128, i+256, i+384
    int br = i >> 6;            // 0..1
    int bc = (i & 63) * 4;
    // k/v: 8 rows x 32 floats = 64 float4; threads 0..63 -> K, 64..127 -> V
    int kr = (i & 63) >> 3, kd = (i & 7) * 4;

    // q fragments for both queries
    unsigned long long q2a[16], q2b[16];
    {
        const float* qp0 = qbase + (size_t)i * 32;
        const float* qp1 = qbase + (size_t)(i + 128) * 32;
        #pragma unroll
        for (int dd = 0; dd < 8; dd++) {
            float4 q4 = ((const float4*)qp0)[dd];
            q2a[2 * dd]     = f2pack(q4.x * sc, q4.y * sc);
            q2a[2 * dd + 1] = f2pack(q4.z * sc, q4.w * sc);
            float4 q5 = ((const float4*)qp1)[dd];
            q2b[2 * dd]     = f2pack(q5.x * sc, q5.y * sc);
            q2b[2 * dd + 1] = f2pack(q5.z * sc, q5.w * sc);
        }
    }

    unsigned long long acc2a[16], acc2b[16];
    #pragma unroll
    for (int dd = 0; dd < 16; dd++) { acc2a[dd] = 0ull; acc2b[dd] = 0ull; }
    float l0 = 0.0f, l1 = 0.0f;

    #define ISSUE(ch)                                                              \
    {                                                                              \
        int st_ = (ch) % 3;                                                        \
        int j0_ = (ch) * JCH;                                                      \
        CP16(sb_u + ((st_ * JCH + br)     * 256 + bc) * 4,                         \
             bbase + (size_t)(j0_ + br)     * 256 + bc);                           \
        CP16(sb_u + ((st_ * JCH + br + 2) * 256 + bc) * 4,                         \
             bbase + (size_t)(j0_ + br + 2) * 256 + bc);                           \
        CP16(sb_u + ((st_ * JCH + br + 4) * 256 + bc) * 4,                         \
             bbase + (size_t)(j0_ + br + 4) * 256 + bc);                           \
        CP16(sb_u + ((st_ * JCH + br + 6) * 256 + bc) * 4,                         \
             bbase + (size_t)(j0_ + br + 6) * 256 + bc);                           \
        if (i < 64) {                                                              \
            CP16(sk_u + ((st_ * JCH + kr) * 32 + kd) * 4,                          \
                 kbase + (size_t)(j0_ + kr) * 32 + kd);                            \
        } else {                                                                   \
            CP16(sv_u + ((st_ * JCH + kr) * 32 + kd) * 4,                          \
                 vbase + (size_t)(j0_ + kr) * 32 + kd);                            \
        }                                                                          \
        cp_commit();                                                               \
    }

    ISSUE(0)
    ISSUE(1)

    for (int ch = 0; ch < NCH; ch++) {
        if (ch < NCH - 1) cp_wait1(); else cp_wait0();
        __syncthreads();
        if (ch + 2 < NCH) ISSUE(ch + 2)

        int st = ch % 3;
        int j0 = ch * JCH;
        #pragma unroll
        for (int jj = 0; jj < JCH; jj++) {
            const ulonglong2* kp = (const ulonglong2*)&k_s[st][jj][0];
            unsigned long long d0a = 0ull, d0b = 0ull, d1a = 0ull, d1b = 0ull;
            #pragma unroll
            for (int dd = 0; dd < 8; dd++) {
                ulonglong2 kk2 = kp[dd];
                d0a = f2fma(q2a[2 * dd],     kk2.x, d0a);
                d0b = f2fma(q2a[2 * dd + 1], kk2.y, d0b);
                d1a = f2fma(q2b[2 * dd],     kk2.x, d1a);
                d1b = f2fma(q2b[2 * dd + 1], kk2.y, d1b);
            }
            float x0, x1, y0, y1, z0, z1, w0, w1;
            f2unpack(d0a, x0, x1); f2unpack(d0b, y0, y1);
            f2unpack(d1a, z0, z1); f2unpack(d1b, w0, w1);
            float s0 = (x0 + x1) + (y0 + y1) + bias_s[st][jj][i];
            float s1 = (z0 + z1) + (w0 + w1) + bias_s[st][jj][i + 128];
            if (!msk[j0 + jj]) { s0 = NEGMAX; s1 = NEGMAX; }
            float p0 = mi0 ? __expf(s0) : 1.0f;   // fully-masked rows: uniform attention
            float p1 = mi1 ? __expf(s1) : 1.0f;
            l0 += p0; l1 += p1;
            unsigned long long p20 = f2dup(p0);
            unsigned long long p21 = f2dup(p1);
            const ulonglong2* vp = (const ulonglong2*)&v_s[st][jj][0];
            #pragma unroll
            for (int dd = 0; dd < 8; dd++) {
                ulonglong2 vv = vp[dd];
                acc2a[2 * dd]     = f2fma(p20, vv.x, acc2a[2 * dd]);
                acc2a[2 * dd + 1] = f2fma(p20, vv.y, acc2a[2 * dd + 1]);
                acc2b[2 * dd]     = f2fma(p21, vv.x, acc2b[2 * dd]);
                acc2b[2 * dd + 1] = f2fma(p21, vv.y, acc2b[2 * dd + 1]);
            }
        }
    }
    #undef ISSUE

    float inv0 = 1.0f / l0;
    float inv1 = 1.0f / l1;
    {
        const float* gp = g_gate + (size_t)(r * 256 + i) * 256 + h * 32;
        float* op       = g_att  + (size_t)(r * 256 + i) * 256 + h * 32;
        #pragma unroll
        for (int dd = 0; dd < 8; dd++) {
            float a, b2, c, d;
            f2unpack(acc2a[2 * dd], a, b2);
            f2unpack(acc2a[2 * dd + 1], c, d);
            float4 g4 = ((const float4*)gp)[dd];
            float4 o;
            o.x = a  * inv0 * g4.x;
            o.y = b2 * inv0 * g4.y;
            o.z = c  * inv0 * g4.z;
            o.w = d  * inv0 * g4.w;
            ((float4*)op)[dd] = o;
        }
    }
    {
        const float* gp = g_gate + (size_t)(r * 256 + i + 128) * 256 + h * 32;
        float* op       = g_att  + (size_t)(r * 256 + i + 128) * 256 + h * 32;
        #pragma unroll
        for (int dd = 0; dd < 8; dd++) {
            float a, b2, c, d;
            f2unpack(acc2b[2 * dd], a, b2);
            f2unpack(acc2b[2 * dd + 1], c, d);
            float4 g4 = ((const float4*)gp)[dd];
            float4 o;
            o.x = a  * inv1 * g4.x;
            o.y = b2 * inv1 * g4.y;
            o.z = c  * inv1 * g4.z;
            o.w = d  * inv1 * g4.w;
            ((float4*)op)[dd] = o;
        }
    }
}

// ---------------- launch ----------------
extern "C" void kernel_launch(void* const* d_in, const int* in_sizes, int n_in,
                              void* d_out, int out_size) {
    const float* x      = (const float*)d_in[0];
    const float* edges  = (const float*)d_in[1];
    const unsigned int* mask      = (const unsigned int*)d_in[2];
    const unsigned int* edge_mask = (const unsigned int*)d_in[3];
    const float* ln_g   = (const float*)d_in[4];
    const float* ln_b   = (const float*)d_in[5];
    const float* lne_g  = (const float*)d_in[6];
    const float* lne_b  = (const float*)d_in[7];
    const float* W_edge = (const float*)d_in[8];
    const float* Wq     = (const float*)d_in[9];
    const float* Wkv    = (const float*)d_in[10];
    const float* Wg     = (const float*)d_in[11];
    const float* bg     = (const float*)d_in[12];
    const float* Wo     = (const float*)d_in[13];
    const float* bo     = (const float*)d_in[14];
    float* out = (float*)d_out;

    ln_x_kernel<<<NTOK / 8, 256>>>(x, ln_g, ln_b);
    bias_kernel<<<(W_DIM * W_DIM) / 8, 256>>>(edges, lne_g, lne_b, W_edge, edge_mask);
    proj_mma<<<dim3(8, NTOK / 128), 256>>>(Wq, Wkv, Wg, bg);
    attn_kernel<<<R_DIM * H_N, 128>>>(mask);
    out_mma<<<dim3(2, NTOK / 128), 256>>>(Wo, bo, out);
}

// round 7
// speedup vs baseline: 1.4754x; 1.2382x over previous
#include <cuda_runtime.h>
#include <cuda_bf16.h>

// Problem constants
#define R_DIM 128
#define W_DIM 256
#define DNODE 256
#define DEDGE 128
#define H_N   8
#define DHEAD 32
#define NTOK  (R_DIM * W_DIM)       // 32768
#define NEGMAX (-3.4028234663852886e38f)

// ---------------- scratch (device globals: allocation-free) ----------------
__device__ float g_q   [NTOK * DNODE];          // [r][h][i][d]
__device__ float g_k   [NTOK * DNODE];          // [r][h][j][d]
__device__ float g_v   [NTOK * DNODE];          // [r][h][j][d]
__device__ float g_gate[NTOK * DNODE];
__device__ float g_bias[H_N * W_DIM * W_DIM];   // [h][j][i]
// bf16 split planes (hi + lo ~= fp32)
__device__ __nv_bfloat16 g_xnh [NTOK * DNODE];  // LN(x) hi, [tok][k]
__device__ __nv_bfloat16 g_xnl [NTOK * DNODE];  // LN(x) lo
__device__ __nv_bfloat16 g_atth[NTOK * DNODE];  // gated attn out hi, [tok][k]
__device__ __nv_bfloat16 g_attl[NTOK * DNODE];
__device__ __nv_bfloat16 g_wph [1024 * 256];    // [n][k]: Wq|Wk|Wv|Wg transposed, hi
__device__ __nv_bfloat16 g_wpl [1024 * 256];
__device__ __nv_bfloat16 g_woh [256 * 256];     // Wo transposed [n][k], hi
__device__ __nv_bfloat16 g_wol [256 * 256];

// ---------------- f32x2 helpers (attention kernel) ----------------
__device__ __forceinline__ unsigned long long f2dup(float x) {
    unsigned long long r;
    asm("mov.b64 %0, {%1, %1};" : "=l"(r) : "f"(x));
    return r;
}
__device__ __forceinline__ unsigned long long f2pack(float lo, float hi) {
    unsigned long long r;
    asm("mov.b64 %0, {%1, %2};" : "=l"(r) : "f"(lo), "f"(hi));
    return r;
}
__device__ __forceinline__ void f2unpack(unsigned long long v, float& lo, float& hi) {
    asm("mov.b64 {%0, %1}, %2;" : "=f"(lo), "=f"(hi) : "l"(v));
}
__device__ __forceinline__ unsigned long long f2fma(unsigned long long a,
                                                    unsigned long long b,
                                                    unsigned long long c) {
    unsigned long long d;
    asm("fma.rn.f32x2 %0, %1, %2, %3;" : "=l"(d) : "l"(a), "l"(b), "l"(c));
    return d;
}

// ---------------- bf16 helpers ----------------
__device__ __forceinline__ void mma_bf16(float* d,
                                         unsigned a0, unsigned a1, unsigned a2, unsigned a3,
                                         unsigned b0, unsigned b1) {
    asm volatile(
        "mma.sync.aligned.m16n8k16.row.col.f32.bf16.bf16.f32 "
        "{%0,%1,%2,%3}, {%4,%5,%6,%7}, {%8,%9}, {%0,%1,%2,%3};"
        : "+f"(d[0]), "+f"(d[1]), "+f"(d[2]), "+f"(d[3])
        : "r"(a0), "r"(a1), "r"(a2), "r"(a3), "r"(b0), "r"(b1));
}
__device__ __forceinline__ void split_bf16(float x, __nv_bfloat16& hi, __nv_bfloat16& lo) {
    hi = __float2bfloat16(x);
    lo = __float2bfloat16(x - __bfloat162float(hi));
}
__device__ __forceinline__ unsigned bfpack(__nv_bfloat16 a, __nv_bfloat16 b) {
    return (unsigned)__bfloat16_as_ushort(a) | ((unsigned)__bfloat16_as_ushort(b) << 16);
}
#define CP16(dst_u32, src_ptr) \
    asm volatile("cp.async.ca.shared.global [%0], [%1], 16;" :: "r"(dst_u32), "l"(src_ptr))
__device__ __forceinline__ void cp_commit() { asm volatile("cp.async.commit_group;"); }
__device__ __forceinline__ void cp_wait1()  { asm volatile("cp.async.wait_group 1;"); }
__device__ __forceinline__ void cp_wait0()  { asm volatile("cp.async.wait_group 0;"); }

// smem row stride (bf16 units): 16 data + 8 pad = 48B, conflict-free & 16B aligned
#define RS 24
#define PLANE (128 * RS)   // bf16 elems per stage plane

// ---------------- kernel 1: LayerNorm(x) -> bf16 split planes ----------------
__global__ void ln_x_kernel(const float* __restrict__ x,
                            const float* __restrict__ g,
                            const float* __restrict__ b) {
    int warp = threadIdx.x >> 5, lane = threadIdx.x & 31;
    int tok  = blockIdx.x * 8 + warp;
    const float* xp = x + (size_t)tok * 256 + lane * 8;
    float4 a0 = *(const float4*)xp;
    float4 a1 = *(const float4*)(xp + 4);
    float s  = a0.x + a0.y + a0.z + a0.w + a1.x + a1.y + a1.z + a1.w;
    float ss = a0.x*a0.x + a0.y*a0.y + a0.z*a0.z + a0.w*a0.w
             + a1.x*a1.x + a1.y*a1.y + a1.z*a1.z + a1.w*a1.w;
    #pragma unroll
    for (int off = 16; off; off >>= 1) {
        s  += __shfl_xor_sync(0xffffffffu, s,  off);
        ss += __shfl_xor_sync(0xffffffffu, ss, off);
    }
    float mu  = s * (1.0f / 256.0f);
    float var = ss * (1.0f / 256.0f) - mu * mu;
    float rs  = rsqrtf(var + 1e-5f);
    float4 g0 = *(const float4*)(g + lane * 8);
    float4 g1 = *(const float4*)(g + lane * 8 + 4);
    float4 b0 = *(const float4*)(b + lane * 8);
    float4 b1 = *(const float4*)(b + lane * 8 + 4);
    float v[8];
    v[0] = (a0.x - mu) * rs * g0.x + b0.x;
    v[1] = (a0.y - mu) * rs * g0.y + b0.y;
    v[2] = (a0.z - mu) * rs * g0.z + b0.z;
    v[3] = (a0.w - mu) * rs * g0.w + b0.w;
    v[4] = (a1.x - mu) * rs * g1.x + b1.x;
    v[5] = (a1.y - mu) * rs * g1.y + b1.y;
    v[6] = (a1.z - mu) * rs * g1.z + b1.z;
    v[7] = (a1.w - mu) * rs * g1.w + b1.w;
    unsigned hu[4], lu[4];
    #pragma unroll
    for (int p = 0; p < 4; p++) {
        __nv_bfloat16 h0, l0, h1, l1;
        split_bf16(v[2 * p], h0, l0);
        split_bf16(v[2 * p + 1], h1, l1);
        hu[p] = bfpack(h0, h1);
        lu[p] = bfpack(l0, l1);
    }
    size_t off = (size_t)tok * 256 + lane * 8;
    *(uint4*)&g_xnh[off] = make_uint4(hu[0], hu[1], hu[2], hu[3]);
    *(uint4*)&g_xnl[off] = make_uint4(lu[0], lu[1], lu[2], lu[3]);
}

// ---------------- kernel 1b: weight split+transpose -> [n][k] bf16 planes ----------
// grid 1280 blocks (n), 256 threads (k). n<1024: proj weights; else Wo.
__global__ void wsplit_kernel(const float* __restrict__ Wq, const float* __restrict__ Wkv,
                              const float* __restrict__ Wg, const float* __restrict__ Wo) {
    int n = blockIdx.x, k = threadIdx.x;
    float w;
    if (n < 256)       w = Wq [(size_t)k * 256 + n];
    else if (n < 768)  w = Wkv[(size_t)k * 512 + (n - 256)];
    else if (n < 1024) w = Wg [(size_t)k * 256 + (n - 768)];
    else               w = Wo [(size_t)k * 256 + (n - 1024)];
    __nv_bfloat16 h, l;
    split_bf16(w, h, l);
    if (n < 1024) {
        g_wph[(size_t)n * 256 + k] = h;
        g_wpl[(size_t)n * 256 + k] = l;
    } else {
        g_woh[(size_t)(n - 1024) * 256 + k] = h;
        g_wol[(size_t)(n - 1024) * 256 + k] = l;
    }
}

// ---------------- kernel 2: edge LN + W_edge + edge_mask -> g_bias[h][j][i] ----------------
__global__ void bias_kernel(const float* __restrict__ edges,
                            const float* __restrict__ lg,
                            const float* __restrict__ lb,
                            const float* __restrict__ We,
                            const unsigned int* __restrict__ emask) {
    __shared__ float sW[DEDGE * H_N];
    __shared__ float sg[DEDGE], sb[DEDGE];
    int t = threadIdx.x;
    for (int l = t; l < DEDGE * H_N; l += 256) sW[l] = We[l];
    if (t < DEDGE) { sg[t] = lg[t]; sb[t] = lb[t]; }
    __syncthreads();

    int warp = t >> 5, lane = t & 31;
    int p = blockIdx.x * 8 + warp;
    int i = p >> 8, j = p & 255;

    if (emask[p] == 0u) {
        if (lane < 8) g_bias[(lane * W_DIM + j) * W_DIM + i] = NEGMAX;
        return;
    }
    const float* ep = edges + (size_t)p * DEDGE + lane * 4;
    float4 e = *(const float4*)ep;
    float s  = e.x + e.y + e.z + e.w;
    float ss = e.x*e.x + e.y*e.y + e.z*e.z + e.w*e.w;
    #pragma unroll
    for (int off = 16; off; off >>= 1) {
        s  += __shfl_xor_sync(0xffffffffu, s,  off);
        ss += __shfl_xor_sync(0xffffffffu, ss, off);
    }
    float mu  = s * (1.0f / 128.0f);
    float var = ss * (1.0f / 128.0f) - mu * mu;
    float rs  = rsqrtf(var + 1e-5f);
    int e0 = lane * 4;
    float en[4];
    en[0] = (e.x - mu) * rs * sg[e0 + 0] + sb[e0 + 0];
    en[1] = (e.y - mu) * rs * sg[e0 + 1] + sb[e0 + 1];
    en[2] = (e.z - mu) * rs * sg[e0 + 2] + sb[e0 + 2];
    en[3] = (e.w - mu) * rs * sg[e0 + 3] + sb[e0 + 3];
    float acc[8];
    #pragma unroll
    for (int h = 0; h < 8; h++) acc[h] = 0.0f;
    #pragma unroll
    for (int c = 0; c < 4; c++) {
        const float* wr = &sW[(e0 + c) * 8];
        #pragma unroll
        for (int h = 0; h < 8; h++) acc[h] += en[c] * wr[h];
    }
    #pragma unroll
    for (int h = 0; h < 8; h++) {
        #pragma unroll
        for (int off = 16; off; off >>= 1)
            acc[h] += __shfl_xor_sync(0xffffffffu, acc[h], off);
    }
    if (lane == 0) {
        #pragma unroll
        for (int h = 0; h < 8; h++)
            g_bias[(h * W_DIM + j) * W_DIM + i] = acc[h];
    }
}

// ---------------- bf16x3 GEMM mainloop pieces (shared by proj/out) ----------------
// smem: 4 planes x 2 stages x 128 rows x RS bf16 = 49152 B exactly
#define GEMM_SMEM()                                                            \
    __shared__ __nv_bfloat16 sAh[2][PLANE], sAl[2][PLANE];                     \
    __shared__ __nv_bfloat16 sBh[2][PLANE], sBl[2][PLANE];

#define GEMM_ISSUE(buf, kt, Ahp, Alp, Bhp, Blp, abase, nbase)                  \
    {                                                                          \
        int k0 = (kt) * 16 + ch;                                               \
        CP16(sAh_u + ((buf) * PLANE + row * RS + ch) * 2,                      \
             (Ahp) + (size_t)((abase) + row) * 256 + k0);                      \
        CP16(sAl_u + ((buf) * PLANE + row * RS + ch) * 2,                      \
             (Alp) + (size_t)((abase) + row) * 256 + k0);                      \
        CP16(sBh_u + ((buf) * PLANE + row * RS + ch) * 2,                      \
             (Bhp) + (size_t)((nbase) + row) * 256 + k0);                      \
        CP16(sBl_u + ((buf) * PLANE + row * RS + ch) * 2,                      \
             (Blp) + (size_t)((nbase) + row) * 256 + k0);                      \
        cp_commit();                                                           \
    }

#define GEMM_KTILE(st)                                                         \
    {                                                                          \
        const __nv_bfloat16* Ah0 = &sAh[st][0];                                \
        const __nv_bfloat16* Al0 = &sAl[st][0];                                \
        const __nv_bfloat16* Bh0 = &sBh[st][0];                                \
        const __nv_bfloat16* Bl0 = &sBl[st][0];                                \
        unsigned bh0[4], bh1[4], bl0[4], bl1[4];                               \
        _Pragma("unroll")                                                      \
        for (int an = 0; an < 4; an++) {                                       \
            int off = (wn * 32 + an * 8 + g) * RS + 2 * c;                     \
            bh0[an] = *(const unsigned*)&Bh0[off];                             \
            bh1[an] = *(const unsigned*)&Bh0[off + 8];                         \
            bl0[an] = *(const unsigned*)&Bl0[off];                             \
            bl1[an] = *(const unsigned*)&Bl0[off + 8];                         \
        }                                                                      \
        _Pragma("unroll")                                                      \
        for (int am = 0; am < 4; am++) {                                       \
            int o0 = (wm * 64 + am * 16 + g) * RS + 2 * c;                     \
            int o1 = o0 + 8 * RS;                                              \
            unsigned ah0 = *(const unsigned*)&Ah0[o0];                         \
            unsigned ah1 = *(const unsigned*)&Ah0[o1];                         \
            unsigned ah2 = *(const unsigned*)&Ah0[o0 + 8];                     \
            unsigned ah3 = *(const unsigned*)&Ah0[o1 + 8];                     \
            unsigned al0 = *(const unsigned*)&Al0[o0];                         \
            unsigned al1 = *(const unsigned*)&Al0[o1];                         \
            unsigned al2 = *(const unsigned*)&Al0[o0 + 8];                     \
            unsigned al3 = *(const unsigned*)&Al0[o1 + 8];                     \
            _Pragma("unroll")                                                  \
            for (int an = 0; an < 4; an++) {                                   \
                float* ac = acc[am][an];                                       \
                mma_bf16(ac, ah0, ah1, ah2, ah3, bh0[an], bh1[an]);            \
                mma_bf16(ac, ah0, ah1, ah2, ah3, bl0[an], bl1[an]);            \
                mma_bf16(ac, al0, al1, al2, al3, bh0[an], bh1[an]);            \
            }                                                                  \
        }                                                                      \
    }

// ---------------- kernel 3: projection GEMM (bf16x3) ----------------
// C[32768 x 1024] = xn @ W; BM=128, BN=128, BK=16; warps 2x4, warp tile 64x32
__global__ void __launch_bounds__(256, 2)
proj_mma(const float* __restrict__ bg) {
    GEMM_SMEM()
    int t = threadIdx.x, lane = t & 31, warp = t >> 5;
    int wm = warp >> 2, wn = warp & 3;
    int g = lane >> 2, c = lane & 3;
    int bn = blockIdx.x, bm = blockIdx.y;
    int nb = bn * 128;
    int abase = bm * 128;

    unsigned sAh_u = (unsigned)__cvta_generic_to_shared(sAh);
    unsigned sAl_u = (unsigned)__cvta_generic_to_shared(sAl);
    unsigned sBh_u = (unsigned)__cvta_generic_to_shared(sBh);
    unsigned sBl_u = (unsigned)__cvta_generic_to_shared(sBl);
    int row = t >> 1, ch = (t & 1) * 8;   // per-thread cp.async: row + 8-elem chunk

    float acc[4][4][4];
    #pragma unroll
    for (int am = 0; am < 4; am++)
        #pragma unroll
        for (int an = 0; an < 4; an++)
            #pragma unroll
            for (int v = 0; v < 4; v++) acc[am][an][v] = 0.0f;

    GEMM_ISSUE(0, 0, g_xnh, g_xnl, g_wph, g_wpl, abase, nb)

    for (int kt = 0; kt < 16; kt++) {
        if (kt < 15) {
            GEMM_ISSUE((kt + 1) & 1, kt + 1, g_xnh, g_xnl, g_wph, g_wpl, abase, nb)
            cp_wait1();
        } else {
            cp_wait0();
        }
        __syncthreads();
        GEMM_KTILE(kt & 1)
        __syncthreads();
    }

    if (nb < 768) {
        float* dst; int base;
        if (nb < 256)      { dst = g_q; base = 0; }
        else if (nb < 512) { dst = g_k; base = 256; }
        else               { dst = g_v; base = 512; }
        #pragma unroll
        for (int am = 0; am < 4; am++) {
            int tok = abase + wm * 64 + am * 16 + g;
            int rr = tok >> 8, iw = tok & 255;
            #pragma unroll
            for (int an = 0; an < 4; an++) {
                int gc = nb + wn * 32 + an * 8 + 2 * c;
                int cq = gc - base;
                int hh = cq >> 5, d8 = cq & 31;
                float* p0 = dst + ((size_t)((rr * 8 + hh) * 256 + iw)) * 32 + d8;
                float* p1 = p0 + 8 * 32;
                *(float2*)p0 = make_float2(acc[am][an][0], acc[am][an][1]);
                *(float2*)p1 = make_float2(acc[am][an][2], acc[am][an][3]);
            }
        }
    } else {
        #pragma unroll
        for (int am = 0; am < 4; am++) {
            int tok = abase + wm * 64 + am * 16 + g;
            #pragma unroll
            for (int an = 0; an < 4; an++) {
                int gc = nb + wn * 32 + an * 8 + 2 * c;
                int gcol = gc - 768;
                float2 bg2 = *(const float2*)(bg + gcol);
                float* p0 = g_gate + (size_t)tok * 256 + gcol;
                float* p1 = p0 + 8 * 256;
                float2 o0, o1;
                o0.x = 1.0f / (1.0f + __expf(-(acc[am][an][0] + bg2.x)));
                o0.y = 1.0f / (1.0f + __expf(-(acc[am][an][1] + bg2.y)));
                o1.x = 1.0f / (1.0f + __expf(-(acc[am][an][2] + bg2.x)));
                o1.y = 1.0f / (1.0f + __expf(-(acc[am][an][3] + bg2.y)));
                *(float2*)p0 = o0;
                *(float2*)p1 = o1;
            }
        }
    }
}

// ---------------- kernel 5: output projection (bf16x3) ----------------
__global__ void __launch_bounds__(256, 2)
out_mma(const float* __restrict__ bo, float* __restrict__ out) {
    GEMM_SMEM()
    int t = threadIdx.x, lane = t & 31, warp = t >> 5;
    int wm = warp >> 2, wn = warp & 3;
    int g = lane >> 2, c = lane & 3;
    int bn = blockIdx.x, bm = blockIdx.y;
    int nb = bn * 128;
    int abase = bm * 128;

    unsigned sAh_u = (unsigned)__cvta_generic_to_shared(sAh);
    unsigned sAl_u = (unsigned)__cvta_generic_to_shared(sAl);
    unsigned sBh_u = (unsigned)__cvta_generic_to_shared(sBh);
    unsigned sBl_u = (unsigned)__cvta_generic_to_shared(sBl);
    int row = t >> 1, ch = (t & 1) * 8;

    float acc[4][4][4];
    #pragma unroll
    for (int am = 0; am < 4; am++)
        #pragma unroll
        for (int an = 0; an < 4; an++)
            #pragma unroll
            for (int v = 0; v < 4; v++) acc[am][an][v] = 0.0f;

    GEMM_ISSUE(0, 0, g_atth, g_attl, g_woh, g_wol, abase, nb)

    for (int kt = 0; kt < 16; kt++) {
        if (kt < 15) {
            GEMM_ISSUE((kt + 1) & 1, kt + 1, g_atth, g_attl, g_woh, g_wol, abase, nb)
            cp_wait1();
        } else {
            cp_wait0();
        }
        __syncthreads();
        GEMM_KTILE(kt & 1)
        __syncthreads();
    }

    #pragma unroll
    for (int am = 0; am < 4; am++) {
        int tok = abase + wm * 64 + am * 16 + g;
        #pragma unroll
        for (int an = 0; an < 4; an++) {
            int gc = nb + wn * 32 + an * 8 + 2 * c;
            float2 bo2 = *(const float2*)(bo + gc);
            float* p0 = out + (size_t)tok * 256 + gc;
            float* p1 = p0 + 8 * 256;
            *(float2*)p0 = make_float2(acc[am][an][0] + bo2.x, acc[am][an][1] + bo2.y);
            *(float2*)p1 = make_float2(acc[am][an][2] + bo2.x, acc[am][an][3] + bo2.y);
        }
    }
}

// ---------------- kernel 4: fused attention, 2 queries/thread + cp.async pipeline ----
#define JCH 8
#define NCH (W_DIM / JCH)       // 32
__global__ void __launch_bounds__(128, 2)
attn_kernel(const unsigned int* __restrict__ mask) {
    __shared__ float bias_s[3][JCH][256];   // 24 KB
    __shared__ float k_s[3][JCH][32];       // 3 KB
    __shared__ float v_s[3][JCH][32];       // 3 KB
    __shared__ unsigned char msk[256];

    int rh = blockIdx.x;
    int r = rh >> 3, h = rh & 7;
    int i = threadIdx.x;                    // 0..127

    unsigned int mw0 = mask[r * 256 + i];
    unsigned int mw1 = mask[r * 256 + i + 128];
    msk[i]       = (mw0 != 0u) ? 1 : 0;
    msk[i + 128] = (mw1 != 0u) ? 1 : 0;
    int mi0 = (mw0 != 0u) ? 1 : 0;
    int mi1 = (mw1 != 0u) ? 1 : 0;

    const float sc = 0.17677669529663689f;  // 32^-0.5
    const float* qbase = g_q + (size_t)((r * 8 + h) * 256) * 32;
    const float* kbase = g_k + (size_t)((r * 8 + h) * 256) * 32;
    const float* vbase = g_v + (size_t)((r * 8 + h) * 256) * 32;
    const float* bbase = g_bias + (size_t)(h * 256) * 256;

    unsigned sb_u = (unsigned)__cvta_generic_to_shared(bias_s);
    unsigned sk_u = (unsigned)__cvta_generic_to_shared(k_s);
    unsigned sv_u = (unsigned)__cvta_generic_to_shared(v_s);

    int br = i >> 6;            // 0..1
    int bc = (i & 63) * 4;
    int kr = (i & 63) >> 3, kd = (i & 7) * 4;

    unsigned long long q2a[16], q2b[16];
    {
        const float* qp0 = qbase + (size_t)i * 32;
        const float* qp1 = qbase + (size_t)(i + 128) * 32;
        #pragma unroll
        for (int dd = 0; dd < 8; dd++) {
            float4 q4 = ((const float4*)qp0)[dd];
            q2a[2 * dd]     = f2pack(q4.x * sc, q4.y * sc);
            q2a[2 * dd + 1] = f2pack(q4.z * sc, q4.w * sc);
            float4 q5 = ((const float4*)qp1)[dd];
            q2b[2 * dd]     = f2pack(q5.x * sc, q5.y * sc);
            q2b[2 * dd + 1] = f2pack(q5.z * sc, q5.w * sc);
        }
    }

    unsigned long long acc2a[16], acc2b[16];
    #pragma unroll
    for (int dd = 0; dd < 16; dd++) { acc2a[dd] = 0ull; acc2b[dd] = 0ull; }
    float l0 = 0.0f, l1 = 0.0f;

    #define ISSUE(ch)                                                              \
    {                                                                              \
        int st_ = (ch) % 3;                                                        \
        int j0_ = (ch) * JCH;                                                      \
        CP16(sb_u + ((st_ * JCH + br)     * 256 + bc) * 4,                         \
             bbase + (size_t)(j0_ + br)     * 256 + bc);                           \
        CP16(sb_u + ((st_ * JCH + br + 2) * 256 + bc) * 4,                         \
             bbase + (size_t)(j0_ + br + 2) * 256 + bc);                           \
        CP16(sb_u + ((st_ * JCH + br + 4) * 256 + bc) * 4,                         \
             bbase + (size_t)(j0_ + br + 4) * 256 + bc);                           \
        CP16(sb_u + ((st_ * JCH + br + 6) * 256 + bc) * 4,                         \
             bbase + (size_t)(j0_ + br + 6) * 256 + bc);                           \
        if (i < 64) {                                                              \
            CP16(sk_u + ((st_ * JCH + kr) * 32 + kd) * 4,                          \
                 kbase + (size_t)(j0_ + kr) * 32 + kd);                            \
        } else {                                                                   \
            CP16(sv_u + ((st_ * JCH + kr) * 32 + kd) * 4,                          \
                 vbase + (size_t)(j0_ + kr) * 32 + kd);                            \
        }                                                                          \
        cp_commit();                                                               \
    }

    ISSUE(0)
    ISSUE(1)

    for (int ch = 0; ch < NCH; ch++) {
        if (ch < NCH - 1) cp_wait1(); else cp_wait0();
        __syncthreads();
        if (ch + 2 < NCH) ISSUE(ch + 2)

        int st = ch % 3;
        int j0 = ch * JCH;
        #pragma unroll
        for (int jj = 0; jj < JCH; jj++) {
            const ulonglong2* kp = (const ulonglong2*)&k_s[st][jj][0];
            unsigned long long d0a = 0ull, d0b = 0ull, d1a = 0ull, d1b = 0ull;
            #pragma unroll
            for (int dd = 0; dd < 8; dd++) {
                ulonglong2 kk2 = kp[dd];
                d0a = f2fma(q2a[2 * dd],     kk2.x, d0a);
                d0b = f2fma(q2a[2 * dd + 1], kk2.y, d0b);
                d1a = f2fma(q2b[2 * dd],     kk2.x, d1a);
                d1b = f2fma(q2b[2 * dd + 1], kk2.y, d1b);
            }
            float x0, x1, y0, y1, z0, z1, w0, w1;
            f2unpack(d0a, x0, x1); f2unpack(d0b, y0, y1);
            f2unpack(d1a, z0, z1); f2unpack(d1b, w0, w1);
            float s0 = (x0 + x1) + (y0 + y1) + bias_s[st][jj][i];
            float s1 = (z0 + z1) + (w0 + w1) + bias_s[st][jj][i + 128];
            if (!msk[j0 + jj]) { s0 = NEGMAX; s1 = NEGMAX; }
            float p0 = mi0 ? __expf(s0) : 1.0f;
            float p1 = mi1 ? __expf(s1) : 1.0f;
            l0 += p0; l1 += p1;
            unsigned long long p20 = f2dup(p0);
            unsigned long long p21 = f2dup(p1);
            const ulonglong2* vp = (const ulonglong2*)&v_s[st][jj][0];
            #pragma unroll
            for (int dd = 0; dd < 8; dd++) {
                ulonglong2 vv = vp[dd];
                acc2a[2 * dd]     = f2fma(p20, vv.x, acc2a[2 * dd]);
                acc2a[2 * dd + 1] = f2fma(p20, vv.y, acc2a[2 * dd + 1]);
                acc2b[2 * dd]     = f2fma(p21, vv.x, acc2b[2 * dd]);
                acc2b[2 * dd + 1] = f2fma(p21, vv.y, acc2b[2 * dd + 1]);
            }
        }
    }
    #undef ISSUE

    float inv0 = 1.0f / l0;
    float inv1 = 1.0f / l1;
    // epilogue: gate, then bf16-split store for the out-projection GEMM
    #pragma unroll
    for (int q = 0; q < 2; q++) {
        int tok = r * 256 + i + q * 128;
        const unsigned long long* ac = q ? acc2b : acc2a;
        float inv = q ? inv1 : inv0;
        const float* gp = g_gate + (size_t)tok * 256 + h * 32;
        size_t ob = (size_t)tok * 256 + h * 32;
        #pragma unroll
        for (int dd = 0; dd < 8; dd++) {
            float a, b2, cc, d;
            f2unpack(ac[2 * dd], a, b2);
            f2unpack(ac[2 * dd + 1], cc, d);
            float4 g4 = ((const float4*)gp)[dd];
            float o0 = a  * inv * g4.x;
            float o1 = b2 * inv * g4.y;
            float o2 = cc * inv * g4.z;
            float o3 = d  * inv * g4.w;
            __nv_bfloat16 h0, l0b, h1, l1b, h2, l2b, h3, l3b;
            split_bf16(o0, h0, l0b);
            split_bf16(o1, h1, l1b);
            split_bf16(o2, h2, l2b);
            split_bf16(o3, h3, l3b);
            *(unsigned*)&g_atth[ob + dd * 4]     = bfpack(h0, h1);
            *(unsigned*)&g_atth[ob + dd * 4 + 2] = bfpack(h2, h3);
            *(unsigned*)&g_attl[ob + dd * 4]     = bfpack(l0b, l1b);
            *(unsigned*)&g_attl[ob + dd * 4 + 2] = bfpack(l2b, l3b);
        }
    }
}

// ---------------- launch ----------------
extern "C" void kernel_launch(void* const* d_in, const int* in_sizes, int n_in,
                              void* d_out, int out_size) {
    const float* x      = (const float*)d_in[0];
    const float* edges  = (const float*)d_in[1];
    const unsigned int* mask      = (const unsigned int*)d_in[2];
    const unsigned int* edge_mask = (const unsigned int*)d_in[3];
    const float* ln_g   = (const float*)d_in[4];
    const float* ln_b   = (const float*)d_in[5];
    const float* lne_g  = (const float*)d_in[6];
    const float* lne_b  = (const float*)d_in[7];
    const float* W_edge = (const float*)d_in[8];
    const float* Wq     = (const float*)d_in[9];
    const float* Wkv    = (const float*)d_in[10];
    const float* Wg     = (const float*)d_in[11];
    const float* bg     = (const float*)d_in[12];
    const float* Wo     = (const float*)d_in[13];
    const float* bo     = (const float*)d_in[14];
    float* out = (float*)d_out;

    ln_x_kernel<<<NTOK / 8, 256>>>(x, ln_g, ln_b);
    wsplit_kernel<<<1280, 256>>>(Wq, Wkv, Wg, Wo);
    bias_kernel<<<(W_DIM * W_DIM) / 8, 256>>>(edges, lne_g, lne_b, W_edge, edge_mask);
    proj_mma<<<dim3(8, NTOK / 128), 256>>>(bg);
    attn_kernel<<<R_DIM * H_N, 128>>>(mask);
    out_mma<<<dim3(2, NTOK / 128), 256>>>(bo, out);
}

// round 8
// speedup vs baseline: 1.6060x; 1.0885x over previous
#include <cuda_runtime.h>
#include <cuda_bf16.h>

// Problem constants
#define R_DIM 128
#define W_DIM 256
#define DNODE 256
#define DEDGE 128
#define H_N   8
#define DHEAD 32
#define NTOK  (R_DIM * W_DIM)       // 32768
#define NEGMAX (-3.4028234663852886e38f)

// ---------------- scratch (device globals: allocation-free) ----------------
__device__ float g_q   [NTOK * DNODE];          // [r][h][i][d]
__device__ float g_k   [NTOK * DNODE];          // [r][h][j][d]
__device__ float g_v   [NTOK * DNODE];          // [r][h][j][d]
__device__ float g_gate[NTOK * DNODE];
__device__ float g_bias[H_N * W_DIM * W_DIM];   // [h][j][i]
// bf16 split planes (hi + lo ~= fp32)
__device__ __nv_bfloat16 g_xnh [NTOK * DNODE];
__device__ __nv_bfloat16 g_xnl [NTOK * DNODE];
__device__ __nv_bfloat16 g_atth[NTOK * DNODE];
__device__ __nv_bfloat16 g_attl[NTOK * DNODE];
__device__ __nv_bfloat16 g_wph [1024 * 256];    // [n][k]
__device__ __nv_bfloat16 g_wpl [1024 * 256];
__device__ __nv_bfloat16 g_woh [256 * 256];
__device__ __nv_bfloat16 g_wol [256 * 256];

// ---------------- f32x2 helpers (attention kernel) ----------------
__device__ __forceinline__ unsigned long long f2dup(float x) {
    unsigned long long r;
    asm("mov.b64 %0, {%1, %1};" : "=l"(r) : "f"(x));
    return r;
}
__device__ __forceinline__ unsigned long long f2pack(float lo, float hi) {
    unsigned long long r;
    asm("mov.b64 %0, {%1, %2};" : "=l"(r) : "f"(lo), "f"(hi));
    return r;
}
__device__ __forceinline__ void f2unpack(unsigned long long v, float& lo, float& hi) {
    asm("mov.b64 {%0, %1}, %2;" : "=f"(lo), "=f"(hi) : "l"(v));
}
__device__ __forceinline__ unsigned long long f2fma(unsigned long long a,
                                                    unsigned long long b,
                                                    unsigned long long c) {
    unsigned long long d;
    asm("fma.rn.f32x2 %0, %1, %2, %3;" : "=l"(d) : "l"(a), "l"(b), "l"(c));
    return d;
}

// ---------------- bf16 helpers ----------------
__device__ __forceinline__ void mma_bf16(float* d,
                                         unsigned a0, unsigned a1, unsigned a2, unsigned a3,
                                         unsigned b0, unsigned b1) {
    asm volatile(
        "mma.sync.aligned.m16n8k16.row.col.f32.bf16.bf16.f32 "
        "{%0,%1,%2,%3}, {%4,%5,%6,%7}, {%8,%9}, {%0,%1,%2,%3};"
        : "+f"(d[0]), "+f"(d[1]), "+f"(d[2]), "+f"(d[3])
        : "r"(a0), "r"(a1), "r"(a2), "r"(a3), "r"(b0), "r"(b1));
}
__device__ __forceinline__ void split_bf16(float x, __nv_bfloat16& hi, __nv_bfloat16& lo) {
    hi = __float2bfloat16(x);
    lo = __float2bfloat16(x - __bfloat162float(hi));
}
__device__ __forceinline__ unsigned bfpack(__nv_bfloat16 a, __nv_bfloat16 b) {
    return (unsigned)__bfloat16_as_ushort(a) | ((unsigned)__bfloat16_as_ushort(b) << 16);
}
#define CP16(dst_u32, src_ptr) \
    asm volatile("cp.async.ca.shared.global [%0], [%1], 16;" :: "r"(dst_u32), "l"(src_ptr))
__device__ __forceinline__ void cp_commit() { asm volatile("cp.async.commit_group;"); }
__device__ __forceinline__ void cp_wait0()  { asm volatile("cp.async.wait_group 0;"); }
__device__ __forceinline__ void cp_wait1()  { asm volatile("cp.async.wait_group 1;"); }
#define LDSM4(r0, r1, r2, r3, addr) \
    asm volatile("ldmatrix.sync.aligned.m8n8.x4.shared.b16 {%0,%1,%2,%3}, [%4];" \
        : "=r"(r0), "=r"(r1), "=r"(r2), "=r"(r3) : "r"(addr));

// smem row stride (bf16 units): 16 data + 8 pad = 48B (16B aligned, LDSM conflict-free)
#define RS 24
#define PLANE (128 * RS)

// ---------------- kernel 1: LayerNorm(x) -> bf16 split planes ----------------
__global__ void ln_x_kernel(const float* __restrict__ x,
                            const float* __restrict__ g,
                            const float* __restrict__ b) {
    int warp = threadIdx.x >> 5, lane = threadIdx.x & 31;
    int tok  = blockIdx.x * 8 + warp;
    const float* xp = x + (size_t)tok * 256 + lane * 8;
    float4 a0 = *(const float4*)xp;
    float4 a1 = *(const float4*)(xp + 4);
    float s  = a0.x + a0.y + a0.z + a0.w + a1.x + a1.y + a1.z + a1.w;
    float ss = a0.x*a0.x + a0.y*a0.y + a0.z*a0.z + a0.w*a0.w
             + a1.x*a1.x + a1.y*a1.y + a1.z*a1.z + a1.w*a1.w;
    #pragma unroll
    for (int off = 16; off; off >>= 1) {
        s  += __shfl_xor_sync(0xffffffffu, s,  off);
        ss += __shfl_xor_sync(0xffffffffu, ss, off);
    }
    float mu  = s * (1.0f / 256.0f);
    float var = ss * (1.0f / 256.0f) - mu * mu;
    float rs  = rsqrtf(var + 1e-5f);
    float4 g0 = *(const float4*)(g + lane * 8);
    float4 g1 = *(const float4*)(g + lane * 8 + 4);
    float4 b0 = *(const float4*)(b + lane * 8);
    float4 b1 = *(const float4*)(b + lane * 8 + 4);
    float v[8];
    v[0] = (a0.x - mu) * rs * g0.x + b0.x;
    v[1] = (a0.y - mu) * rs * g0.y + b0.y;
    v[2] = (a0.z - mu) * rs * g0.z + b0.z;
    v[3] = (a0.w - mu) * rs * g0.w + b0.w;
    v[4] = (a1.x - mu) * rs * g1.x + b1.x;
    v[5] = (a1.y - mu) * rs * g1.y + b1.y;
    v[6] = (a1.z - mu) * rs * g1.z + b1.z;
    v[7] = (a1.w - mu) * rs * g1.w + b1.w;
    unsigned hu[4], lu[4];
    #pragma unroll
    for (int p = 0; p < 4; p++) {
        __nv_bfloat16 h0, l0, h1, l1;
        split_bf16(v[2 * p], h0, l0);
        split_bf16(v[2 * p + 1], h1, l1);
        hu[p] = bfpack(h0, h1);
        lu[p] = bfpack(l0, l1);
    }
    size_t off = (size_t)tok * 256 + lane * 8;
    *(uint4*)&g_xnh[off] = make_uint4(hu[0], hu[1], hu[2], hu[3]);
    *(uint4*)&g_xnl[off] = make_uint4(lu[0], lu[1], lu[2], lu[3]);
}

// ---------------- kernel 1b: weight split+transpose -> [n][k] bf16 planes ----------
__global__ void wsplit_kernel(const float* __restrict__ Wq, const float* __restrict__ Wkv,
                              const float* __restrict__ Wg, const float* __restrict__ Wo) {
    int n = blockIdx.x, k = threadIdx.x;
    float w;
    if (n < 256)       w = Wq [(size_t)k * 256 + n];
    else if (n < 768)  w = Wkv[(size_t)k * 512 + (n - 256)];
    else if (n < 1024) w = Wg [(size_t)k * 256 + (n - 768)];
    else               w = Wo [(size_t)k * 256 + (n - 1024)];
    __nv_bfloat16 h, l;
    split_bf16(w, h, l);
    if (n < 1024) {
        g_wph[(size_t)n * 256 + k] = h;
        g_wpl[(size_t)n * 256 + k] = l;
    } else {
        g_woh[(size_t)(n - 1024) * 256 + k] = h;
        g_wol[(size_t)(n - 1024) * 256 + k] = l;
    }
}

// ---------------- kernel 2: edge LN + W_edge + edge_mask -> g_bias[h][j][i] ----------------
__global__ void bias_kernel(const float* __restrict__ edges,
                            const float* __restrict__ lg,
                            const float* __restrict__ lb,
                            const float* __restrict__ We,
                            const unsigned int* __restrict__ emask) {
    __shared__ float sW[DEDGE * H_N];
    __shared__ float sg[DEDGE], sb[DEDGE];
    int t = threadIdx.x;
    for (int l = t; l < DEDGE * H_N; l += 256) sW[l] = We[l];
    if (t < DEDGE) { sg[t] = lg[t]; sb[t] = lb[t]; }
    __syncthreads();

    int warp = t >> 5, lane = t & 31;
    int p = blockIdx.x * 8 + warp;
    int i = p >> 8, j = p & 255;

    if (emask[p] == 0u) {
        if (lane < 8) g_bias[(lane * W_DIM + j) * W_DIM + i] = NEGMAX;
        return;
    }
    const float* ep = edges + (size_t)p * DEDGE + lane * 4;
    float4 e = *(const float4*)ep;
    float s  = e.x + e.y + e.z + e.w;
    float ss = e.x*e.x + e.y*e.y + e.z*e.z + e.w*e.w;
    #pragma unroll
    for (int off = 16; off; off >>= 1) {
        s  += __shfl_xor_sync(0xffffffffu, s,  off);
        ss += __shfl_xor_sync(0xffffffffu, ss, off);
    }
    float mu  = s * (1.0f / 128.0f);
    float var = ss * (1.0f / 128.0f) - mu * mu;
    float rs  = rsqrtf(var + 1e-5f);
    int e0 = lane * 4;
    float en[4];
    en[0] = (e.x - mu) * rs * sg[e0 + 0] + sb[e0 + 0];
    en[1] = (e.y - mu) * rs * sg[e0 + 1] + sb[e0 + 1];
    en[2] = (e.z - mu) * rs * sg[e0 + 2] + sb[e0 + 2];
    en[3] = (e.w - mu) * rs * sg[e0 + 3] + sb[e0 + 3];
    float acc[8];
    #pragma unroll
    for (int h = 0; h < 8; h++) acc[h] = 0.0f;
    #pragma unroll
    for (int c = 0; c < 4; c++) {
        const float* wr = &sW[(e0 + c) * 8];
        #pragma unroll
        for (int h = 0; h < 8; h++) acc[h] += en[c] * wr[h];
    }
    #pragma unroll
    for (int h = 0; h < 8; h++) {
        #pragma unroll
        for (int off = 16; off; off >>= 1)
            acc[h] += __shfl_xor_sync(0xffffffffu, acc[h], off);
    }
    if (lane == 0) {
        #pragma unroll
        for (int h = 0; h < 8; h++)
            g_bias[(h * W_DIM + j) * W_DIM + i] = acc[h];
    }
}

// ---------------- bf16x3 GEMM (ldmatrix + single-sync pipeline) ----------------
#define GEMM_SMEM()                                                            \
    __shared__ __nv_bfloat16 sAh[2][PLANE], sAl[2][PLANE];                     \
    __shared__ __nv_bfloat16 sBh[2][PLANE], sBl[2][PLANE];

#define GEMM_ISSUE(buf, kt, Ahp, Alp, Bhp, Blp, abase, nbase)                  \
    {                                                                          \
        int k0 = (kt) * 16 + ch;                                               \
        CP16(sAh_u + ((buf) * PLANE + row * RS + ch) * 2,                      \
             (Ahp) + (size_t)((abase) + row) * 256 + k0);                      \
        CP16(sAl_u + ((buf) * PLANE + row * RS + ch) * 2,                      \
             (Alp) + (size_t)((abase) + row) * 256 + k0);                      \
        CP16(sBh_u + ((buf) * PLANE + row * RS + ch) * 2,                      \
             (Bhp) + (size_t)((nbase) + row) * 256 + k0);                      \
        CP16(sBl_u + ((buf) * PLANE + row * RS + ch) * 2,                      \
             (Blp) + (size_t)((nbase) + row) * 256 + k0);                      \
        cp_commit();                                                           \
    }

// lane-local ldmatrix address offsets (bf16-element units within a plane):
//   A frag (m16k16 x4): arow = (l&7) + ((l>>3)&1)*8, achunk = (l>>4)*8
//   B frag (2x n8k16):  brow = (l&7) + ((l>>4)&1)*8, bchunk = ((l>>3)&1)*8
#define GEMM_LANEOFF()                                                         \
    int arow  = (lane & 7) + ((lane >> 3) & 1) * 8;                            \
    int achnk = (lane >> 4) * 8;                                               \
    int brow  = (lane & 7) + ((lane >> 4) & 1) * 8;                            \
    int bchnk = ((lane >> 3) & 1) * 8;

#define GEMM_KTILE(st)                                                         \
    {                                                                          \
        unsigned stoff = (unsigned)(st) * PLANE * 2;                           \
        unsigned bh[4][2], bl[4][2];                                           \
        _Pragma("unroll")                                                      \
        for (int p = 0; p < 2; p++) {                                          \
            unsigned bo = ((wn * 32 + p * 16 + brow) * RS + bchnk) * 2;        \
            LDSM4(bh[2*p][0], bh[2*p][1], bh[2*p+1][0], bh[2*p+1][1],          \
                  sBh_u + stoff + bo)                                          \
            LDSM4(bl[2*p][0], bl[2*p][1], bl[2*p+1][0], bl[2*p+1][1],          \
                  sBl_u + stoff + bo)                                          \
        }                                                                      \
        _Pragma("unroll")                                                      \
        for (int am = 0; am < 4; am++) {                                       \
            unsigned ao = ((wm * 64 + am * 16 + arow) * RS + achnk) * 2;       \
            unsigned ah0, ah1, ah2, ah3, al0, al1, al2, al3;                   \
            LDSM4(ah0, ah1, ah2, ah3, sAh_u + stoff + ao)                      \
            LDSM4(al0, al1, al2, al3, sAl_u + stoff + ao)                      \
            _Pragma("unroll")                                                  \
            for (int an = 0; an < 4; an++) {                                   \
                float* ac = acc[am][an];                                       \
                mma_bf16(ac, ah0, ah1, ah2, ah3, bh[an][0], bh[an][1]);        \
                mma_bf16(ac, ah0, ah1, ah2, ah3, bl[an][0], bl[an][1]);        \
                mma_bf16(ac, al0, al1, al2, al3, bh[an][0], bh[an][1]);        \
            }                                                                  \
        }                                                                      \
    }

// mainloop: wait0 -> sync -> issue(kt+1) -> compute(kt); loads overlap compute
#define GEMM_MAINLOOP(Ahp, Alp, Bhp, Blp, abase, nbase)                        \
    GEMM_ISSUE(0, 0, Ahp, Alp, Bhp, Blp, abase, nbase)                         \
    for (int kt = 0; kt < 16; kt++) {                                          \
        cp_wait0();                                                            \
        __syncthreads();                                                       \
        if (kt < 15)                                                           \
            GEMM_ISSUE((kt + 1) & 1, kt + 1, Ahp, Alp, Bhp, Blp, abase, nbase) \
        GEMM_KTILE(kt & 1)                                                     \
    }

// ---------------- kernel 3: projection GEMM (bf16x3) ----------------
__global__ void __launch_bounds__(256, 2)
proj_mma(const float* __restrict__ bg) {
    GEMM_SMEM()
    int t = threadIdx.x, lane = t & 31, warp = t >> 5;
    int wm = warp >> 2, wn = warp & 3;
    int g = lane >> 2, c = lane & 3;
    int bn = blockIdx.x, bm = blockIdx.y;
    int nb = bn * 128;
    int abase = bm * 128;

    unsigned sAh_u = (unsigned)__cvta_generic_to_shared(sAh);
    unsigned sAl_u = (unsigned)__cvta_generic_to_shared(sAl);
    unsigned sBh_u = (unsigned)__cvta_generic_to_shared(sBh);
    unsigned sBl_u = (unsigned)__cvta_generic_to_shared(sBl);
    int row = t >> 1, ch = (t & 1) * 8;
    GEMM_LANEOFF()

    float acc[4][4][4];
    #pragma unroll
    for (int am = 0; am < 4; am++)
        #pragma unroll
        for (int an = 0; an < 4; an++)
            #pragma unroll
            for (int v = 0; v < 4; v++) acc[am][an][v] = 0.0f;

    GEMM_MAINLOOP(g_xnh, g_xnl, g_wph, g_wpl, abase, nb)

    if (nb < 768) {
        float* dst; int base;
        if (nb < 256)      { dst = g_q; base = 0; }
        else if (nb < 512) { dst = g_k; base = 256; }
        else               { dst = g_v; base = 512; }
        #pragma unroll
        for (int am = 0; am < 4; am++) {
            int tok = abase + wm * 64 + am * 16 + g;
            int rr = tok >> 8, iw = tok & 255;
            #pragma unroll
            for (int an = 0; an < 4; an++) {
                int gc = nb + wn * 32 + an * 8 + 2 * c;
                int cq = gc - base;
                int hh = cq >> 5, d8 = cq & 31;
                float* p0 = dst + ((size_t)((rr * 8 + hh) * 256 + iw)) * 32 + d8;
                float* p1 = p0 + 8 * 32;
                *(float2*)p0 = make_float2(acc[am][an][0], acc[am][an][1]);
                *(float2*)p1 = make_float2(acc[am][an][2], acc[am][an][3]);
            }
        }
    } else {
        #pragma unroll
        for (int am = 0; am < 4; am++) {
            int tok = abase + wm * 64 + am * 16 + g;
            #pragma unroll
            for (int an = 0; an < 4; an++) {
                int gc = nb + wn * 32 + an * 8 + 2 * c;
                int gcol = gc - 768;
                float2 bg2 = *(const float2*)(bg + gcol);
                float* p0 = g_gate + (size_t)tok * 256 + gcol;
                float* p1 = p0 + 8 * 256;
                float2 o0, o1;
                o0.x = 1.0f / (1.0f + __expf(-(acc[am][an][0] + bg2.x)));
                o0.y = 1.0f / (1.0f + __expf(-(acc[am][an][1] + bg2.y)));
                o1.x = 1.0f / (1.0f + __expf(-(acc[am][an][2] + bg2.x)));
                o1.y = 1.0f / (1.0f + __expf(-(acc[am][an][3] + bg2.y)));
                *(float2*)p0 = o0;
                *(float2*)p1 = o1;
            }
        }
    }
}

// ---------------- kernel 5: output projection (bf16x3) ----------------
__global__ void __launch_bounds__(256, 2)
out_mma(const float* __restrict__ bo, float* __restrict__ out) {
    GEMM_SMEM()
    int t = threadIdx.x, lane = t & 31, warp = t >> 5;
    int wm = warp >> 2, wn = warp & 3;
    int g = lane >> 2, c = lane & 3;
    int bn = blockIdx.x, bm = blockIdx.y;
    int nb = bn * 128;
    int abase = bm * 128;

    unsigned sAh_u = (unsigned)__cvta_generic_to_shared(sAh);
    unsigned sAl_u = (unsigned)__cvta_generic_to_shared(sAl);
    unsigned sBh_u = (unsigned)__cvta_generic_to_shared(sBh);
    unsigned sBl_u = (unsigned)__cvta_generic_to_shared(sBl);
    int row = t >> 1, ch = (t & 1) * 8;
    GEMM_LANEOFF()

    float acc[4][4][4];
    #pragma unroll
    for (int am = 0; am < 4; am++)
        #pragma unroll
        for (int an = 0; an < 4; an++)
            #pragma unroll
            for (int v = 0; v < 4; v++) acc[am][an][v] = 0.0f;

    GEMM_MAINLOOP(g_atth, g_attl, g_woh, g_wol, abase, nb)

    #pragma unroll
    for (int am = 0; am < 4; am++) {
        int tok = abase + wm * 64 + am * 16 + g;
        #pragma unroll
        for (int an = 0; an < 4; an++) {
            int gc = nb + wn * 32 + an * 8 + 2 * c;
            float2 bo2 = *(const float2*)(bo + gc);
            float* p0 = out + (size_t)tok * 256 + gc;
            float* p1 = p0 + 8 * 256;
            *(float2*)p0 = make_float2(acc[am][an][0] + bo2.x, acc[am][an][1] + bo2.y);
            *(float2*)p1 = make_float2(acc[am][an][2] + bo2.x, acc[am][an][3] + bo2.y);
        }
    }
}

// ---------------- kernel 4: fused attention, 2 queries/thread + cp.async pipeline ----
#define JCH 8
#define NCH (W_DIM / JCH)       // 32
__global__ void __launch_bounds__(128, 2)
attn_kernel(const unsigned int* __restrict__ mask) {
    __shared__ float bias_s[3][JCH][256];
    __shared__ float k_s[3][JCH][32];
    __shared__ float v_s[3][JCH][32];
    __shared__ unsigned char msk[256];

    int rh = blockIdx.x;
    int r = rh >> 3, h = rh & 7;
    int i = threadIdx.x;

    unsigned int mw0 = mask[r * 256 + i];
    unsigned int mw1 = mask[r * 256 + i + 128];
    msk[i]       = (mw0 != 0u) ? 1 : 0;
    msk[i + 128] = (mw1 != 0u) ? 1 : 0;
    int mi0 = (mw0 != 0u) ? 1 : 0;
    int mi1 = (mw1 != 0u) ? 1 : 0;

    const float sc = 0.17677669529663689f;
    const float* qbase = g_q + (size_t)((r * 8 + h) * 256) * 32;
    const float* kbase = g_k + (size_t)((r * 8 + h) * 256) * 32;
    const float* vbase = g_v + (size_t)((r * 8 + h) * 256) * 32;
    const float* bbase = g_bias + (size_t)(h * 256) * 256;

    unsigned sb_u = (unsigned)__cvta_generic_to_shared(bias_s);
    unsigned sk_u = (unsigned)__cvta_generic_to_shared(k_s);
    unsigned sv_u = (unsigned)__cvta_generic_to_shared(v_s);

    int br = i >> 6;
    int bc = (i & 63) * 4;
    int kr = (i & 63) >> 3, kd = (i & 7) * 4;

    unsigned long long q2a[16], q2b[16];
    {
        const float* qp0 = qbase + (size_t)i * 32;
        const float* qp1 = qbase + (size_t)(i + 128) * 32;
        #pragma unroll
        for (int dd = 0; dd < 8; dd++) {
            float4 q4 = ((const float4*)qp0)[dd];
            q2a[2 * dd]     = f2pack(q4.x * sc, q4.y * sc);
            q2a[2 * dd + 1] = f2pack(q4.z * sc, q4.w * sc);
            float4 q5 = ((const float4*)qp1)[dd];
            q2b[2 * dd]     = f2pack(q5.x * sc, q5.y * sc);
            q2b[2 * dd + 1] = f2pack(q5.z * sc, q5.w * sc);
        }
    }

    unsigned long long acc2a[16], acc2b[16];
    #pragma unroll
    for (int dd = 0; dd < 16; dd++) { acc2a[dd] = 0ull; acc2b[dd] = 0ull; }
    float l0 = 0.0f, l1 = 0.0f;

    #define ISSUE(ch)                                                              \
    {                                                                              \
        int st_ = (ch) % 3;                                                        \
        int j0_ = (ch) * JCH;                                                      \
        CP16(sb_u + ((st_ * JCH + br)     * 256 + bc) * 4,                         \
             bbase + (size_t)(j0_ + br)     * 256 + bc);                           \
        CP16(sb_u + ((st_ * JCH + br + 2) * 256 + bc) * 4,                         \
             bbase + (size_t)(j0_ + br + 2) * 256 + bc);                           \
        CP16(sb_u + ((st_ * JCH + br + 4) * 256 + bc) * 4,                         \
             bbase + (size_t)(j0_ + br + 4) * 256 + bc);                           \
        CP16(sb_u + ((st_ * JCH + br + 6) * 256 + bc) * 4,                         \
             bbase + (size_t)(j0_ + br + 6) * 256 + bc);                           \
        if (i < 64) {                                                              \
            CP16(sk_u + ((st_ * JCH + kr) * 32 + kd) * 4,                          \
                 kbase + (size_t)(j0_ + kr) * 32 + kd);                            \
        } else {                                                                   \
            CP16(sv_u + ((st_ * JCH + kr) * 32 + kd) * 4,                          \
                 vbase + (size_t)(j0_ + kr) * 32 + kd);                            \
        }                                                                          \
        cp_commit();                                                               \
    }

    ISSUE(0)
    ISSUE(1)

    for (int ch = 0; ch < NCH; ch++) {
        if (ch < NCH - 1) cp_wait1(); else cp_wait0();
        __syncthreads();
        if (ch + 2 < NCH) ISSUE(ch + 2)

        int st = ch % 3;
        int j0 = ch * JCH;
        #pragma unroll
        for (int jj = 0; jj < JCH; jj++) {
            const ulonglong2* kp = (const ulonglong2*)&k_s[st][jj][0];
            unsigned long long d0a = 0ull, d0b = 0ull, d1a = 0ull, d1b = 0ull;
            #pragma unroll
            for (int dd = 0; dd < 8; dd++) {
                ulonglong2 kk2 = kp[dd];
                d0a = f2fma(q2a[2 * dd],     kk2.x, d0a);
                d0b = f2fma(q2a[2 * dd + 1], kk2.y, d0b);
                d1a = f2fma(q2b[2 * dd],     kk2.x, d1a);
                d1b = f2fma(q2b[2 * dd + 1], kk2.y, d1b);
            }
            float x0, x1, y0, y1, z0, z1, w0, w1;
            f2unpack(d0a, x0, x1); f2unpack(d0b, y0, y1);
            f2unpack(d1a, z0, z1); f2unpack(d1b, w0, w1);
            float s0 = (x0 + x1) + (y0 + y1) + bias_s[st][jj][i];
            float s1 = (z0 + z1) + (w0 + w1) + bias_s[st][jj][i + 128];
            if (!msk[j0 + jj]) { s0 = NEGMAX; s1 = NEGMAX; }
            float p0 = mi0 ? __expf(s0) : 1.0f;
            float p1 = mi1 ? __expf(s1) : 1.0f;
            l0 += p0; l1 += p1;
            unsigned long long p20 = f2dup(p0);
            unsigned long long p21 = f2dup(p1);
            const ulonglong2* vp = (const ulonglong2*)&v_s[st][jj][0];
            #pragma unroll
            for (int dd = 0; dd < 8; dd++) {
                ulonglong2 vv = vp[dd];
                acc2a[2 * dd]     = f2fma(p20, vv.x, acc2a[2 * dd]);
                acc2a[2 * dd + 1] = f2fma(p20, vv.y, acc2a[2 * dd + 1]);
                acc2b[2 * dd]     = f2fma(p21, vv.x, acc2b[2 * dd]);
                acc2b[2 * dd + 1] = f2fma(p21, vv.y, acc2b[2 * dd + 1]);
            }
        }
    }
    #undef ISSUE

    float inv0 = 1.0f / l0;
    float inv1 = 1.0f / l1;
    #pragma unroll
    for (int q = 0; q < 2; q++) {
        int tok = r * 256 + i + q * 128;
        const unsigned long long* ac = q ? acc2b : acc2a;
        float inv = q ? inv1 : inv0;
        const float* gp = g_gate + (size_t)tok * 256 + h * 32;
        size_t ob = (size_t)tok * 256 + h * 32;
        #pragma unroll
        for (int dd = 0; dd < 8; dd++) {
            float a, b2, cc, d;
            f2unpack(ac[2 * dd], a, b2);
            f2unpack(ac[2 * dd + 1], cc, d);
            float4 g4 = ((const float4*)gp)[dd];
            float o0 = a  * inv * g4.x;
            float o1 = b2 * inv * g4.y;
            float o2 = cc * inv * g4.z;
            float o3 = d  * inv * g4.w;
            __nv_bfloat16 h0, l0b, h1, l1b, h2, l2b, h3, l3b;
            split_bf16(o0, h0, l0b);
            split_bf16(o1, h1, l1b);
            split_bf16(o2, h2, l2b);
            split_bf16(o3, h3, l3b);
            *(unsigned*)&g_atth[ob + dd * 4]     = bfpack(h0, h1);
            *(unsigned*)&g_atth[ob + dd * 4 + 2] = bfpack(h2, h3);
            *(unsigned*)&g_attl[ob + dd * 4]     = bfpack(l0b, l1b);
            *(unsigned*)&g_attl[ob + dd * 4 + 2] = bfpack(l2b, l3b);
        }
    }
}

// ---------------- launch ----------------
extern "C" void kernel_launch(void* const* d_in, const int* in_sizes, int n_in,
                              void* d_out, int out_size) {
    const float* x      = (const float*)d_in[0];
    const float* edges  = (const float*)d_in[1];
    const unsigned int* mask      = (const unsigned int*)d_in[2];
    const unsigned int* edge_mask = (const unsigned int*)d_in[3];
    const float* ln_g   = (const float*)d_in[4];
    const float* ln_b   = (const float*)d_in[5];
    const float* lne_g  = (const float*)d_in[6];
    const float* lne_b  = (const float*)d_in[7];
    const float* W_edge = (const float*)d_in[8];
    const float* Wq     = (const float*)d_in[9];
    const float* Wkv    = (const float*)d_in[10];
    const float* Wg     = (const float*)d_in[11];
    const float* bg     = (const float*)d_in[12];
    const float* Wo     = (const float*)d_in[13];
    const float* bo     = (const float*)d_in[14];
    float* out = (float*)d_out;

    ln_x_kernel<<<NTOK / 8, 256>>>(x, ln_g, ln_b);
    wsplit_kernel<<<1280, 256>>>(Wq, Wkv, Wg, Wo);
    bias_kernel<<<(W_DIM * W_DIM) / 8, 256>>>(edges, lne_g, lne_b, W_edge, edge_mask);
    proj_mma<<<dim3(8, NTOK / 128), 256>>>(bg);
    attn_kernel<<<R_DIM * H_N, 128>>>(mask);
    out_mma<<<dim3(2, NTOK / 128), 256>>>(bo, out);
}

// round 9
// speedup vs baseline: 1.6278x; 1.0136x over previous
#include <cuda_runtime.h>
#include <cuda_bf16.h>
#include <cuda_fp16.h>

// Problem constants
#define R_DIM 128
#define W_DIM 256
#define DNODE 256
#define DEDGE 128
#define H_N   8
#define DHEAD 32
#define NTOK  (R_DIM * W_DIM)       // 32768
#define NEGMAX (-3.4028234663852886e38f)

// ---------------- scratch (device globals: allocation-free) ----------------
__device__ float g_q   [NTOK * DNODE];          // [r][h][i][d]
__device__ float g_k   [NTOK * DNODE];          // [r][h][j][d]
__device__ float g_v   [NTOK * DNODE];          // [r][h][j][d]
__device__ float g_gate[NTOK * DNODE];
__device__ __half g_bias[H_N * W_DIM * W_DIM];  // [h][j][i], fp16 (masked = -65504)
// bf16 split planes (hi + lo ~= fp32)
__device__ __nv_bfloat16 g_xnh [NTOK * DNODE];
__device__ __nv_bfloat16 g_xnl [NTOK * DNODE];
__device__ __nv_bfloat16 g_atth[NTOK * DNODE];
__device__ __nv_bfloat16 g_attl[NTOK * DNODE];
__device__ __nv_bfloat16 g_wph [1024 * 256];    // [n][k]
__device__ __nv_bfloat16 g_wpl [1024 * 256];
__device__ __nv_bfloat16 g_woh [256 * 256];
__device__ __nv_bfloat16 g_wol [256 * 256];

// ---------------- f32x2 helpers (attention kernel) ----------------
__device__ __forceinline__ unsigned long long f2dup(float x) {
    unsigned long long r;
    asm("mov.b64 %0, {%1, %1};" : "=l"(r) : "f"(x));
    return r;
}
__device__ __forceinline__ unsigned long long f2pack(float lo, float hi) {
    unsigned long long r;
    asm("mov.b64 %0, {%1, %2};" : "=l"(r) : "f"(lo), "f"(hi));
    return r;
}
__device__ __forceinline__ void f2unpack(unsigned long long v, float& lo, float& hi) {
    asm("mov.b64 {%0, %1}, %2;" : "=f"(lo), "=f"(hi) : "l"(v));
}
__device__ __forceinline__ unsigned long long f2fma(unsigned long long a,
                                                    unsigned long long b,
                                                    unsigned long long c) {
    unsigned long long d;
    asm("fma.rn.f32x2 %0, %1, %2, %3;" : "=l"(d) : "l"(a), "l"(b), "l"(c));
    return d;
}

// ---------------- bf16 helpers ----------------
__device__ __forceinline__ void mma_bf16(float* d,
                                         unsigned a0, unsigned a1, unsigned a2, unsigned a3,
                                         unsigned b0, unsigned b1) {
    asm volatile(
        "mma.sync.aligned.m16n8k16.row.col.f32.bf16.bf16.f32 "
        "{%0,%1,%2,%3}, {%4,%5,%6,%7}, {%8,%9}, {%0,%1,%2,%3};"
        : "+f"(d[0]), "+f"(d[1]), "+f"(d[2]), "+f"(d[3])
        : "r"(a0), "r"(a1), "r"(a2), "r"(a3), "r"(b0), "r"(b1));
}
__device__ __forceinline__ void split_bf16(float x, __nv_bfloat16& hi, __nv_bfloat16& lo) {
    hi = __float2bfloat16(x);
    lo = __float2bfloat16(x - __bfloat162float(hi));
}
__device__ __forceinline__ unsigned bfpack(__nv_bfloat16 a, __nv_bfloat16 b) {
    return (unsigned)__bfloat16_as_ushort(a) | ((unsigned)__bfloat16_as_ushort(b) << 16);
}
#define CP16(dst_u32, src_ptr) \
    asm volatile("cp.async.ca.shared.global [%0], [%1], 16;" :: "r"(dst_u32), "l"(src_ptr))
__device__ __forceinline__ void cp_commit() { asm volatile("cp.async.commit_group;"); }
__device__ __forceinline__ void cp_wait0()  { asm volatile("cp.async.wait_group 0;"); }
__device__ __forceinline__ void cp_wait1()  { asm volatile("cp.async.wait_group 1;"); }
#define LDSM4(r0, r1, r2, r3, addr) \
    asm volatile("ldmatrix.sync.aligned.m8n8.x4.shared.b16 {%0,%1,%2,%3}, [%4];" \
        : "=r"(r0), "=r"(r1), "=r"(r2), "=r"(r3) : "r"(addr));

// GEMM smem: RS=16 (no pad), XOR swizzle (chunk ^= (row&4)<<1) for conflict-free LDSM
#define RS 16
#define PLANE (128 * RS)    // 2048 bf16 = 4KB per plane; 4 planes x 3 stages = 48KB

// ---------------- kernel 1: LayerNorm(x) -> bf16 split planes ----------------
__global__ void ln_x_kernel(const float* __restrict__ x,
                            const float* __restrict__ g,
                            const float* __restrict__ b) {
    int warp = threadIdx.x >> 5, lane = threadIdx.x & 31;
    int tok  = blockIdx.x * 8 + warp;
    const float* xp = x + (size_t)tok * 256 + lane * 8;
    float4 a0 = *(const float4*)xp;
    float4 a1 = *(const float4*)(xp + 4);
    float s  = a0.x + a0.y + a0.z + a0.w + a1.x + a1.y + a1.z + a1.w;
    float ss = a0.x*a0.x + a0.y*a0.y + a0.z*a0.z + a0.w*a0.w
             + a1.x*a1.x + a1.y*a1.y + a1.z*a1.z + a1.w*a1.w;
    #pragma unroll
    for (int off = 16; off; off >>= 1) {
        s  += __shfl_xor_sync(0xffffffffu, s,  off);
        ss += __shfl_xor_sync(0xffffffffu, ss, off);
    }
    float mu  = s * (1.0f / 256.0f);
    float var = ss * (1.0f / 256.0f) - mu * mu;
    float rs  = rsqrtf(var + 1e-5f);
    float4 g0 = *(const float4*)(g + lane * 8);
    float4 g1 = *(const float4*)(g + lane * 8 + 4);
    float4 b0 = *(const float4*)(b + lane * 8);
    float4 b1 = *(const float4*)(b + lane * 8 + 4);
    float v[8];
    v[0] = (a0.x - mu) * rs * g0.x + b0.x;
    v[1] = (a0.y - mu) * rs * g0.y + b0.y;
    v[2] = (a0.z - mu) * rs * g0.z + b0.z;
    v[3] = (a0.w - mu) * rs * g0.w + b0.w;
    v[4] = (a1.x - mu) * rs * g1.x + b1.x;
    v[5] = (a1.y - mu) * rs * g1.y + b1.y;
    v[6] = (a1.z - mu) * rs * g1.z + b1.z;
    v[7] = (a1.w - mu) * rs * g1.w + b1.w;
    unsigned hu[4], lu[4];
    #pragma unroll
    for (int p = 0; p < 4; p++) {
        __nv_bfloat16 h0, l0, h1, l1;
        split_bf16(v[2 * p], h0, l0);
        split_bf16(v[2 * p + 1], h1, l1);
        hu[p] = bfpack(h0, h1);
        lu[p] = bfpack(l0, l1);
    }
    size_t off = (size_t)tok * 256 + lane * 8;
    *(uint4*)&g_xnh[off] = make_uint4(hu[0], hu[1], hu[2], hu[3]);
    *(uint4*)&g_xnl[off] = make_uint4(lu[0], lu[1], lu[2], lu[3]);
}

// ---------------- kernel 1b: weight split+transpose -> [n][k] bf16 planes ----------
__global__ void wsplit_kernel(const float* __restrict__ Wq, const float* __restrict__ Wkv,
                              const float* __restrict__ Wg, const float* __restrict__ Wo) {
    int n = blockIdx.x, k = threadIdx.x;
    float w;
    if (n < 256)       w = Wq [(size_t)k * 256 + n];
    else if (n < 768)  w = Wkv[(size_t)k * 512 + (n - 256)];
    else if (n < 1024) w = Wg [(size_t)k * 256 + (n - 768)];
    else               w = Wo [(size_t)k * 256 + (n - 1024)];
    __nv_bfloat16 h, l;
    split_bf16(w, h, l);
    if (n < 1024) {
        g_wph[(size_t)n * 256 + k] = h;
        g_wpl[(size_t)n * 256 + k] = l;
    } else {
        g_woh[(size_t)(n - 1024) * 256 + k] = h;
        g_wol[(size_t)(n - 1024) * 256 + k] = l;
    }
}

// ---------------- kernel 2: edge LN + W_edge + edge_mask -> fp16 g_bias[h][j][i] ------
__global__ void bias_kernel(const float* __restrict__ edges,
                            const float* __restrict__ lg,
                            const float* __restrict__ lb,
                            const float* __restrict__ We,
                            const unsigned int* __restrict__ emask) {
    __shared__ float sW[DEDGE * H_N];
    __shared__ float sg[DEDGE], sb[DEDGE];
    int t = threadIdx.x;
    for (int l = t; l < DEDGE * H_N; l += 256) sW[l] = We[l];
    if (t < DEDGE) { sg[t] = lg[t]; sb[t] = lb[t]; }
    __syncthreads();

    int warp = t >> 5, lane = t & 31;
    int p = blockIdx.x * 8 + warp;
    int i = p >> 8, j = p & 255;

    if (emask[p] == 0u) {
        if (lane < 8) g_bias[(lane * W_DIM + j) * W_DIM + i] = __float2half(-65504.0f);
        return;
    }
    const float* ep = edges + (size_t)p * DEDGE + lane * 4;
    float4 e = *(const float4*)ep;
    float s  = e.x + e.y + e.z + e.w;
    float ss = e.x*e.x + e.y*e.y + e.z*e.z + e.w*e.w;
    #pragma unroll
    for (int off = 16; off; off >>= 1) {
        s  += __shfl_xor_sync(0xffffffffu, s,  off);
        ss += __shfl_xor_sync(0xffffffffu, ss, off);
    }
    float mu  = s * (1.0f / 128.0f);
    float var = ss * (1.0f / 128.0f) - mu * mu;
    float rs  = rsqrtf(var + 1e-5f);
    int e0 = lane * 4;
    float en[4];
    en[0] = (e.x - mu) * rs * sg[e0 + 0] + sb[e0 + 0];
    en[1] = (e.y - mu) * rs * sg[e0 + 1] + sb[e0 + 1];
    en[2] = (e.z - mu) * rs * sg[e0 + 2] + sb[e0 + 2];
    en[3] = (e.w - mu) * rs * sg[e0 + 3] + sb[e0 + 3];
    float acc[8];
    #pragma unroll
    for (int h = 0; h < 8; h++) acc[h] = 0.0f;
    #pragma unroll
    for (int c = 0; c < 4; c++) {
        const float* wr = &sW[(e0 + c) * 8];
        #pragma unroll
        for (int h = 0; h < 8; h++) acc[h] += en[c] * wr[h];
    }
    #pragma unroll
    for (int h = 0; h < 8; h++) {
        #pragma unroll
        for (int off = 16; off; off >>= 1)
            acc[h] += __shfl_xor_sync(0xffffffffu, acc[h], off);
    }
    if (lane == 0) {
        #pragma unroll
        for (int h = 0; h < 8; h++)
            g_bias[(h * W_DIM + j) * W_DIM + i] = __float2half(acc[h]);
    }
}

// ---------------- bf16x3 GEMM (ldmatrix + swizzle + 3-stage pipeline) ----------------
#define GEMM_SMEM()                                                            \
    __shared__ __nv_bfloat16 sAh[3][PLANE], sAl[3][PLANE];                     \
    __shared__ __nv_bfloat16 sBh[3][PLANE], sBl[3][PLANE];

// cp.async store: row = t>>1 (0..127), ch = (t&1)*8, swizzled chunk
#define GEMM_ISSUE(buf, kt, Ahp, Alp, Bhp, Blp, abase, nbase)                  \
    {                                                                          \
        int k0 = (kt) * 16 + ch;                                               \
        unsigned doff = ((unsigned)(buf) * PLANE + row * RS + chsw) * 2;       \
        CP16(sAh_u + doff, (Ahp) + (size_t)((abase) + row) * 256 + k0);        \
        CP16(sAl_u + doff, (Alp) + (size_t)((abase) + row) * 256 + k0);        \
        CP16(sBh_u + doff, (Bhp) + (size_t)((nbase) + row) * 256 + k0);        \
        CP16(sBl_u + doff, (Blp) + (size_t)((nbase) + row) * 256 + k0);        \
        cp_commit();                                                           \
    }

// lane-local ldmatrix offsets (with swizzle):
//   A frag: arow = (l&7) + ((l>>3)&1)*8, achunk = (l>>4)*8
//   B frag: brow = (l&7) + ((l>>4)&1)*8, bchunk = ((l>>3)&1)*8
#define GEMM_LANEOFF()                                                         \
    int arow  = (lane & 7) + ((lane >> 3) & 1) * 8;                            \
    int achnk = ((lane >> 4) * 8) ^ ((arow & 4) << 1);                         \
    int brow  = (lane & 7) + ((lane >> 4) & 1) * 8;                            \
    int bchnk = (((lane >> 3) & 1) * 8) ^ ((brow & 4) << 1);

#define GEMM_KTILE(st)                                                         \
    {                                                                          \
        unsigned stoff = (unsigned)(st) * PLANE * 2;                           \
        unsigned bh[4][2], bl[4][2];                                           \
        _Pragma("unroll")                                                      \
        for (int p = 0; p < 2; p++) {                                          \
            unsigned bo = ((wn * 32 + p * 16 + brow) * RS + bchnk) * 2;        \
            LDSM4(bh[2*p][0], bh[2*p][1], bh[2*p+1][0], bh[2*p+1][1],          \
                  sBh_u + stoff + bo)                                          \
            LDSM4(bl[2*p][0], bl[2*p][1], bl[2*p+1][0], bl[2*p+1][1],          \
                  sBl_u + stoff + bo)                                          \
        }                                                                      \
        _Pragma("unroll")                                                      \
        for (int am = 0; am < 4; am++) {                                       \
            unsigned ao = ((wm * 64 + am * 16 + arow) * RS + achnk) * 2;       \
            unsigned ah0, ah1, ah2, ah3, al0, al1, al2, al3;                   \
            LDSM4(ah0, ah1, ah2, ah3, sAh_u + stoff + ao)                      \
            LDSM4(al0, al1, al2, al3, sAl_u + stoff + ao)                      \
            _Pragma("unroll")                                                  \
            for (int an = 0; an < 4; an++) {                                   \
                float* ac = acc[am][an];                                       \
                mma_bf16(ac, ah0, ah1, ah2, ah3, bh[an][0], bh[an][1]);        \
                mma_bf16(ac, ah0, ah1, ah2, ah3, bl[an][0], bl[an][1]);        \
                mma_bf16(ac, al0, al1, al2, al3, bh[an][0], bh[an][1]);        \
            }                                                                  \
        }                                                                      \
    }

// 3-stage mainloop: wait1 (kt ready) -> sync -> issue(kt+2) -> compute(kt)
#define GEMM_MAINLOOP(Ahp, Alp, Bhp, Blp, abase, nbase)                        \
    GEMM_ISSUE(0, 0, Ahp, Alp, Bhp, Blp, abase, nbase)                         \
    GEMM_ISSUE(1, 1, Ahp, Alp, Bhp, Blp, abase, nbase)                         \
    for (int kt = 0; kt < 16; kt++) {                                          \
        if (kt < 15) cp_wait1(); else cp_wait0();                              \
        __syncthreads();                                                       \
        if (kt <= 13) {                                                        \
            int nbuf = (kt + 2) % 3;                                           \
            GEMM_ISSUE(nbuf, kt + 2, Ahp, Alp, Bhp, Blp, abase, nbase)         \
        }                                                                      \
        GEMM_KTILE(kt % 3)                                                     \
    }

// ---------------- kernel 3: projection GEMM (bf16x3) ----------------
__global__ void __launch_bounds__(256, 2)
proj_mma(const float* __restrict__ bg) {
    GEMM_SMEM()
    int t = threadIdx.x, lane = t & 31, warp = t >> 5;
    int wm = warp >> 2, wn = warp & 3;
    int g = lane >> 2, c = lane & 3;
    int bn = blockIdx.x, bm = blockIdx.y;
    int nb = bn * 128;
    int abase = bm * 128;

    unsigned sAh_u = (unsigned)__cvta_generic_to_shared(sAh);
    unsigned sAl_u = (unsigned)__cvta_generic_to_shared(sAl);
    unsigned sBh_u = (unsigned)__cvta_generic_to_shared(sBh);
    unsigned sBl_u = (unsigned)__cvta_generic_to_shared(sBl);
    int row = t >> 1, ch = (t & 1) * 8;
    int chsw = ch ^ ((row & 4) << 1);
    GEMM_LANEOFF()

    float acc[4][4][4];
    #pragma unroll
    for (int am = 0; am < 4; am++)
        #pragma unroll
        for (int an = 0; an < 4; an++)
            #pragma unroll
            for (int v = 0; v < 4; v++) acc[am][an][v] = 0.0f;

    GEMM_MAINLOOP(g_xnh, g_xnl, g_wph, g_wpl, abase, nb)

    if (nb < 768) {
        float* dst; int base;
        if (nb < 256)      { dst = g_q; base = 0; }
        else if (nb < 512) { dst = g_k; base = 256; }
        else               { dst = g_v; base = 512; }
        #pragma unroll
        for (int am = 0; am < 4; am++) {
            int tok = abase + wm * 64 + am * 16 + g;
            int rr = tok >> 8, iw = tok & 255;
            #pragma unroll
            for (int an = 0; an < 4; an++) {
                int gc = nb + wn * 32 + an * 8 + 2 * c;
                int cq = gc - base;
                int hh = cq >> 5, d8 = cq & 31;
                float* p0 = dst + ((size_t)((rr * 8 + hh) * 256 + iw)) * 32 + d8;
                float* p1 = p0 + 8 * 32;
                *(float2*)p0 = make_float2(acc[am][an][0], acc[am][an][1]);
                *(float2*)p1 = make_float2(acc[am][an][2], acc[am][an][3]);
            }
        }
    } else {
        #pragma unroll
        for (int am = 0; am < 4; am++) {
            int tok = abase + wm * 64 + am * 16 + g;
            #pragma unroll
            for (int an = 0; an < 4; an++) {
                int gc = nb + wn * 32 + an * 8 + 2 * c;
                int gcol = gc - 768;
                float2 bg2 = *(const float2*)(bg + gcol);
                float* p0 = g_gate + (size_t)tok * 256 + gcol;
                float* p1 = p0 + 8 * 256;
                float2 o0, o1;
                o0.x = 1.0f / (1.0f + __expf(-(acc[am][an][0] + bg2.x)));
                o0.y = 1.0f / (1.0f + __expf(-(acc[am][an][1] + bg2.y)));
                o1.x = 1.0f / (1.0f + __expf(-(acc[am][an][2] + bg2.x)));
                o1.y = 1.0f / (1.0f + __expf(-(acc[am][an][3] + bg2.y)));
                *(float2*)p0 = o0;
                *(float2*)p1 = o1;
            }
        }
    }
}

// ---------------- kernel 5: output projection (bf16x3) ----------------
__global__ void __launch_bounds__(256, 2)
out_mma(const float* __restrict__ bo, float* __restrict__ out) {
    GEMM_SMEM()
    int t = threadIdx.x, lane = t & 31, warp = t >> 5;
    int wm = warp >> 2, wn = warp & 3;
    int g = lane >> 2, c = lane & 3;
    int bn = blockIdx.x, bm = blockIdx.y;
    int nb = bn * 128;
    int abase = bm * 128;

    unsigned sAh_u = (unsigned)__cvta_generic_to_shared(sAh);
    unsigned sAl_u = (unsigned)__cvta_generic_to_shared(sAl);
    unsigned sBh_u = (unsigned)__cvta_generic_to_shared(sBh);
    unsigned sBl_u = (unsigned)__cvta_generic_to_shared(sBl);
    int row = t >> 1, ch = (t & 1) * 8;
    int chsw = ch ^ ((row & 4) << 1);
    GEMM_LANEOFF()

    float acc[4][4][4];
    #pragma unroll
    for (int am = 0; am < 4; am++)
        #pragma unroll
        for (int an = 0; an < 4; an++)
            #pragma unroll
            for (int v = 0; v < 4; v++) acc[am][an][v] = 0.0f;

    GEMM_MAINLOOP(g_atth, g_attl, g_woh, g_wol, abase, nb)

    #pragma unroll
    for (int am = 0; am < 4; am++) {
        int tok = abase + wm * 64 + am * 16 + g;
        #pragma unroll
        for (int an = 0; an < 4; an++) {
            int gc = nb + wn * 32 + an * 8 + 2 * c;
            float2 bo2 = *(const float2*)(bo + gc);
            float* p0 = out + (size_t)tok * 256 + gc;
            float* p1 = p0 + 8 * 256;
            *(float2*)p0 = make_float2(acc[am][an][0] + bo2.x, acc[am][an][1] + bo2.y);
            *(float2*)p1 = make_float2(acc[am][an][2] + bo2.x, acc[am][an][3] + bo2.y);
        }
    }
}

// ---------------- kernel 4: fused attention, 2 q/thread + fp16 bias + cp.async ----
#define JCH 8
#define NCH (W_DIM / JCH)       // 32
__global__ void __launch_bounds__(128, 2)
attn_kernel(const unsigned int* __restrict__ mask) {
    __shared__ __half bias_s[3][JCH][256];   // 12 KB
    __shared__ float k_s[3][JCH][32];        // 3 KB
    __shared__ float v_s[3][JCH][32];        // 3 KB
    __shared__ unsigned char msk[256];

    int rh = blockIdx.x;
    int r = rh >> 3, h = rh & 7;
    int i = threadIdx.x;

    unsigned int mw0 = mask[r * 256 + i];
    unsigned int mw1 = mask[r * 256 + i + 128];
    msk[i]       = (mw0 != 0u) ? 1 : 0;
    msk[i + 128] = (mw1 != 0u) ? 1 : 0;
    int mi0 = (mw0 != 0u) ? 1 : 0;
    int mi1 = (mw1 != 0u) ? 1 : 0;

    const float sc = 0.17677669529663689f;
    const float* qbase = g_q + (size_t)((r * 8 + h) * 256) * 32;
    const float* kbase = g_k + (size_t)((r * 8 + h) * 256) * 32;
    const float* vbase = g_v + (size_t)((r * 8 + h) * 256) * 32;
    const __half* bbase = g_bias + (size_t)(h * 256) * 256;

    unsigned sb_u = (unsigned)__cvta_generic_to_shared(bias_s);
    unsigned sk_u = (unsigned)__cvta_generic_to_shared(k_s);
    unsigned sv_u = (unsigned)__cvta_generic_to_shared(v_s);

    // bias: 8 rows x 256 halves = 4KB = 256 x 16B chunks; thread does idx=i, i+128
    int br0 = i >> 5,  bc0 = (i & 31) * 8;   // chunk = 8 halves
    int br1 = br0 + 4;
    // k/v: 8 rows x 32 floats = 64 x 16B; threads 0..63 -> K, 64..127 -> V
    int kr = (i & 63) >> 3, kd = (i & 7) * 4;

    unsigned long long q2a[16], q2b[16];
    {
        const float* qp0 = qbase + (size_t)i * 32;
        const float* qp1 = qbase + (size_t)(i + 128) * 32;
        #pragma unroll
        for (int dd = 0; dd < 8; dd++) {
            float4 q4 = ((const float4*)qp0)[dd];
            q2a[2 * dd]     = f2pack(q4.x * sc, q4.y * sc);
            q2a[2 * dd + 1] = f2pack(q4.z * sc, q4.w * sc);
            float4 q5 = ((const float4*)qp1)[dd];
            q2b[2 * dd]     = f2pack(q5.x * sc, q5.y * sc);
            q2b[2 * dd + 1] = f2pack(q5.z * sc, q5.w * sc);
        }
    }

    unsigned long long acc2a[16], acc2b[16];
    #pragma unroll
    for (int dd = 0; dd < 16; dd++) { acc2a[dd] = 0ull; acc2b[dd] = 0ull; }
    float l0 = 0.0f, l1 = 0.0f;

    #define ISSUE(ch)                                                              \
    {                                                                              \
        int st_ = (ch) % 3;                                                        \
        int j0_ = (ch) * JCH;                                                      \
        CP16(sb_u + ((st_ * JCH + br0) * 256 + bc0) * 2,                           \
             bbase + (size_t)(j0_ + br0) * 256 + bc0);                             \
        CP16(sb_u + ((st_ * JCH + br1) * 256 + bc0) * 2,                           \
             bbase + (size_t)(j0_ + br1) * 256 + bc0);                             \
        if (i < 64) {                                                              \
            CP16(sk_u + ((st_ * JCH + kr) * 32 + kd) * 4,                          \
                 kbase + (size_t)(j0_ + kr) * 32 + kd);                            \
        } else {                                                                   \
            CP16(sv_u + ((st_ * JCH + kr) * 32 + kd) * 4,                          \
                 vbase + (size_t)(j0_ + kr) * 32 + kd);                            \
        }                                                                          \
        cp_commit();                                                               \
    }

    ISSUE(0)
    ISSUE(1)

    for (int ch = 0; ch < NCH; ch++) {
        if (ch < NCH - 1) cp_wait1(); else cp_wait0();
        __syncthreads();
        if (ch + 2 < NCH) ISSUE(ch + 2)

        int st = ch % 3;
        int j0 = ch * JCH;
        #pragma unroll
        for (int jj = 0; jj < JCH; jj++) {
            const ulonglong2* kp = (const ulonglong2*)&k_s[st][jj][0];
            unsigned long long d0a = 0ull, d0b = 0ull, d1a = 0ull, d1b = 0ull;
            #pragma unroll
            for (int dd = 0; dd < 8; dd++) {
                ulonglong2 kk2 = kp[dd];
                d0a = f2fma(q2a[2 * dd],     kk2.x, d0a);
                d0b = f2fma(q2a[2 * dd + 1], kk2.y, d0b);
                d1a = f2fma(q2b[2 * dd],     kk2.x, d1a);
                d1b = f2fma(q2b[2 * dd + 1], kk2.y, d1b);
            }
            float x0, x1, y0, y1, z0, z1, w0, w1;
            f2unpack(d0a, x0, x1); f2unpack(d0b, y0, y1);
            f2unpack(d1a, z0, z1); f2unpack(d1b, w0, w1);
            float s0 = (x0 + x1) + (y0 + y1) + __half2float(bias_s[st][jj][i]);
            float s1 = (z0 + z1) + (w0 + w1) + __half2float(bias_s[st][jj][i + 128]);
            if (!msk[j0 + jj]) { s0 = NEGMAX; s1 = NEGMAX; }
            float p0 = mi0 ? __expf(s0) : 1.0f;
            float p1 = mi1 ? __expf(s1) : 1.0f;
            l0 += p0; l1 += p1;
            unsigned long long p20 = f2dup(p0);
            unsigned long long p21 = f2dup(p1);
            const ulonglong2* vp = (const ulonglong2*)&v_s[st][jj][0];
            #pragma unroll
            for (int dd = 0; dd < 8; dd++) {
                ulonglong2 vv = vp[dd];
                acc2a[2 * dd]     = f2fma(p20, vv.x, acc2a[2 * dd]);
                acc2a[2 * dd + 1] = f2fma(p20, vv.y, acc2a[2 * dd + 1]);
                acc2b[2 * dd]     = f2fma(p21, vv.x, acc2b[2 * dd]);
                acc2b[2 * dd + 1] = f2fma(p21, vv.y, acc2b[2 * dd + 1]);
            }
        }
    }
    #undef ISSUE

    float inv0 = 1.0f / l0;
    float inv1 = 1.0f / l1;
    #pragma unroll
    for (int q = 0; q < 2; q++) {
        int tok = r * 256 + i + q * 128;
        const unsigned long long* ac = q ? acc2b : acc2a;
        float inv = q ? inv1 : inv0;
        const float* gp = g_gate + (size_t)tok * 256 + h * 32;
        size_t ob = (size_t)tok * 256 + h * 32;
        #pragma unroll
        for (int dd = 0; dd < 8; dd++) {
            float a, b2, cc, d;
            f2unpack(ac[2 * dd], a, b2);
            f2unpack(ac[2 * dd + 1], cc, d);
            float4 g4 = ((const float4*)gp)[dd];
            float o0 = a  * inv * g4.x;
            float o1 = b2 * inv * g4.y;
            float o2 = cc * inv * g4.z;
            float o3 = d  * inv * g4.w;
            __nv_bfloat16 h0, l0b, h1, l1b, h2, l2b, h3, l3b;
            split_bf16(o0, h0, l0b);
            split_bf16(o1, h1, l1b);
            split_bf16(o2, h2, l2b);
            split_bf16(o3, h3, l3b);
            *(unsigned*)&g_atth[ob + dd * 4]     = bfpack(h0, h1);
            *(unsigned*)&g_atth[ob + dd * 4 + 2] = bfpack(h2, h3);
            *(unsigned*)&g_attl[ob + dd * 4]     = bfpack(l0b, l1b);
            *(unsigned*)&g_attl[ob + dd * 4 + 2] = bfpack(l2b, l3b);
        }
    }
}

// ---------------- launch ----------------
extern "C" void kernel_launch(void* const* d_in, const int* in_sizes, int n_in,
                              void* d_out, int out_size) {
    const float* x      = (const float*)d_in[0];
    const float* edges  = (const float*)d_in[1];
    const unsigned int* mask      = (const unsigned int*)d_in[2];
    const unsigned int* edge_mask = (const unsigned int*)d_in[3];
    const float* ln_g   = (const float*)d_in[4];
    const float* ln_b   = (const float*)d_in[5];
    const float* lne_g  = (const float*)d_in[6];
    const float* lne_b  = (const float*)d_in[7];
    const float* W_edge = (const float*)d_in[8];
    const float* Wq     = (const float*)d_in[9];
    const float* Wkv    = (const float*)d_in[10];
    const float* Wg     = (const float*)d_in[11];
    const float* bg     = (const float*)d_in[12];
    const float* Wo     = (const float*)d_in[13];
    const float* bo     = (const float*)d_in[14];
    float* out = (float*)d_out;

    ln_x_kernel<<<NTOK / 8, 256>>>(x, ln_g, ln_b);
    wsplit_kernel<<<1280, 256>>>(Wq, Wkv, Wg, Wo);
    bias_kernel<<<(W_DIM * W_DIM) / 8, 256>>>(edges, lne_g, lne_b, W_edge, edge_mask);
    proj_mma<<<dim3(8, NTOK / 128), 256>>>(bg);
    attn_kernel<<<R_DIM * H_N, 128>>>(mask);
    out_mma<<<dim3(2, NTOK / 128), 256>>>(bo, out);
}

// round 11
// speedup vs baseline: 1.8795x; 1.1546x over previous
#include <cuda_runtime.h>
#include <cuda_bf16.h>
#include <cuda_fp16.h>

// Problem constants
#define R_DIM 128
#define W_DIM 256
#define DNODE 256
#define DEDGE 128
#define H_N   8
#define DHEAD 32
#define NTOK  (R_DIM * W_DIM)       // 32768
#define NEGMAX (-3.4028234663852886e38f)

// ---------------- scratch (device globals: allocation-free) ----------------
__device__ float g_q   [NTOK * DNODE];          // [rh][i][32] fp32 (unscaled)
__device__ float g_gate[NTOK * DNODE];
__device__ __half g_bias[H_N * W_DIM * W_DIM];  // [h][j][i], fp16 (masked = -65504)
// bf16 split planes (hi + lo ~= fp32)
__device__ __nv_bfloat16 g_xnh [NTOK * DNODE];
__device__ __nv_bfloat16 g_xnl [NTOK * DNODE];
__device__ __nv_bfloat16 g_atth[NTOK * DNODE];
__device__ __nv_bfloat16 g_attl[NTOK * DNODE];
__device__ __nv_bfloat16 g_wph [1024 * 256];    // [n][k]
__device__ __nv_bfloat16 g_wpl [1024 * 256];
__device__ __nv_bfloat16 g_woh [256 * 256];
__device__ __nv_bfloat16 g_wol [256 * 256];
__device__ __nv_bfloat16 g_kh  [NTOK * DNODE];  // [rh][j][32d]
__device__ __nv_bfloat16 g_kl  [NTOK * DNODE];
__device__ __nv_bfloat16 g_vh  [NTOK * DNODE];  // [rh][32d][256j] (transposed)
__device__ __nv_bfloat16 g_vl  [NTOK * DNODE];

// ---------------- helpers ----------------
__device__ __forceinline__ void mma_bf16(float* d,
                                         unsigned a0, unsigned a1, unsigned a2, unsigned a3,
                                         unsigned b0, unsigned b1) {
    asm volatile(
        "mma.sync.aligned.m16n8k16.row.col.f32.bf16.bf16.f32 "
        "{%0,%1,%2,%3}, {%4,%5,%6,%7}, {%8,%9}, {%0,%1,%2,%3};"
        : "+f"(d[0]), "+f"(d[1]), "+f"(d[2]), "+f"(d[3])
        : "r"(a0), "r"(a1), "r"(a2), "r"(a3), "r"(b0), "r"(b1));
}
__device__ __forceinline__ void split_bf16(float x, __nv_bfloat16& hi, __nv_bfloat16& lo) {
    hi = __float2bfloat16(x);
    lo = __float2bfloat16(x - __bfloat162float(hi));
}
__device__ __forceinline__ unsigned bfpack(__nv_bfloat16 a, __nv_bfloat16 b) {
    return (unsigned)__bfloat16_as_ushort(a) | ((unsigned)__bfloat16_as_ushort(b) << 16);
}
// split two floats into packed hi/lo bf16x2
__device__ __forceinline__ void split2(float a, float b, unsigned& hi, unsigned& lo) {
    __nv_bfloat16 ha, la, hb, lb;
    split_bf16(a, ha, la);
    split_bf16(b, hb, lb);
    hi = bfpack(ha, hb);
    lo = bfpack(la, lb);
}
#define CP16(dst_u32, src_ptr) \
    asm volatile("cp.async.ca.shared.global [%0], [%1], 16;" :: "r"(dst_u32), "l"(src_ptr))
__device__ __forceinline__ void cp_commit() { asm volatile("cp.async.commit_group;"); }
__device__ __forceinline__ void cp_wait0()  { asm volatile("cp.async.wait_group 0;"); }
__device__ __forceinline__ void cp_wait1()  { asm volatile("cp.async.wait_group 1;"); }
#define LDSM4(r0, r1, r2, r3, addr) \
    asm volatile("ldmatrix.sync.aligned.m8n8.x4.shared.b16 {%0,%1,%2,%3}, [%4];" \
        : "=r"(r0), "=r"(r1), "=r"(r2), "=r"(r3) : "r"(addr));

// GEMM smem: RS=16 (no pad), XOR swizzle (chunk ^= (row&4)<<1)
#define RS 16
#define PLANE (128 * RS)

// ---------------- kernel 1: LayerNorm(x) -> bf16 split planes ----------------
__global__ void ln_x_kernel(const float* __restrict__ x,
                            const float* __restrict__ g,
                            const float* __restrict__ b) {
    int warp = threadIdx.x >> 5, lane = threadIdx.x & 31;
    int tok  = blockIdx.x * 8 + warp;
    const float* xp = x + (size_t)tok * 256 + lane * 8;
    float4 a0 = *(const float4*)xp;
    float4 a1 = *(const float4*)(xp + 4);
    float s  = a0.x + a0.y + a0.z + a0.w + a1.x + a1.y + a1.z + a1.w;
    float ss = a0.x*a0.x + a0.y*a0.y + a0.z*a0.z + a0.w*a0.w
             + a1.x*a1.x + a1.y*a1.y + a1.z*a1.z + a1.w*a1.w;
    #pragma unroll
    for (int off = 16; off; off >>= 1) {
        s  += __shfl_xor_sync(0xffffffffu, s,  off);
        ss += __shfl_xor_sync(0xffffffffu, ss, off);
    }
    float mu  = s * (1.0f / 256.0f);
    float var = ss * (1.0f / 256.0f) - mu * mu;
    float rs  = rsqrtf(var + 1e-5f);
    float4 g0 = *(const float4*)(g + lane * 8);
    float4 g1 = *(const float4*)(g + lane * 8 + 4);
    float4 b0 = *(const float4*)(b + lane * 8);
    float4 b1 = *(const float4*)(b + lane * 8 + 4);
    float v[8];
    v[0] = (a0.x - mu) * rs * g0.x + b0.x;
    v[1] = (a0.y - mu) * rs * g0.y + b0.y;
    v[2] = (a0.z - mu) * rs * g0.z + b0.z;
    v[3] = (a0.w - mu) * rs * g0.w + b0.w;
    v[4] = (a1.x - mu) * rs * g1.x + b1.x;
    v[5] = (a1.y - mu) * rs * g1.y + b1.y;
    v[6] = (a1.z - mu) * rs * g1.z + b1.z;
    v[7] = (a1.w - mu) * rs * g1.w + b1.w;
    unsigned hu[4], lu[4];
    #pragma unroll
    for (int p = 0; p < 4; p++) split2(v[2 * p], v[2 * p + 1], hu[p], lu[p]);
    size_t off = (size_t)tok * 256 + lane * 8;
    *(uint4*)&g_xnh[off] = make_uint4(hu[0], hu[1], hu[2], hu[3]);
    *(uint4*)&g_xnl[off] = make_uint4(lu[0], lu[1], lu[2], lu[3]);
}

// ---------------- kernel 1b: weight split+transpose -> [n][k] bf16 planes ----------
__global__ void wsplit_kernel(const float* __restrict__ Wq, const float* __restrict__ Wkv,
                              const float* __restrict__ Wg, const float* __restrict__ Wo) {
    int n = blockIdx.x, k = threadIdx.x;
    float w;
    if (n < 256)       w = Wq [(size_t)k * 256 + n];
    else if (n < 768)  w = Wkv[(size_t)k * 512 + (n - 256)];
    else if (n < 1024) w = Wg [(size_t)k * 256 + (n - 768)];
    else               w = Wo [(size_t)k * 256 + (n - 1024)];
    __nv_bfloat16 h, l;
    split_bf16(w, h, l);
    if (n < 1024) {
        g_wph[(size_t)n * 256 + k] = h;
        g_wpl[(size_t)n * 256 + k] = l;
    } else {
        g_woh[(size_t)(n - 1024) * 256 + k] = h;
        g_wol[(size_t)(n - 1024) * 256 + k] = l;
    }
}

// ---------------- kernel 2: edge LN + W_edge + edge_mask -> fp16 g_bias[h][j][i] ------
__global__ void bias_kernel(const float* __restrict__ edges,
                            const float* __restrict__ lg,
                            const float* __restrict__ lb,
                            const float* __restrict__ We,
                            const unsigned int* __restrict__ emask) {
    __shared__ float sW[DEDGE * H_N];
    __shared__ float sg[DEDGE], sb[DEDGE];
    int t = threadIdx.x;
    for (int l = t; l < DEDGE * H_N; l += 256) sW[l] = We[l];
    if (t < DEDGE) { sg[t] = lg[t]; sb[t] = lb[t]; }
    __syncthreads();

    int warp = t >> 5, lane = t & 31;
    int p = blockIdx.x * 8 + warp;
    int i = p >> 8, j = p & 255;

    if (emask[p] == 0u) {
        if (lane < 8) g_bias[(lane * W_DIM + j) * W_DIM + i] = __float2half(-65504.0f);
        return;
    }
    const float* ep = edges + (size_t)p * DEDGE + lane * 4;
    float4 e = *(const float4*)ep;
    float s  = e.x + e.y + e.z + e.w;
    float ss = e.x*e.x + e.y*e.y + e.z*e.z + e.w*e.w;
    #pragma unroll
    for (int off = 16; off; off >>= 1) {
        s  += __shfl_xor_sync(0xffffffffu, s,  off);
        ss += __shfl_xor_sync(0xffffffffu, ss, off);
    }
    float mu  = s * (1.0f / 128.0f);
    float var = ss * (1.0f / 128.0f) - mu * mu;
    float rs  = rsqrtf(var + 1e-5f);
    int e0 = lane * 4;
    float en[4];
    en[0] = (e.x - mu) * rs * sg[e0 + 0] + sb[e0 + 0];
    en[1] = (e.y - mu) * rs * sg[e0 + 1] + sb[e0 + 1];
    en[2] = (e.z - mu) * rs * sg[e0 + 2] + sb[e0 + 2];
    en[3] = (e.w - mu) * rs * sg[e0 + 3] + sb[e0 + 3];
    float acc[8];
    #pragma unroll
    for (int h = 0; h < 8; h++) acc[h] = 0.0f;
    #pragma unroll
    for (int c = 0; c < 4; c++) {
        const float* wr = &sW[(e0 + c) * 8];
        #pragma unroll
        for (int h = 0; h < 8; h++) acc[h] += en[c] * wr[h];
    }
    #pragma unroll
    for (int h = 0; h < 8; h++) {
        #pragma unroll
        for (int off = 16; off; off >>= 1)
            acc[h] += __shfl_xor_sync(0xffffffffu, acc[h], off);
    }
    if (lane == 0) {
        #pragma unroll
        for (int h = 0; h < 8; h++)
            g_bias[(h * W_DIM + j) * W_DIM + i] = __float2half(acc[h]);
    }
}

// ---------------- bf16x3 GEMM (ldmatrix + swizzle + 3-stage pipeline) ----------------
#define GEMM_SMEM()                                                            \
    __shared__ __nv_bfloat16 sAh[3][PLANE], sAl[3][PLANE];                     \
    __shared__ __nv_bfloat16 sBh[3][PLANE], sBl[3][PLANE];

#define GEMM_ISSUE(buf, kt, Ahp, Alp, Bhp, Blp, abase, nbase)                  \
    {                                                                          \
        int k0 = (kt) * 16 + ch;                                               \
        unsigned doff = ((unsigned)(buf) * PLANE + row * RS + chsw) * 2;       \
        CP16(sAh_u + doff, (Ahp) + (size_t)((abase) + row) * 256 + k0);        \
        CP16(sAl_u + doff, (Alp) + (size_t)((abase) + row) * 256 + k0);        \
        CP16(sBh_u + doff, (Bhp) + (size_t)((nbase) + row) * 256 + k0);        \
        CP16(sBl_u + doff, (Blp) + (size_t)((nbase) + row) * 256 + k0);        \
        cp_commit();                                                           \
    }

#define GEMM_LANEOFF()                                                         \
    int arow  = (lane & 7) + ((lane >> 3) & 1) * 8;                            \
    int achnk = ((lane >> 4) * 8) ^ ((arow & 4) << 1);                         \
    int brow  = (lane & 7) + ((lane >> 4) & 1) * 8;                            \
    int bchnk = (((lane >> 3) & 1) * 8) ^ ((brow & 4) << 1);

#define GEMM_KTILE(st)                                                         \
    {                                                                          \
        unsigned stoff = (unsigned)(st) * PLANE * 2;                           \
        unsigned bh[4][2], bl[4][2];                                           \
        _Pragma("unroll")                                                      \
        for (int p = 0; p < 2; p++) {                                          \
            unsigned bo = ((wn * 32 + p * 16 + brow) * RS + bchnk) * 2;        \
            LDSM4(bh[2*p][0], bh[2*p][1], bh[2*p+1][0], bh[2*p+1][1],          \
                  sBh_u + stoff + bo)                                          \
            LDSM4(bl[2*p][0], bl[2*p][1], bl[2*p+1][0], bl[2*p+1][1],          \
                  sBl_u + stoff + bo)                                          \
        }                                                                      \
        _Pragma("unroll")                                                      \
        for (int am = 0; am < 4; am++) {                                       \
            unsigned ao = ((wm * 64 + am * 16 + arow) * RS + achnk) * 2;       \
            unsigned ah0, ah1, ah2, ah3, al0, al1, al2, al3;                   \
            LDSM4(ah0, ah1, ah2, ah3, sAh_u + stoff + ao)                      \
            LDSM4(al0, al1, al2, al3, sAl_u + stoff + ao)                      \
            _Pragma("unroll")                                                  \
            for (int an = 0; an < 4; an++) {                                   \
                float* ac = acc[am][an];                                       \
                mma_bf16(ac, ah0, ah1, ah2, ah3, bh[an][0], bh[an][1]);        \
                mma_bf16(ac, ah0, ah1, ah2, ah3, bl[an][0], bl[an][1]);        \
                mma_bf16(ac, al0, al1, al2, al3, bh[an][0], bh[an][1]);        \
            }                                                                  \
        }                                                                      \
    }

#define GEMM_MAINLOOP(Ahp, Alp, Bhp, Blp, abase, nbase)                        \
    GEMM_ISSUE(0, 0, Ahp, Alp, Bhp, Blp, abase, nbase)                         \
    GEMM_ISSUE(1, 1, Ahp, Alp, Bhp, Blp, abase, nbase)                         \
    for (int kt = 0; kt < 16; kt++) {                                          \
        if (kt < 15) cp_wait1(); else cp_wait0();                              \
        __syncthreads();                                                       \
        if (kt <= 13) {                                                        \
            int nbuf = (kt + 2) % 3;                                           \
            GEMM_ISSUE(nbuf, kt + 2, Ahp, Alp, Bhp, Blp, abase, nbase)         \
        }                                                                      \
        GEMM_KTILE(kt % 3)                                                     \
    }

// ---------------- kernel 3: projection GEMM (bf16x3) ----------------
__global__ void __launch_bounds__(256, 2)
proj_mma(const float* __restrict__ bg) {
    GEMM_SMEM()
    int t = threadIdx.x, lane = t & 31, warp = t >> 5;
    int wm = warp >> 2, wn = warp & 3;
    int g = lane >> 2, c = lane & 3;
    int bn = blockIdx.x, bm = blockIdx.y;
    int nb = bn * 128;
    int abase = bm * 128;

    unsigned sAh_u = (unsigned)__cvta_generic_to_shared(sAh);
    unsigned sAl_u = (unsigned)__cvta_generic_to_shared(sAl);
    unsigned sBh_u = (unsigned)__cvta_generic_to_shared(sBh);
    unsigned sBl_u = (unsigned)__cvta_generic_to_shared(sBl);
    int row = t >> 1, ch = (t & 1) * 8;
    int chsw = ch ^ ((row & 4) << 1);
    GEMM_LANEOFF()

    float acc[4][4][4];
    #pragma unroll
    for (int am = 0; am < 4; am++)
        #pragma unroll
        for (int an = 0; an < 4; an++)
            #pragma unroll
            for (int v = 0; v < 4; v++) acc[am][an][v] = 0.0f;

    GEMM_MAINLOOP(g_xnh, g_xnl, g_wph, g_wpl, abase, nb)

    #pragma unroll
    for (int am = 0; am < 4; am++) {
        int tok = abase + wm * 64 + am * 16 + g;
        int rr = tok >> 8, iw = tok & 255;
        #pragma unroll
        for (int an = 0; an < 4; an++) {
            int gc = nb + wn * 32 + an * 8 + 2 * c;
            float a0 = acc[am][an][0], a1 = acc[am][an][1];
            float a2 = acc[am][an][2], a3 = acc[am][an][3];
            if (gc < 256) {                       // q: fp32, [rh][i][d]
                int hh = gc >> 5, d8 = gc & 31;
                float* p0 = g_q + ((size_t)((rr * 8 + hh) * 256 + iw)) * 32 + d8;
                *(float2*)p0            = make_float2(a0, a1);
                *(float2*)(p0 + 8 * 32) = make_float2(a2, a3);
            } else if (gc < 512) {                // k: bf16 split, [rh][j][d]
                int cq = gc - 256;
                int hh = cq >> 5, d8 = cq & 31;
                size_t b0 = ((size_t)((rr * 8 + hh) * 256 + iw)) * 32 + d8;
                unsigned hi0, lo0, hi1, lo1;
                split2(a0, a1, hi0, lo0);
                split2(a2, a3, hi1, lo1);
                *(unsigned*)&g_kh[b0] = hi0;  *(unsigned*)&g_kl[b0] = lo0;
                *(unsigned*)&g_kh[b0 + 256] = hi1;  *(unsigned*)&g_kl[b0 + 256] = lo1;
            } else if (gc < 768) {                // v: bf16 split, transposed [rh][d][j]
                int cq = gc - 512;
                int hh = cq >> 5, d8 = cq & 31;
                size_t vb = ((size_t)((rr * 8 + hh) * 32 + d8)) * 256 + iw;
                __nv_bfloat16 h0, l0, h1, l1;
                split_bf16(a0, h0, l0);  g_vh[vb] = h0;        g_vl[vb] = l0;
                split_bf16(a1, h1, l1);  g_vh[vb + 256] = h1;  g_vl[vb + 256] = l1;
                split_bf16(a2, h0, l0);  g_vh[vb + 8] = h0;    g_vl[vb + 8] = l0;
                split_bf16(a3, h1, l1);  g_vh[vb + 264] = h1;  g_vl[vb + 264] = l1;
            } else {                              // gate: sigmoid fp32
                int gcol = gc - 768;
                float2 bg2 = *(const float2*)(bg + gcol);
                float* p0 = g_gate + (size_t)tok * 256 + gcol;
                float* p1 = p0 + 8 * 256;
                *(float2*)p0 = make_float2(1.0f / (1.0f + __expf(-(a0 + bg2.x))),
                                           1.0f / (1.0f + __expf(-(a1 + bg2.y))));
                *(float2*)p1 = make_float2(1.0f / (1.0f + __expf(-(a2 + bg2.x))),
                                           1.0f / (1.0f + __expf(-(a3 + bg2.y))));
            }
        }
    }
}

// ---------------- kernel 5: output projection (bf16x3) ----------------
__global__ void __launch_bounds__(256, 2)
out_mma(const float* __restrict__ bo, float* __restrict__ out) {
    GEMM_SMEM()
    int t = threadIdx.x, lane = t & 31, warp = t >> 5;
    int wm = warp >> 2, wn = warp & 3;
    int g = lane >> 2, c = lane & 3;
    int bn = blockIdx.x, bm = blockIdx.y;
    int nb = bn * 128;
    int abase = bm * 128;

    unsigned sAh_u = (unsigned)__cvta_generic_to_shared(sAh);
    unsigned sAl_u = (unsigned)__cvta_generic_to_shared(sAl);
    unsigned sBh_u = (unsigned)__cvta_generic_to_shared(sBh);
    unsigned sBl_u = (unsigned)__cvta_generic_to_shared(sBl);
    int row = t >> 1, ch = (t & 1) * 8;
    int chsw = ch ^ ((row & 4) << 1);
    GEMM_LANEOFF()

    float acc[4][4][4];
    #pragma unroll
    for (int am = 0; am < 4; am++)
        #pragma unroll
        for (int an = 0; an < 4; an++)
            #pragma unroll
            for (int v = 0; v < 4; v++) acc[am][an][v] = 0.0f;

    GEMM_MAINLOOP(g_atth, g_attl, g_woh, g_wol, abase, nb)

    #pragma unroll
    for (int am = 0; am < 4; am++) {
        int tok = abase + wm * 64 + am * 16 + g;
        #pragma unroll
        for (int an = 0; an < 4; an++) {
            int gc = nb + wn * 32 + an * 8 + 2 * c;
            float2 bo2 = *(const float2*)(bo + gc);
            float* p0 = out + (size_t)tok * 256 + gc;
            float* p1 = p0 + 8 * 256;
            *(float2*)p0 = make_float2(acc[am][an][0] + bo2.x, acc[am][an][1] + bo2.y);
            *(float2*)p1 = make_float2(acc[am][an][2] + bo2.x, acc[am][an][3] + bo2.y);
        }
    }
}

// ---------------- kernel 4: attention via bf16x3 mma.sync ----------------
// one CTA per (r,h); 256 threads (8 warps, 32 queries each); keys in 8 chunks of 32
#define A_BIAS_SZ (32 * 264 * 2)      // 16896
#define A_K_OFF   A_BIAS_SZ           // kh at 16896
#define A_KL_OFF  (A_K_OFF + 32 * 80) // 19456
#define A_VH_OFF  (A_KL_OFF + 32 * 80)
#define A_VL_OFF  (A_VH_OFF + 32 * 80)
#define A_STAGE   (A_VL_OFF + 32 * 80)   // 27136
#define A_SMEM    (3 * A_STAGE)          // 81408

__global__ void __launch_bounds__(256, 1)
attn_mma(const unsigned int* __restrict__ mask) {
    extern __shared__ char asmem[];
    __shared__ unsigned mwords[8];

    int t = threadIdx.x, lane = t & 31, w = t >> 5;
    int g = lane >> 2, c = lane & 3;
    int rh = blockIdx.x;
    int r = rh >> 3, h = rh & 7;
    unsigned smem_u = (unsigned)__cvta_generic_to_shared(asmem);

    // key-mask ballot words
    if (w == 0) {
        #pragma unroll
        for (int q = 0; q < 8; q++) {
            unsigned bit = (mask[r * 256 + q * 32 + lane] != 0u) ? 1u : 0u;
            unsigned word = __ballot_sync(0xffffffffu, bit);
            if (lane == 0) mwords[q] = word;
        }
    }

    const float sc = 0.17677669529663689f;   // 32^-0.5
    int mbase = w * 32;
    int i_r[2][2];
    int rowv[2][2];
    unsigned qh[2][2][4], ql[2][2][4];
    #pragma unroll
    for (int mt = 0; mt < 2; mt++) {
        int i0 = mbase + mt * 16 + g, i1 = i0 + 8;
        i_r[mt][0] = i0; i_r[mt][1] = i1;
        rowv[mt][0] = (mask[r * 256 + i0] != 0u);
        rowv[mt][1] = (mask[r * 256 + i1] != 0u);
        const float* q0 = g_q + ((size_t)rh * 256 + i0) * 32;
        const float* q1 = g_q + ((size_t)rh * 256 + i1) * 32;
        #pragma unroll
        for (int ks = 0; ks < 2; ks++) {
            float2 x0 = *(const float2*)(q0 + ks * 16 + 2 * c);
            float2 x1 = *(const float2*)(q1 + ks * 16 + 2 * c);
            float2 x2 = *(const float2*)(q0 + ks * 16 + 2 * c + 8);
            float2 x3 = *(const float2*)(q1 + ks * 16 + 2 * c + 8);
            split2(x0.x * sc, x0.y * sc, qh[mt][ks][0], ql[mt][ks][0]);
            split2(x1.x * sc, x1.y * sc, qh[mt][ks][1], ql[mt][ks][1]);
            split2(x2.x * sc, x2.y * sc, qh[mt][ks][2], ql[mt][ks][2]);
            split2(x3.x * sc, x3.y * sc, qh[mt][ks][3], ql[mt][ks][3]);
        }
    }

    float O[2][4][4];
    float l[2][2] = {{0.0f, 0.0f}, {0.0f, 0.0f}};
    #pragma unroll
    for (int mt = 0; mt < 2; mt++)
        #pragma unroll
        for (int dt = 0; dt < 4; dt++)
            #pragma unroll
            for (int v = 0; v < 4; v++) O[mt][dt][v] = 0.0f;

    const __half* bbase = g_bias + (size_t)(h * 256) * 256;
    const __nv_bfloat16* khb = g_kh + (size_t)rh * 256 * 32;
    const __nv_bfloat16* klb = g_kl + (size_t)rh * 256 * 32;
    const __nv_bfloat16* vhb = g_vh + (size_t)rh * 32 * 256;
    const __nv_bfloat16* vlb = g_vl + (size_t)rh * 32 * 256;

    // cp.async per chunk: bias 4 + K/L 1 + V/L 1 per thread
    int bjr = t >> 3, bsg = t & 7;
    int tt = t & 127, kvr = tt >> 2, kvs = tt & 3;

    #define AISSUE(chv)                                                            \
    {                                                                              \
        unsigned sb = smem_u + (unsigned)((chv) % 3) * A_STAGE;                    \
        const __half* bs = bbase + (size_t)((chv) * 32 + bjr) * 256;               \
        _Pragma("unroll")                                                          \
        for (int q = 0; q < 4; q++)                                                \
            CP16(sb + bjr * 528 + (bsg + 8 * q) * 16, bs + (bsg + 8 * q) * 8);     \
        if (t < 128) {                                                             \
            CP16(sb + A_K_OFF  + kvr * 80 + kvs * 16,                              \
                 khb + (size_t)((chv) * 32 + kvr) * 32 + kvs * 8);                 \
            CP16(sb + A_VH_OFF + kvr * 80 + kvs * 16,                              \
                 vhb + (size_t)kvr * 256 + (chv) * 32 + kvs * 8);                  \
        } else {                                                                   \
            CP16(sb + A_KL_OFF + kvr * 80 + kvs * 16,                              \
                 klb + (size_t)((chv) * 32 + kvr) * 32 + kvs * 8);                 \
            CP16(sb + A_VL_OFF + kvr * 80 + kvs * 16,                              \
                 vlb + (size_t)kvr * 256 + (chv) * 32 + kvs * 8);                  \
        }                                                                          \
        cp_commit();                                                               \
    }

    AISSUE(0)
    AISSUE(1)

    int brow = (lane & 7) + ((lane >> 4) & 1) * 8;
    int bch  = ((lane >> 3) & 1) * 8;

    for (int chk = 0; chk < 8; chk++) {
        if (chk < 7) cp_wait1(); else cp_wait0();
        __syncthreads();
        if (chk + 2 < 8) AISSUE(chk + 2)

        int st = chk % 3;
        unsigned sb = smem_u + (unsigned)st * A_STAGE;
        const __half* bias_s = (const __half*)(asmem + st * A_STAGE);

        // K fragments
        unsigned kfh[2][4][2], kfl[2][4][2];
        #pragma unroll
        for (int p = 0; p < 2; p++) {
            #pragma unroll
            for (int ks = 0; ks < 2; ks++) {
                unsigned ao = sb + A_K_OFF + (p * 16 + brow) * 80 + (ks * 16 + bch) * 2;
                LDSM4(kfh[ks][2*p][0], kfh[ks][2*p][1], kfh[ks][2*p+1][0], kfh[ks][2*p+1][1], ao)
                unsigned al_ = sb + A_KL_OFF + (p * 16 + brow) * 80 + (ks * 16 + bch) * 2;
                LDSM4(kfl[ks][2*p][0], kfl[ks][2*p][1], kfl[ks][2*p+1][0], kfl[ks][2*p+1][1], al_)
            }
        }

        // S = (q*sc) @ K^T  (bf16x3)
        float S[2][4][4];
        #pragma unroll
        for (int mt = 0; mt < 2; mt++)
            #pragma unroll
            for (int jt = 0; jt < 4; jt++) {
                #pragma unroll
                for (int v = 0; v < 4; v++) S[mt][jt][v] = 0.0f;
                #pragma unroll
                for (int ks = 0; ks < 2; ks++) {
                    mma_bf16(S[mt][jt], qh[mt][ks][0], qh[mt][ks][1], qh[mt][ks][2], qh[mt][ks][3],
                             kfh[ks][jt][0], kfh[ks][jt][1]);
                    mma_bf16(S[mt][jt], qh[mt][ks][0], qh[mt][ks][1], qh[mt][ks][2], qh[mt][ks][3],
                             kfl[ks][jt][0], kfl[ks][jt][1]);
                    mma_bf16(S[mt][jt], ql[mt][ks][0], ql[mt][ks][1], ql[mt][ks][2], ql[mt][ks][3],
                             kfh[ks][jt][0], kfh[ks][jt][1]);
                }
            }

        // bias + mask + exp
        unsigned mb = mwords[chk];
        #pragma unroll
        for (int mt = 0; mt < 2; mt++) {
            #pragma unroll
            for (int jt = 0; jt < 4; jt++) {
                int j0 = jt * 8 + 2 * c;
                float b00 = __half2float(bias_s[j0 * 264 + i_r[mt][0]]);
                float b01 = __half2float(bias_s[(j0 + 1) * 264 + i_r[mt][0]]);
                float b10 = __half2float(bias_s[j0 * 264 + i_r[mt][1]]);
                float b11 = __half2float(bias_s[(j0 + 1) * 264 + i_r[mt][1]]);
                unsigned jm0 = (mb >> j0) & 1u, jm1 = (mb >> (j0 + 1)) & 1u;
                float p00 = jm0 ? __expf(S[mt][jt][0] + b00) : 0.0f;
                float p01 = jm1 ? __expf(S[mt][jt][1] + b01) : 0.0f;
                float p10 = jm0 ? __expf(S[mt][jt][2] + b10) : 0.0f;
                float p11 = jm1 ? __expf(S[mt][jt][3] + b11) : 0.0f;
                if (!rowv[mt][0]) { p00 = 1.0f; p01 = 1.0f; }
                if (!rowv[mt][1]) { p10 = 1.0f; p11 = 1.0f; }
                l[mt][0] += p00 + p01;
                l[mt][1] += p10 + p11;
                S[mt][jt][0] = p00; S[mt][jt][1] = p01;
                S[mt][jt][2] = p10; S[mt][jt][3] = p11;
            }
        }

        // O += P @ V  (P split exactly; V split)
        #pragma unroll
        for (int ks = 0; ks < 2; ks++) {
            unsigned vfh[4][2], vfl[4][2];
            #pragma unroll
            for (int p = 0; p < 2; p++) {
                unsigned ao = sb + A_VH_OFF + (p * 16 + brow) * 80 + (ks * 16 + bch) * 2;
                LDSM4(vfh[2*p][0], vfh[2*p][1], vfh[2*p+1][0], vfh[2*p+1][1], ao)
                unsigned al_ = sb + A_VL_OFF + (p * 16 + brow) * 80 + (ks * 16 + bch) * 2;
                LDSM4(vfl[2*p][0], vfl[2*p][1], vfl[2*p+1][0], vfl[2*p+1][1], al_)
            }
            #pragma unroll
            for (int mt = 0; mt < 2; mt++) {
                const float* PA = S[mt][2 * ks];
                const float* PB = S[mt][2 * ks + 1];
                unsigned ah0, ah1, ah2, ah3, al0, al1, al2, al3;
                split2(PA[0], PA[1], ah0, al0);
                split2(PA[2], PA[3], ah1, al1);
                split2(PB[0], PB[1], ah2, al2);
                split2(PB[2], PB[3], ah3, al3);
                #pragma unroll
                for (int dt = 0; dt < 4; dt++) {
                    mma_bf16(O[mt][dt], ah0, ah1, ah2, ah3, vfh[dt][0], vfh[dt][1]);
                    mma_bf16(O[mt][dt], ah0, ah1, ah2, ah3, vfl[dt][0], vfl[dt][1]);
                    mma_bf16(O[mt][dt], al0, al1, al2, al3, vfh[dt][0], vfh[dt][1]);
                }
            }
        }
    }
    #undef AISSUE

    // finalize: reduce l over quad, normalize, gate, split-store
    float inv[2][2];
    #pragma unroll
    for (int mt = 0; mt < 2; mt++)
        #pragma unroll
        for (int rr2 = 0; rr2 < 2; rr2++) {
            float ls = l[mt][rr2];
            ls += __shfl_xor_sync(0xffffffffu, ls, 1);
            ls += __shfl_xor_sync(0xffffffffu, ls, 2);
            inv[mt][rr2] = 1.0f / ls;
        }

    #pragma unroll
    for (int mt = 0; mt < 2; mt++) {
        int tok0 = r * 256 + i_r[mt][0];
        int tok1 = r * 256 + i_r[mt][1];
        #pragma unroll
        for (int dt = 0; dt < 4; dt++) {
            int col = h * 32 + dt * 8 + 2 * c;
            float2 g0 = *(const float2*)&g_gate[(size_t)tok0 * 256 + col];
            float2 g1 = *(const float2*)&g_gate[(size_t)tok1 * 256 + col];
            float o00 = O[mt][dt][0] * inv[mt][0] * g0.x;
            float o01 = O[mt][dt][1] * inv[mt][0] * g0.y;
            float o10 = O[mt][dt][2] * inv[mt][1] * g1.x;
            float o11 = O[mt][dt][3] * inv[mt][1] * g1.y;
            unsigned hi0, lo0, hi1, lo1;
            split2(o00, o01, hi0, lo0);
            split2(o10, o11, hi1, lo1);
            *(unsigned*)&g_atth[(size_t)tok0 * 256 + col] = hi0;
            *(unsigned*)&g_attl[(size_t)tok0 * 256 + col] = lo0;
            *(unsigned*)&g_atth[(size_t)tok1 * 256 + col] = hi1;
            *(unsigned*)&g_attl[(size_t)tok1 * 256 + col] = lo1;
        }
    }
}

// ---------------- launch ----------------
extern "C" void kernel_launch(void* const* d_in, const int* in_sizes, int n_in,
                              void* d_out, int out_size) {
    const float* x      = (const float*)d_in[0];
    const float* edges  = (const float*)d_in[1];
    const unsigned int* mask      = (const unsigned int*)d_in[2];
    const unsigned int* edge_mask = (const unsigned int*)d_in[3];
    const float* ln_g   = (const float*)d_in[4];
    const float* ln_b   = (const float*)d_in[5];
    const float* lne_g  = (const float*)d_in[6];
    const float* lne_b  = (const float*)d_in[7];
    const float* W_edge = (const float*)d_in[8];
    const float* Wq     = (const float*)d_in[9];
    const float* Wkv    = (const float*)d_in[10];
    const float* Wg     = (const float*)d_in[11];
    const float* bg     = (const float*)d_in[12];
    const float* Wo     = (const float*)d_in[13];
    const float* bo     = (const float*)d_in[14];
    float* out = (float*)d_out;

    cudaFuncSetAttribute(attn_mma, cudaFuncAttributeMaxDynamicSharedMemorySize, A_SMEM);

    ln_x_kernel<<<NTOK / 8, 256>>>(x, ln_g, ln_b);
    wsplit_kernel<<<1280, 256>>>(Wq, Wkv, Wg, Wo);
    bias_kernel<<<(W_DIM * W_DIM) / 8, 256>>>(edges, lne_g, lne_b, W_edge, edge_mask);
    proj_mma<<<dim3(8, NTOK / 128), 256>>>(bg);
    attn_mma<<<R_DIM * H_N, 256, A_SMEM>>>(mask);
    out_mma<<<dim3(2, NTOK / 128), 256>>>(bo, out);
}

// round 12
// speedup vs baseline: 1.9669x; 1.0465x over previous
#include <cuda_runtime.h>
#include <cuda_bf16.h>
#include <cuda_fp16.h>

// Problem constants
#define R_DIM 128
#define W_DIM 256
#define DNODE 256
#define DEDGE 128
#define H_N   8
#define DHEAD 32
#define NTOK  (R_DIM * W_DIM)       // 32768
#define NEGMAX (-3.4028234663852886e38f)

// ---------------- scratch (device globals: allocation-free) ----------------
__device__ float g_q   [NTOK * DNODE];          // [rh][i][32] fp32 (unscaled)
__device__ float g_gate[NTOK * DNODE];
__device__ __half g_bias[H_N * W_DIM * W_DIM];  // [h][j][i], fp16 (masked = -65504)
// bf16 split planes (hi + lo ~= fp32)
__device__ __nv_bfloat16 g_xnh [NTOK * DNODE];
__device__ __nv_bfloat16 g_xnl [NTOK * DNODE];
__device__ __nv_bfloat16 g_atth[NTOK * DNODE];
__device__ __nv_bfloat16 g_attl[NTOK * DNODE];
__device__ __nv_bfloat16 g_wph [1024 * 256];    // [n][k]
__device__ __nv_bfloat16 g_wpl [1024 * 256];
__device__ __nv_bfloat16 g_woh [256 * 256];
__device__ __nv_bfloat16 g_wol [256 * 256];
__device__ __nv_bfloat16 g_kh  [NTOK * DNODE];  // [rh][j][32d]
__device__ __nv_bfloat16 g_kl  [NTOK * DNODE];
__device__ __nv_bfloat16 g_vh  [NTOK * DNODE];  // [rh][32d][256j] (transposed)
__device__ __nv_bfloat16 g_vl  [NTOK * DNODE];

// ---------------- helpers ----------------
__device__ __forceinline__ void mma_bf16(float* d,
                                         unsigned a0, unsigned a1, unsigned a2, unsigned a3,
                                         unsigned b0, unsigned b1) {
    asm volatile(
        "mma.sync.aligned.m16n8k16.row.col.f32.bf16.bf16.f32 "
        "{%0,%1,%2,%3}, {%4,%5,%6,%7}, {%8,%9}, {%0,%1,%2,%3};"
        : "+f"(d[0]), "+f"(d[1]), "+f"(d[2]), "+f"(d[3])
        : "r"(a0), "r"(a1), "r"(a2), "r"(a3), "r"(b0), "r"(b1));
}
__device__ __forceinline__ void split_bf16(float x, __nv_bfloat16& hi, __nv_bfloat16& lo) {
    hi = __float2bfloat16(x);
    lo = __float2bfloat16(x - __bfloat162float(hi));
}
__device__ __forceinline__ unsigned bfpack(__nv_bfloat16 a, __nv_bfloat16 b) {
    return (unsigned)__bfloat16_as_ushort(a) | ((unsigned)__bfloat16_as_ushort(b) << 16);
}
__device__ __forceinline__ void split2(float a, float b, unsigned& hi, unsigned& lo) {
    __nv_bfloat16 ha, la, hb, lb;
    split_bf16(a, ha, la);
    split_bf16(b, hb, lb);
    hi = bfpack(ha, hb);
    lo = bfpack(la, lb);
}
#define CP16(dst_u32, src_ptr) \
    asm volatile("cp.async.ca.shared.global [%0], [%1], 16;" :: "r"(dst_u32), "l"(src_ptr))
__device__ __forceinline__ void cp_commit() { asm volatile("cp.async.commit_group;"); }
__device__ __forceinline__ void cp_wait0()  { asm volatile("cp.async.wait_group 0;"); }
__device__ __forceinline__ void cp_wait1()  { asm volatile("cp.async.wait_group 1;"); }
#define LDSM4(r0, r1, r2, r3, addr) \
    asm volatile("ldmatrix.sync.aligned.m8n8.x4.shared.b16 {%0,%1,%2,%3}, [%4];" \
        : "=r"(r0), "=r"(r1), "=r"(r2), "=r"(r3) : "r"(addr));

// GEMM smem: RS=16 (no pad), XOR swizzle (chunk ^= (row&4)<<1)
#define RS 16
#define PLANE (128 * RS)

// ---------------- kernel 1 (fused): LayerNorm(x) + weight split/transpose ----------
__global__ void prep_kernel(const float* __restrict__ x,
                            const float* __restrict__ g,
                            const float* __restrict__ b,
                            const float* __restrict__ Wq, const float* __restrict__ Wkv,
                            const float* __restrict__ Wg, const float* __restrict__ Wo) {
    if (blockIdx.x < NTOK / 8) {
        // ---- LayerNorm part ----
        int warp = threadIdx.x >> 5, lane = threadIdx.x & 31;
        int tok  = blockIdx.x * 8 + warp;
        const float* xp = x + (size_t)tok * 256 + lane * 8;
        float4 a0 = *(const float4*)xp;
        float4 a1 = *(const float4*)(xp + 4);
        float s  = a0.x + a0.y + a0.z + a0.w + a1.x + a1.y + a1.z + a1.w;
        float ss = a0.x*a0.x + a0.y*a0.y + a0.z*a0.z + a0.w*a0.w
                 + a1.x*a1.x + a1.y*a1.y + a1.z*a1.z + a1.w*a1.w;
        #pragma unroll
        for (int off = 16; off; off >>= 1) {
            s  += __shfl_xor_sync(0xffffffffu, s,  off);
            ss += __shfl_xor_sync(0xffffffffu, ss, off);
        }
        float mu  = s * (1.0f / 256.0f);
        float var = ss * (1.0f / 256.0f) - mu * mu;
        float rs  = rsqrtf(var + 1e-5f);
        float4 g0 = *(const float4*)(g + lane * 8);
        float4 g1 = *(const float4*)(g + lane * 8 + 4);
        float4 b0 = *(const float4*)(b + lane * 8);
        float4 b1 = *(const float4*)(b + lane * 8 + 4);
        float v[8];
        v[0] = (a0.x - mu) * rs * g0.x + b0.x;
        v[1] = (a0.y - mu) * rs * g0.y + b0.y;
        v[2] = (a0.z - mu) * rs * g0.z + b0.z;
        v[3] = (a0.w - mu) * rs * g0.w + b0.w;
        v[4] = (a1.x - mu) * rs * g1.x + b1.x;
        v[5] = (a1.y - mu) * rs * g1.y + b1.y;
        v[6] = (a1.z - mu) * rs * g1.z + b1.z;
        v[7] = (a1.w - mu) * rs * g1.w + b1.w;
        unsigned hu[4], lu[4];
        #pragma unroll
        for (int p = 0; p < 4; p++) split2(v[2 * p], v[2 * p + 1], hu[p], lu[p]);
        size_t off = (size_t)tok * 256 + lane * 8;
        *(uint4*)&g_xnh[off] = make_uint4(hu[0], hu[1], hu[2], hu[3]);
        *(uint4*)&g_xnl[off] = make_uint4(lu[0], lu[1], lu[2], lu[3]);
    } else {
        // ---- weight split part ----
        int n = blockIdx.x - NTOK / 8, k = threadIdx.x;
        float w;
        if (n < 256)       w = Wq [(size_t)k * 256 + n];
        else if (n < 768)  w = Wkv[(size_t)k * 512 + (n - 256)];
        else if (n < 1024) w = Wg [(size_t)k * 256 + (n - 768)];
        else               w = Wo [(size_t)k * 256 + (n - 1024)];
        __nv_bfloat16 h, l;
        split_bf16(w, h, l);
        if (n < 1024) {
            g_wph[(size_t)n * 256 + k] = h;
            g_wpl[(size_t)n * 256 + k] = l;
        } else {
            g_woh[(size_t)(n - 1024) * 256 + k] = h;
            g_wol[(size_t)(n - 1024) * 256 + k] = l;
        }
    }
}

// ---------------- kernel 2: edge LN + W_edge + edge_mask -> fp16 g_bias[h][j][i] ------
__global__ void bias_kernel(const float* __restrict__ edges,
                            const float* __restrict__ lg,
                            const float* __restrict__ lb,
                            const float* __restrict__ We,
                            const unsigned int* __restrict__ emask) {
    __shared__ float sW[DEDGE * H_N];
    __shared__ float sg[DEDGE], sb[DEDGE];
    int t = threadIdx.x;
    for (int l = t; l < DEDGE * H_N; l += 256) sW[l] = We[l];
    if (t < DEDGE) { sg[t] = lg[t]; sb[t] = lb[t]; }
    __syncthreads();

    int warp = t >> 5, lane = t & 31;
    int p = blockIdx.x * 8 + warp;
    int i = p >> 8, j = p & 255;

    if (emask[p] == 0u) {
        if (lane < 8) g_bias[(lane * W_DIM + j) * W_DIM + i] = __float2half(-65504.0f);
        return;
    }
    const float* ep = edges + (size_t)p * DEDGE + lane * 4;
    float4 e = *(const float4*)ep;
    float s  = e.x + e.y + e.z + e.w;
    float ss = e.x*e.x + e.y*e.y + e.z*e.z + e.w*e.w;
    #pragma unroll
    for (int off = 16; off; off >>= 1) {
        s  += __shfl_xor_sync(0xffffffffu, s,  off);
        ss += __shfl_xor_sync(0xffffffffu, ss, off);
    }
    float mu  = s * (1.0f / 128.0f);
    float var = ss * (1.0f / 128.0f) - mu * mu;
    float rs  = rsqrtf(var + 1e-5f);
    int e0 = lane * 4;
    float en[4];
    en[0] = (e.x - mu) * rs * sg[e0 + 0] + sb[e0 + 0];
    en[1] = (e.y - mu) * rs * sg[e0 + 1] + sb[e0 + 1];
    en[2] = (e.z - mu) * rs * sg[e0 + 2] + sb[e0 + 2];
    en[3] = (e.w - mu) * rs * sg[e0 + 3] + sb[e0 + 3];
    float acc[8];
    #pragma unroll
    for (int h = 0; h < 8; h++) acc[h] = 0.0f;
    #pragma unroll
    for (int c = 0; c < 4; c++) {
        const float* wr = &sW[(e0 + c) * 8];
        #pragma unroll
        for (int h = 0; h < 8; h++) acc[h] += en[c] * wr[h];
    }
    #pragma unroll
    for (int h = 0; h < 8; h++) {
        #pragma unroll
        for (int off = 16; off; off >>= 1)
            acc[h] += __shfl_xor_sync(0xffffffffu, acc[h], off);
    }
    if (lane == 0) {
        #pragma unroll
        for (int h = 0; h < 8; h++)
            g_bias[(h * W_DIM + j) * W_DIM + i] = __float2half(acc[h]);
    }
}

// ---------------- bf16x3 GEMM (ldmatrix + swizzle + 3-stage pipeline) ----------------
#define GEMM_SMEM()                                                            \
    __shared__ __nv_bfloat16 sAh[3][PLANE], sAl[3][PLANE];                     \
    __shared__ __nv_bfloat16 sBh[3][PLANE], sBl[3][PLANE];

#define GEMM_ISSUE(buf, kt, Ahp, Alp, Bhp, Blp, abase, nbase)                  \
    {                                                                          \
        int k0 = (kt) * 16 + ch;                                               \
        unsigned doff = ((unsigned)(buf) * PLANE + row * RS + chsw) * 2;       \
        CP16(sAh_u + doff, (Ahp) + (size_t)((abase) + row) * 256 + k0);        \
        CP16(sAl_u + doff, (Alp) + (size_t)((abase) + row) * 256 + k0);        \
        CP16(sBh_u + doff, (Bhp) + (size_t)((nbase) + row) * 256 + k0);        \
        CP16(sBl_u + doff, (Blp) + (size_t)((nbase) + row) * 256 + k0);        \
        cp_commit();                                                           \
    }

#define GEMM_LANEOFF()                                                         \
    int arow  = (lane & 7) + ((lane >> 3) & 1) * 8;                            \
    int achnk = ((lane >> 4) * 8) ^ ((arow & 4) << 1);                         \
    int brow  = (lane & 7) + ((lane >> 4) & 1) * 8;                            \
    int bchnk = (((lane >> 3) & 1) * 8) ^ ((brow & 4) << 1);

#define GEMM_KTILE(st)                                                         \
    {                                                                          \
        unsigned stoff = (unsigned)(st) * PLANE * 2;                           \
        unsigned bh[4][2], bl[4][2];                                           \
        _Pragma("unroll")                                                      \
        for (int p = 0; p < 2; p++) {                                          \
            unsigned bo = ((wn * 32 + p * 16 + brow) * RS + bchnk) * 2;        \
            LDSM4(bh[2*p][0], bh[2*p][1], bh[2*p+1][0], bh[2*p+1][1],          \
                  sBh_u + stoff + bo)                                          \
            LDSM4(bl[2*p][0], bl[2*p][1], bl[2*p+1][0], bl[2*p+1][1],          \
                  sBl_u + stoff + bo)                                          \
        }                                                                      \
        _Pragma("unroll")                                                      \
        for (int am = 0; am < 4; am++) {                                       \
            unsigned ao = ((wm * 64 + am * 16 + arow) * RS + achnk) * 2;       \
            unsigned ah0, ah1, ah2, ah3, al0, al1, al2, al3;                   \
            LDSM4(ah0, ah1, ah2, ah3, sAh_u + stoff + ao)                      \
            LDSM4(al0, al1, al2, al3, sAl_u + stoff + ao)                      \
            _Pragma("unroll")                                                  \
            for (int an = 0; an < 4; an++) {                                   \
                float* ac = acc[am][an];                                       \
                mma_bf16(ac, ah0, ah1, ah2, ah3, bh[an][0], bh[an][1]);        \
                mma_bf16(ac, ah0, ah1, ah2, ah3, bl[an][0], bl[an][1]);        \
                mma_bf16(ac, al0, al1, al2, al3, bh[an][0], bh[an][1]);        \
            }                                                                  \
        }                                                                      \
    }

#define GEMM_MAINLOOP(Ahp, Alp, Bhp, Blp, abase, nbase)                        \
    GEMM_ISSUE(0, 0, Ahp, Alp, Bhp, Blp, abase, nbase)                         \
    GEMM_ISSUE(1, 1, Ahp, Alp, Bhp, Blp, abase, nbase)                         \
    for (int kt = 0; kt < 16; kt++) {                                          \
        if (kt < 15) cp_wait1(); else cp_wait0();                              \
        __syncthreads();                                                       \
        if (kt <= 13) {                                                        \
            int nbuf = (kt + 2) % 3;                                           \
            GEMM_ISSUE(nbuf, kt + 2, Ahp, Alp, Bhp, Blp, abase, nbase)         \
        }                                                                      \
        GEMM_KTILE(kt % 3)                                                     \
    }

// ---------------- kernel 3: projection GEMM (bf16x3) ----------------
__global__ void __launch_bounds__(256, 2)
proj_mma(const float* __restrict__ bg) {
    GEMM_SMEM()
    int t = threadIdx.x, lane = t & 31, warp = t >> 5;
    int wm = warp >> 2, wn = warp & 3;
    int g = lane >> 2, c = lane & 3;
    int bn = blockIdx.x, bm = blockIdx.y;
    int nb = bn * 128;
    int abase = bm * 128;

    unsigned sAh_u = (unsigned)__cvta_generic_to_shared(sAh);
    unsigned sAl_u = (unsigned)__cvta_generic_to_shared(sAl);
    unsigned sBh_u = (unsigned)__cvta_generic_to_shared(sBh);
    unsigned sBl_u = (unsigned)__cvta_generic_to_shared(sBl);
    int row = t >> 1, ch = (t & 1) * 8;
    int chsw = ch ^ ((row & 4) << 1);
    GEMM_LANEOFF()

    float acc[4][4][4];
    #pragma unroll
    for (int am = 0; am < 4; am++)
        #pragma unroll
        for (int an = 0; an < 4; an++)
            #pragma unroll
            for (int v = 0; v < 4; v++) acc[am][an][v] = 0.0f;

    GEMM_MAINLOOP(g_xnh, g_xnl, g_wph, g_wpl, abase, nb)

    #pragma unroll
    for (int am = 0; am < 4; am++) {
        int tok = abase + wm * 64 + am * 16 + g;
        int rr = tok >> 8, iw = tok & 255;
        #pragma unroll
        for (int an = 0; an < 4; an++) {
            int gc = nb + wn * 32 + an * 8 + 2 * c;
            float a0 = acc[am][an][0], a1 = acc[am][an][1];
            float a2 = acc[am][an][2], a3 = acc[am][an][3];
            if (gc < 256) {                       // q: fp32, [rh][i][d]
                int hh = gc >> 5, d8 = gc & 31;
                float* p0 = g_q + ((size_t)((rr * 8 + hh) * 256 + iw)) * 32 + d8;
                *(float2*)p0            = make_float2(a0, a1);
                *(float2*)(p0 + 8 * 32) = make_float2(a2, a3);
            } else if (gc < 512) {                // k: bf16 split, [rh][j][d]
                int cq = gc - 256;
                int hh = cq >> 5, d8 = cq & 31;
                size_t b0 = ((size_t)((rr * 8 + hh) * 256 + iw)) * 32 + d8;
                unsigned hi0, lo0, hi1, lo1;
                split2(a0, a1, hi0, lo0);
                split2(a2, a3, hi1, lo1);
                *(unsigned*)&g_kh[b0] = hi0;  *(unsigned*)&g_kl[b0] = lo0;
                *(unsigned*)&g_kh[b0 + 256] = hi1;  *(unsigned*)&g_kl[b0 + 256] = lo1;
            } else if (gc < 768) {                // v: bf16 split, transposed [rh][d][j]
                int cq = gc - 512;
                int hh = cq >> 5, d8 = cq & 31;
                size_t vb = ((size_t)((rr * 8 + hh) * 32 + d8)) * 256 + iw;
                __nv_bfloat16 h0, l0, h1, l1;
                split_bf16(a0, h0, l0);  g_vh[vb] = h0;        g_vl[vb] = l0;
                split_bf16(a1, h1, l1);  g_vh[vb + 256] = h1;  g_vl[vb + 256] = l1;
                split_bf16(a2, h0, l0);  g_vh[vb + 8] = h0;    g_vl[vb + 8] = l0;
                split_bf16(a3, h1, l1);  g_vh[vb + 264] = h1;  g_vl[vb + 264] = l1;
            } else {                              // gate: sigmoid fp32
                int gcol = gc - 768;
                float2 bg2 = *(const float2*)(bg + gcol);
                float* p0 = g_gate + (size_t)tok * 256 + gcol;
                float* p1 = p0 + 8 * 256;
                *(float2*)p0 = make_float2(1.0f / (1.0f + __expf(-(a0 + bg2.x))),
                                           1.0f / (1.0f + __expf(-(a1 + bg2.y))));
                *(float2*)p1 = make_float2(1.0f / (1.0f + __expf(-(a2 + bg2.x))),
                                           1.0f / (1.0f + __expf(-(a3 + bg2.y))));
            }
        }
    }
}

// ---------------- kernel 5: output projection (bf16x3) ----------------
__global__ void __launch_bounds__(256, 2)
out_mma(const float* __restrict__ bo, float* __restrict__ out) {
    GEMM_SMEM()
    int t = threadIdx.x, lane = t & 31, warp = t >> 5;
    int wm = warp >> 2, wn = warp & 3;
    int g = lane >> 2, c = lane & 3;
    int bn = blockIdx.x, bm = blockIdx.y;
    int nb = bn * 128;
    int abase = bm * 128;

    unsigned sAh_u = (unsigned)__cvta_generic_to_shared(sAh);
    unsigned sAl_u = (unsigned)__cvta_generic_to_shared(sAl);
    unsigned sBh_u = (unsigned)__cvta_generic_to_shared(sBh);
    unsigned sBl_u = (unsigned)__cvta_generic_to_shared(sBl);
    int row = t >> 1, ch = (t & 1) * 8;
    int chsw = ch ^ ((row & 4) << 1);
    GEMM_LANEOFF()

    float acc[4][4][4];
    #pragma unroll
    for (int am = 0; am < 4; am++)
        #pragma unroll
        for (int an = 0; an < 4; an++)
            #pragma unroll
            for (int v = 0; v < 4; v++) acc[am][an][v] = 0.0f;

    GEMM_MAINLOOP(g_atth, g_attl, g_woh, g_wol, abase, nb)

    #pragma unroll
    for (int am = 0; am < 4; am++) {
        int tok = abase + wm * 64 + am * 16 + g;
        #pragma unroll
        for (int an = 0; an < 4; an++) {
            int gc = nb + wn * 32 + an * 8 + 2 * c;
            float2 bo2 = *(const float2*)(bo + gc);
            float* p0 = out + (size_t)tok * 256 + gc;
            float* p1 = p0 + 8 * 256;
            *(float2*)p0 = make_float2(acc[am][an][0] + bo2.x, acc[am][an][1] + bo2.y);
            *(float2*)p1 = make_float2(acc[am][an][2] + bo2.x, acc[am][an][3] + bo2.y);
        }
    }
}

// ---------------- kernel 4: attention via bf16x3 mma.sync (16 warps, 16 q/warp) ----
#define A_BIAS_SZ (32 * 264 * 2)      // 16896
#define A_K_OFF   A_BIAS_SZ
#define A_KL_OFF  (A_K_OFF  + 2560)   // 32 rows * 80 B per plane
#define A_VH_OFF  (A_K_OFF  + 5120)
#define A_VL_OFF  (A_K_OFF  + 7680)
#define A_STAGE   (A_K_OFF  + 10240)  // 27136
#define A_SMEM    (3 * A_STAGE)       // 81408

__global__ void __launch_bounds__(512, 1)
attn_mma(const unsigned int* __restrict__ mask) {
    extern __shared__ char asmem[];
    __shared__ unsigned mwords[8];

    int t = threadIdx.x, lane = t & 31, w = t >> 5;   // w = 0..15
    int g = lane >> 2, c = lane & 3;
    int rh = blockIdx.x;
    int r = rh >> 3, h = rh & 7;
    unsigned smem_u = (unsigned)__cvta_generic_to_shared(asmem);

    // key-mask ballot words
    if (w == 0) {
        #pragma unroll
        for (int q = 0; q < 8; q++) {
            unsigned bit = (mask[r * 256 + q * 32 + lane] != 0u) ? 1u : 0u;
            unsigned word = __ballot_sync(0xffffffffu, bit);
            if (lane == 0) mwords[q] = word;
        }
    }

    const float sc = 0.17677669529663689f;   // 32^-0.5
    int i0 = w * 16 + g, i1 = i0 + 8;
    int rowv0 = (mask[r * 256 + i0] != 0u);
    int rowv1 = (mask[r * 256 + i1] != 0u);

    // Q fragments (scaled, split)
    unsigned qh[2][4], ql[2][4];
    {
        const float* q0 = g_q + ((size_t)rh * 256 + i0) * 32;
        const float* q1 = g_q + ((size_t)rh * 256 + i1) * 32;
        #pragma unroll
        for (int ks = 0; ks < 2; ks++) {
            float2 x0 = *(const float2*)(q0 + ks * 16 + 2 * c);
            float2 x1 = *(const float2*)(q1 + ks * 16 + 2 * c);
            float2 x2 = *(const float2*)(q0 + ks * 16 + 2 * c + 8);
            float2 x3 = *(const float2*)(q1 + ks * 16 + 2 * c + 8);
            split2(x0.x * sc, x0.y * sc, qh[ks][0], ql[ks][0]);
            split2(x1.x * sc, x1.y * sc, qh[ks][1], ql[ks][1]);
            split2(x2.x * sc, x2.y * sc, qh[ks][2], ql[ks][2]);
            split2(x3.x * sc, x3.y * sc, qh[ks][3], ql[ks][3]);
        }
    }

    float O[4][4];
    float l0 = 0.0f, l1 = 0.0f;
    #pragma unroll
    for (int dt = 0; dt < 4; dt++)
        #pragma unroll
        for (int v = 0; v < 4; v++) O[dt][v] = 0.0f;

    const __half* bbase = g_bias + (size_t)(h * 256) * 256;
    const __nv_bfloat16* khb = g_kh + (size_t)rh * 256 * 32;
    const __nv_bfloat16* klb = g_kl + (size_t)rh * 256 * 32;
    const __nv_bfloat16* vhb = g_vh + (size_t)rh * 32 * 256;
    const __nv_bfloat16* vlb = g_vl + (size_t)rh * 32 * 256;

    // per-chunk cp.async (512 threads): 2 bias chunks + 1 KV chunk per thread
    int b_r  = t >> 4;                 // 0..31 bias row
    int b_s0 = (t & 15) * 2;           // 16B chunk within row (of 32)
    int kvp  = t >> 7;                 // plane 0..3
    int kvr  = (t >> 2) & 31;          // row 0..31
    int kvs  = t & 3;                  // 16B chunk within 64B row

    #define AISSUE(chv)                                                            \
    {                                                                              \
        unsigned sb = smem_u + (unsigned)((chv) % 3) * A_STAGE;                    \
        const __half* bs = bbase + (size_t)((chv) * 32 + b_r) * 256;               \
        CP16(sb + b_r * 528 + b_s0 * 16,       bs + b_s0 * 8);                     \
        CP16(sb + b_r * 528 + (b_s0 + 1) * 16, bs + (b_s0 + 1) * 8);               \
        unsigned kvo = sb + A_K_OFF + (unsigned)kvp * 2560 + kvr * 80 + kvs * 16;  \
        if (kvp == 0)                                                              \
            CP16(kvo, khb + (size_t)((chv) * 32 + kvr) * 32 + kvs * 8);            \
        else if (kvp == 1)                                                         \
            CP16(kvo, klb + (size_t)((chv) * 32 + kvr) * 32 + kvs * 8);            \
        else if (kvp == 2)                                                         \
            CP16(kvo, vhb + (size_t)kvr * 256 + (chv) * 32 + kvs * 8);             \
        else                                                                       \
            CP16(kvo, vlb + (size_t)kvr * 256 + (chv) * 32 + kvs * 8);             \
        cp_commit();                                                               \
    }

    AISSUE(0)
    AISSUE(1)

    int brow = (lane & 7) + ((lane >> 4) & 1) * 8;
    int bch  = ((lane >> 3) & 1) * 8;

    for (int chk = 0; chk < 8; chk++) {
        if (chk < 7) cp_wait1(); else cp_wait0();
        __syncthreads();
        if (chk + 2 < 8) AISSUE(chk + 2)

        int st = chk % 3;
        unsigned sb = smem_u + (unsigned)st * A_STAGE;
        const __half* bias_s = (const __half*)(asmem + st * A_STAGE);

        // K fragments
        unsigned kfh[2][4][2], kfl[2][4][2];
        #pragma unroll
        for (int p = 0; p < 2; p++) {
            #pragma unroll
            for (int ks = 0; ks < 2; ks++) {
                unsigned ao = sb + A_K_OFF + (p * 16 + brow) * 80 + (ks * 16 + bch) * 2;
                LDSM4(kfh[ks][2*p][0], kfh[ks][2*p][1], kfh[ks][2*p+1][0], kfh[ks][2*p+1][1], ao)
                unsigned al_ = sb + A_KL_OFF + (p * 16 + brow) * 80 + (ks * 16 + bch) * 2;
                LDSM4(kfl[ks][2*p][0], kfl[ks][2*p][1], kfl[ks][2*p+1][0], kfl[ks][2*p+1][1], al_)
            }
        }

        // S = (q*sc) @ K^T  (bf16x3)
        float S[4][4];
        #pragma unroll
        for (int jt = 0; jt < 4; jt++) {
            #pragma unroll
            for (int v = 0; v < 4; v++) S[jt][v] = 0.0f;
            #pragma unroll
            for (int ks = 0; ks < 2; ks++) {
                mma_bf16(S[jt], qh[ks][0], qh[ks][1], qh[ks][2], qh[ks][3],
                         kfh[ks][jt][0], kfh[ks][jt][1]);
                mma_bf16(S[jt], qh[ks][0], qh[ks][1], qh[ks][2], qh[ks][3],
                         kfl[ks][jt][0], kfl[ks][jt][1]);
                mma_bf16(S[jt], ql[ks][0], ql[ks][1], ql[ks][2], ql[ks][3],
                         kfh[ks][jt][0], kfh[ks][jt][1]);
            }
        }

        // bias + mask + exp
        unsigned mb = mwords[chk];
        #pragma unroll
        for (int jt = 0; jt < 4; jt++) {
            int j0 = jt * 8 + 2 * c;
            float b00 = __half2float(bias_s[j0 * 264 + i0]);
            float b01 = __half2float(bias_s[(j0 + 1) * 264 + i0]);
            float b10 = __half2float(bias_s[j0 * 264 + i1]);
            float b11 = __half2float(bias_s[(j0 + 1) * 264 + i1]);
            unsigned jm0 = (mb >> j0) & 1u, jm1 = (mb >> (j0 + 1)) & 1u;
            float p00 = jm0 ? __expf(S[jt][0] + b00) : 0.0f;
            float p01 = jm1 ? __expf(S[jt][1] + b01) : 0.0f;
            float p10 = jm0 ? __expf(S[jt][2] + b10) : 0.0f;
            float p11 = jm1 ? __expf(S[jt][3] + b11) : 0.0f;
            if (!rowv0) { p00 = 1.0f; p01 = 1.0f; }
            if (!rowv1) { p10 = 1.0f; p11 = 1.0f; }
            l0 += p00 + p01;
            l1 += p10 + p11;
            S[jt][0] = p00; S[jt][1] = p01;
            S[jt][2] = p10; S[jt][3] = p11;
        }

        // O += P @ V  (P split exactly; V split)
        #pragma unroll
        for (int ks = 0; ks < 2; ks++) {
            unsigned vfh[4][2], vfl[4][2];
            #pragma unroll
            for (int p = 0; p < 2; p++) {
                unsigned ao = sb + A_VH_OFF + (p * 16 + brow) * 80 + (ks * 16 + bch) * 2;
                LDSM4(vfh[2*p][0], vfh[2*p][1], vfh[2*p+1][0], vfh[2*p+1][1], ao)
                unsigned al_ = sb + A_VL_OFF + (p * 16 + brow) * 80 + (ks * 16 + bch) * 2;
                LDSM4(vfl[2*p][0], vfl[2*p][1], vfl[2*p+1][0], vfl[2*p+1][1], al_)
            }
            const float* PA = S[2 * ks];
            const float* PB = S[2 * ks + 1];
            unsigned ah0, ah1, ah2, ah3, al0, al1, al2, al3;
            split2(PA[0], PA[1], ah0, al0);
            split2(PA[2], PA[3], ah1, al1);
            split2(PB[0], PB[1], ah2, al2);
            split2(PB[2], PB[3], ah3, al3);
            #pragma unroll
            for (int dt = 0; dt < 4; dt++) {
                mma_bf16(O[dt], ah0, ah1, ah2, ah3, vfh[dt][0], vfh[dt][1]);
                mma_bf16(O[dt], ah0, ah1, ah2, ah3, vfl[dt][0], vfl[dt][1]);
                mma_bf16(O[dt], al0, al1, al2, al3, vfh[dt][0], vfh[dt][1]);
            }
        }
    }
    #undef AISSUE

    // finalize: reduce l over quad, normalize, gate, split-store
    l0 += __shfl_xor_sync(0xffffffffu, l0, 1);
    l0 += __shfl_xor_sync(0xffffffffu, l0, 2);
    l1 += __shfl_xor_sync(0xffffffffu, l1, 1);
    l1 += __shfl_xor_sync(0xffffffffu, l1, 2);
    float inv0 = 1.0f / l0;
    float inv1 = 1.0f / l1;

    int tok0 = r * 256 + i0;
    int tok1 = r * 256 + i1;
    #pragma unroll
    for (int dt = 0; dt < 4; dt++) {
        int col = h * 32 + dt * 8 + 2 * c;
        float2 g0 = *(const float2*)&g_gate[(size_t)tok0 * 256 + col];
        float2 g1 = *(const float2*)&g_gate[(size_t)tok1 * 256 + col];
        float o00 = O[dt][0] * inv0 * g0.x;
        float o01 = O[dt][1] * inv0 * g0.y;
        float o10 = O[dt][2] * inv1 * g1.x;
        float o11 = O[dt][3] * inv1 * g1.y;
        unsigned hi0, lo0, hi1, lo1;
        split2(o00, o01, hi0, lo0);
        split2(o10, o11, hi1, lo1);
        *(unsigned*)&g_atth[(size_t)tok0 * 256 + col] = hi0;
        *(unsigned*)&g_attl[(size_t)tok0 * 256 + col] = lo0;
        *(unsigned*)&g_atth[(size_t)tok1 * 256 + col] = hi1;
        *(unsigned*)&g_attl[(size_t)tok1 * 256 + col] = lo1;
    }
}

// ---------------- launch ----------------
extern "C" void kernel_launch(void* const* d_in, const int* in_sizes, int n_in,
                              void* d_out, int out_size) {
    const float* x      = (const float*)d_in[0];
    const float* edges  = (const float*)d_in[1];
    const unsigned int* mask      = (const unsigned int*)d_in[2];
    const unsigned int* edge_mask = (const unsigned int*)d_in[3];
    const float* ln_g   = (const float*)d_in[4];
    const float* ln_b   = (const float*)d_in[5];
    const float* lne_g  = (const float*)d_in[6];
    const float* lne_b  = (const float*)d_in[7];
    const float* W_edge = (const float*)d_in[8];
    const float* Wq     = (const float*)d_in[9];
    const float* Wkv    = (const float*)d_in[10];
    const float* Wg     = (const float*)d_in[11];
    const float* bg     = (const float*)d_in[12];
    const float* Wo     = (const float*)d_in[13];
    const float* bo     = (const float*)d_in[14];
    float* out = (float*)d_out;

    cudaFuncSetAttribute(attn_mma, cudaFuncAttributeMaxDynamicSharedMemorySize, A_SMEM);

    prep_kernel<<<NTOK / 8 + 1280, 256>>>(x, ln_g, ln_b, Wq, Wkv, Wg, Wo);
    bias_kernel<<<(W_DIM * W_DIM) / 8, 256>>>(edges, lne_g, lne_b, W_edge, edge_mask);
    proj_mma<<<dim3(8, NTOK / 128), 256>>>(bg);
    attn_mma<<<R_DIM * H_N, 512, A_SMEM>>>(mask);
    out_mma<<<dim3(2, NTOK / 128), 256>>>(bo, out);
}